// round 1
// baseline (speedup 1.0000x reference)
#include <cuda_runtime.h>

// ---------------------------------------------------------------------------
// MoCoGraph: two 2-layer GAT encoders + MoCo logits, fp32.
// Shapes (from setup): N=10000, E=160000, G=1000, H=4, C=128, B=1024, R=1024.
// ---------------------------------------------------------------------------

#define NMAX   10240
#define ETMAX  180224      // E + N with margin
#define F512   512
#define C128   128

// ------------------------- device scratch (no mallocs) ---------------------
__device__ float g_H   [(size_t)NMAX * F512];   // GEMM output (per layer)
__device__ float g_aggr[(size_t)NMAX * F512];   // attention aggregation
__device__ float g_asrc[NMAX * 4];
__device__ float g_adst[NMAX * 4];
__device__ float g_emax[NMAX * 4];
__device__ float g_denom[NMAX * 4];
__device__ float g_ebuf[(size_t)ETMAX * 4];
__device__ float g_seedq[(size_t)NMAX * C128];
__device__ float g_seedk[(size_t)NMAX * C128];
// momentum-blended key params
__device__ float g_Wk1m[1024 * F512];
__device__ float g_Wk2m[F512 * F512];
__device__ float g_ask1m[F512], g_adk1m[F512], g_bk1m[F512];
__device__ float g_ask2m[F512], g_adk2m[F512], g_bk2m[C128];

// ------------------------------ small kernels ------------------------------
__global__ void blend_kernel(const float* __restrict__ pk,
                             const float* __restrict__ pq,
                             float* __restrict__ out, int n) {
    int i = blockIdx.x * blockDim.x + threadIdx.x;
    if (i < n) out[i] = 0.99f * pk[i] + 0.01f * pq[i];
}

// ------------------------------ SGEMM 128x128x8 ----------------------------
// A[M,K] row-major, B[K,N] row-major, C[M,N]. K%8==0, K%4==0, N%128==0.
__global__ __launch_bounds__(256)
void sgemm_kernel(int M, int N, int K,
                  const float* __restrict__ A,
                  const float* __restrict__ B,
                  float* __restrict__ C) {
    const int BM = 128, BN = 128, BK = 8, TM = 8, TN = 8;
    __shared__ float As[BK][BM];
    __shared__ float Bs[BK][BN];

    const int tid = threadIdx.x;
    const int threadCol = tid % (BN / TN);   // 0..15
    const int threadRow = tid / (BN / TN);   // 0..15
    const int cRow = blockIdx.y, cCol = blockIdx.x;

    const int innerRowA = tid / (BK / 4);        // 0..127
    const int innerColA = (tid % (BK / 4)) * 4;  // 0 or 4
    const int innerRowB = tid / (BN / 4);        // 0..7
    const int innerColB = (tid % (BN / 4)) * 4;  // 0..124

    float acc[TM * TN];
#pragma unroll
    for (int i = 0; i < TM * TN; i++) acc[i] = 0.f;
    float regM[TM], regN[TN];

    const int globalRowA = cRow * BM + innerRowA;
    const float* Aptr = A + (size_t)cRow * BM * K;
    const float* Bptr = B + cCol * BN;

    for (int kt = 0; kt < K; kt += BK) {
        float4 a4;
        if (globalRowA < M)
            a4 = *(const float4*)(Aptr + (size_t)innerRowA * K + kt + innerColA);
        else
            a4 = make_float4(0.f, 0.f, 0.f, 0.f);
        As[innerColA + 0][innerRowA] = a4.x;
        As[innerColA + 1][innerRowA] = a4.y;
        As[innerColA + 2][innerRowA] = a4.z;
        As[innerColA + 3][innerRowA] = a4.w;

        float4 b4 = *(const float4*)(Bptr + (size_t)(kt + innerRowB) * N + innerColB);
        *(float4*)(&Bs[innerRowB][innerColB]) = b4;

        __syncthreads();
#pragma unroll
        for (int k = 0; k < BK; k++) {
#pragma unroll
            for (int i = 0; i < TM; i++) regM[i] = As[k][threadRow * TM + i];
#pragma unroll
            for (int j = 0; j < TN; j++) regN[j] = Bs[k][threadCol * TN + j];
#pragma unroll
            for (int i = 0; i < TM; i++)
#pragma unroll
                for (int j = 0; j < TN; j++)
                    acc[i * TN + j] += regM[i] * regN[j];
        }
        __syncthreads();
    }

#pragma unroll
    for (int i = 0; i < TM; i++) {
        int row = cRow * BM + threadRow * TM + i;
        if (row >= M) continue;
#pragma unroll
        for (int j = 0; j < TN; j += 4) {
            float4 v = make_float4(acc[i * TN + j], acc[i * TN + j + 1],
                                   acc[i * TN + j + 2], acc[i * TN + j + 3]);
            *(float4*)(&C[(size_t)row * N + cCol * BN + threadCol * TN + j]) = v;
        }
    }
}

// ---------------------------- attention scores -----------------------------
// a_src[n,h] = sum_c H[n,h*128+c]*att_s[h,c] ; a_dst likewise.
__global__ void att_scores_kernel(const float* __restrict__ Hf,
                                  const float* __restrict__ att_s,
                                  const float* __restrict__ att_d,
                                  float* __restrict__ a_s,
                                  float* __restrict__ a_d, int N) {
    int n = blockIdx.x;
    if (n >= N) return;
    int h = threadIdx.y;     // 0..3
    int lane = threadIdx.x;  // 0..31
    const float* row = Hf + (size_t)n * F512 + h * C128;
    float ss = 0.f, sd = 0.f;
#pragma unroll
    for (int j = 0; j < 4; j++) {
        int c = lane + 32 * j;
        float v = row[c];
        ss += v * att_s[h * C128 + c];
        sd += v * att_d[h * C128 + c];
    }
#pragma unroll
    for (int o = 16; o > 0; o >>= 1) {
        ss += __shfl_down_sync(0xffffffffu, ss, o);
        sd += __shfl_down_sync(0xffffffffu, sd, o);
    }
    if (lane == 0) { a_s[n * 4 + h] = ss; a_d[n * 4 + h] = sd; }
}

__device__ __forceinline__ void atomicMaxF(float* addr, float v) {
    if (v >= 0.f) atomicMax((int*)addr, __float_as_int(v));
    else          atomicMin((unsigned int*)addr, __float_as_uint(v));
}

// pass 1: e = leaky_relu(a_src[s]+a_dst[d]); segment max via atomics
__global__ void edge_pass1(const int* __restrict__ ei, int E, int N,
                           const float* __restrict__ a_s,
                           const float* __restrict__ a_d,
                           float* __restrict__ ebuf,
                           float* __restrict__ emax, int dlim) {
    int idx = blockIdx.x * blockDim.x + threadIdx.x;
    int ET = E + N;
    if (idx >= ET * 4) return;
    int i = idx >> 2, h = idx & 3;
    int s, d;
    if (i < E) { s = ei[i]; d = ei[E + i]; } else { s = d = i - E; }
    if (d >= dlim) return;
    float e = a_s[s * 4 + h] + a_d[d * 4 + h];
    e = e > 0.f ? e : 0.2f * e;
    ebuf[idx] = e;
    atomicMaxF(&emax[d * 4 + h], e);
}

// pass 2: ee = exp(e - emax[d]); segment sum
__global__ void edge_pass2(const int* __restrict__ ei, int E, int N,
                           float* __restrict__ ebuf,
                           const float* __restrict__ emax,
                           float* __restrict__ denom, int dlim) {
    int idx = blockIdx.x * blockDim.x + threadIdx.x;
    int ET = E + N;
    if (idx >= ET * 4) return;
    int i = idx >> 2, h = idx & 3;
    int d;
    if (i < E) d = ei[E + i]; else d = i - E;
    if (d >= dlim) return;
    float ee = expf(ebuf[idx] - emax[d * 4 + h]);
    ebuf[idx] = ee;
    atomicAdd(&denom[d * 4 + h], ee);
}

// pass 3: aggr[d,h,c] += H[s,h,c] * alpha
__global__ void edge_pass3(const int* __restrict__ ei, int E, int N,
                           const float* __restrict__ Hf,
                           const float* __restrict__ ebuf,
                           const float* __restrict__ denom,
                           float* __restrict__ aggr, int dlim) {
    long idx = (long)blockIdx.x * blockDim.x + threadIdx.x;
    long ET = E + N;
    if (idx >= ET * 512) return;
    int c = (int)(idx & 127);
    int h = (int)((idx >> 7) & 3);
    long i = idx >> 9;
    int s, d;
    if (i < E) { s = ei[i]; d = ei[E + i]; } else { s = d = (int)(i - E); }
    if (d >= dlim) return;
    float alpha = ebuf[i * 4 + h] / (denom[d * 4 + h] + 1e-16f);
    atomicAdd(&aggr[(size_t)d * F512 + h * C128 + c],
              Hf[(size_t)s * F512 + h * C128 + c] * alpha);
}

__global__ void bias_relu_kernel(float* __restrict__ aggr,
                                 const float* __restrict__ bias, int N) {
    int idx = blockIdx.x * blockDim.x + threadIdx.x;
    if (idx >= N * F512) return;
    float v = aggr[idx] + bias[idx & 511];
    aggr[idx] = v > 0.f ? v : 0.f;
}

// layer-2 epilogue: mean over 4 heads + bias, then row l2-normalize (seed rows)
__global__ void head_mean_norm_kernel(const float* __restrict__ aggr,
                                      const float* __restrict__ bias,
                                      float* __restrict__ outv, int B) {
    int n = blockIdx.x;
    if (n >= B) return;
    int c = threadIdx.x;  // 128
    size_t base = (size_t)n * F512;
    float v = 0.25f * (aggr[base + c] + aggr[base + 128 + c] +
                       aggr[base + 256 + c] + aggr[base + 384 + c]) + bias[c];
    float s = v * v;
#pragma unroll
    for (int o = 16; o > 0; o >>= 1) s += __shfl_down_sync(0xffffffffu, s, o);
    __shared__ float red[4];
    if ((c & 31) == 0) red[c >> 5] = s;
    __syncthreads();
    float tot = red[0] + red[1] + red[2] + red[3];
    outv[(size_t)n * C128 + c] = v * rsqrtf(tot + 1e-24f);
}

// logits: out[n,0] = q.k /T ; out[n,1+k] = q . queue[:,k] / T
__global__ void logits_kernel(const float* __restrict__ q,
                              const float* __restrict__ kv,
                              const float* __restrict__ queue,
                              float* __restrict__ out, int B, int R) {
    int n = blockIdx.x;
    if (n >= B) return;
    __shared__ float qs[128];
    int tid = threadIdx.x;
    if (tid < 128) qs[tid] = q[(size_t)n * 128 + tid];
    __syncthreads();
    for (int col = tid; col <= R; col += blockDim.x) {
        float acc = 0.f;
        if (col == 0) {
#pragma unroll 4
            for (int c = 0; c < 128; c++) acc += qs[c] * kv[(size_t)n * 128 + c];
        } else {
            int kk = col - 1;
#pragma unroll 4
            for (int c = 0; c < 128; c++) acc += qs[c] * queue[(size_t)c * R + kk];
        }
        out[(size_t)n * (R + 1) + col] = acc / 0.2f;
    }
}

// ------------------------------- host helpers ------------------------------
static void run_gat_encoder(const float* x, const int* ei, int N, int E, int G,
                            const float* W1, const float* as1, const float* ad1, const float* b1,
                            const float* W2, const float* as2, const float* ad2, const float* b2,
                            float* outseed, int B,
                            float* Hbuf, float* aggr, float* asrc, float* adst,
                            float* emax, float* denom, float* ebuf) {
    int ET = E + N;
    int t1 = ET * 4;
    long t3 = (long)ET * 512;

    // ---- layer 1 ----
    {
        dim3 grid((F512 + 127) / 128, (N + 127) / 128);
        sgemm_kernel<<<grid, 256>>>(N, F512, G, x, W1, Hbuf);
    }
    att_scores_kernel<<<N, dim3(32, 4)>>>(Hbuf, as1, ad1, asrc, adst, N);
    cudaMemsetAsync(emax, 0xFF, (size_t)N * 4 * sizeof(float));
    cudaMemsetAsync(denom, 0, (size_t)N * 4 * sizeof(float));
    cudaMemsetAsync(aggr, 0, (size_t)N * F512 * sizeof(float));
    edge_pass1<<<(t1 + 255) / 256, 256>>>(ei, E, N, asrc, adst, ebuf, emax, N);
    edge_pass2<<<(t1 + 255) / 256, 256>>>(ei, E, N, ebuf, emax, denom, N);
    edge_pass3<<<(int)((t3 + 255) / 256), 256>>>(ei, E, N, Hbuf, ebuf, denom, aggr, N);
    bias_relu_kernel<<<(N * F512 + 255) / 256, 256>>>(aggr, b1, N);

    // ---- layer 2 (only dst < B matters for the output) ----
    {
        dim3 grid((F512 + 127) / 128, (N + 127) / 128);
        sgemm_kernel<<<grid, 256>>>(N, F512, F512, aggr, W2, Hbuf);
    }
    att_scores_kernel<<<N, dim3(32, 4)>>>(Hbuf, as2, ad2, asrc, adst, N);
    cudaMemsetAsync(emax, 0xFF, (size_t)N * 4 * sizeof(float));
    cudaMemsetAsync(denom, 0, (size_t)N * 4 * sizeof(float));
    cudaMemsetAsync(aggr, 0, (size_t)B * F512 * sizeof(float));
    edge_pass1<<<(t1 + 255) / 256, 256>>>(ei, E, N, asrc, adst, ebuf, emax, B);
    edge_pass2<<<(t1 + 255) / 256, 256>>>(ei, E, N, ebuf, emax, denom, B);
    edge_pass3<<<(int)((t3 + 255) / 256), 256>>>(ei, E, N, Hbuf, ebuf, denom, aggr, B);
    head_mean_norm_kernel<<<B, 128>>>(aggr, b2, outseed, B);
}

extern "C" void kernel_launch(void* const* d_in, const int* in_sizes, int n_in,
                              void* d_out, int out_size) {
    // Input layout (metadata order). num_seed_nodes may or may not be a buffer:
    // with it, n_in == 21 and params start at index 4.
    int base = n_in - 17;

    const float* im_q = (const float*)d_in[0];
    const float* im_k = (const float*)d_in[1];
    const int*   ei   = (const int*)d_in[2];

    const float* Wq1  = (const float*)d_in[base + 0];
    const float* asq1 = (const float*)d_in[base + 1];
    const float* adq1 = (const float*)d_in[base + 2];
    const float* bq1  = (const float*)d_in[base + 3];
    const float* Wq2  = (const float*)d_in[base + 4];
    const float* asq2 = (const float*)d_in[base + 5];
    const float* adq2 = (const float*)d_in[base + 6];
    const float* bq2  = (const float*)d_in[base + 7];
    const float* Wk1  = (const float*)d_in[base + 8];
    const float* ask1 = (const float*)d_in[base + 9];
    const float* adk1 = (const float*)d_in[base + 10];
    const float* bk1  = (const float*)d_in[base + 11];
    const float* Wk2  = (const float*)d_in[base + 12];
    const float* ask2 = (const float*)d_in[base + 13];
    const float* adk2 = (const float*)d_in[base + 14];
    const float* bk2  = (const float*)d_in[base + 15];
    const float* queue= (const float*)d_in[base + 16];

    int G = in_sizes[base] / F512;          // Wq1 is [G, 512]
    int N = in_sizes[0] / G;                // im_q is [N, G]
    int E = in_sizes[2] / 2;                // edge_index [2, E]
    int R = in_sizes[base + 16] / C128;     // queue [128, R]
    int B = (out_size % (R + 2) == 0) ? out_size / (R + 2) : out_size / (R + 1);
    if (B > N) B = N;

    // resolve scratch symbols
    float *Hbuf, *aggr, *asrc, *adst, *emax, *denom, *ebuf, *seedq, *seedk;
    float *Wk1m, *Wk2m, *ask1m, *adk1m, *bk1m, *ask2m, *adk2m, *bk2m;
    cudaGetSymbolAddress((void**)&Hbuf, g_H);
    cudaGetSymbolAddress((void**)&aggr, g_aggr);
    cudaGetSymbolAddress((void**)&asrc, g_asrc);
    cudaGetSymbolAddress((void**)&adst, g_adst);
    cudaGetSymbolAddress((void**)&emax, g_emax);
    cudaGetSymbolAddress((void**)&denom, g_denom);
    cudaGetSymbolAddress((void**)&ebuf, g_ebuf);
    cudaGetSymbolAddress((void**)&seedq, g_seedq);
    cudaGetSymbolAddress((void**)&seedk, g_seedk);
    cudaGetSymbolAddress((void**)&Wk1m, g_Wk1m);
    cudaGetSymbolAddress((void**)&Wk2m, g_Wk2m);
    cudaGetSymbolAddress((void**)&ask1m, g_ask1m);
    cudaGetSymbolAddress((void**)&adk1m, g_adk1m);
    cudaGetSymbolAddress((void**)&bk1m, g_bk1m);
    cudaGetSymbolAddress((void**)&ask2m, g_ask2m);
    cudaGetSymbolAddress((void**)&adk2m, g_adk2m);
    cudaGetSymbolAddress((void**)&bk2m, g_bk2m);

    // momentum blend of key-encoder params: k' = 0.99k + 0.01q
    blend_kernel<<<(G * F512 + 255) / 256, 256>>>(Wk1, Wq1, Wk1m, G * F512);
    blend_kernel<<<2, 256>>>(ask1, asq1, ask1m, F512);
    blend_kernel<<<2, 256>>>(adk1, adq1, adk1m, F512);
    blend_kernel<<<2, 256>>>(bk1, bq1, bk1m, F512);
    blend_kernel<<<(F512 * F512 + 255) / 256, 256>>>(Wk2, Wq2, Wk2m, F512 * F512);
    blend_kernel<<<2, 256>>>(ask2, asq2, ask2m, F512);
    blend_kernel<<<2, 256>>>(adk2, adq2, adk2m, F512);
    blend_kernel<<<1, 128>>>(bk2, bq2, bk2m, C128);

    // query encoder
    run_gat_encoder(im_q, ei, N, E, G, Wq1, asq1, adq1, bq1, Wq2, asq2, adq2, bq2,
                    seedq, B, Hbuf, aggr, asrc, adst, emax, denom, ebuf);
    // key encoder (blended params)
    run_gat_encoder(im_k, ei, N, E, G, Wk1m, ask1m, adk1m, bk1m, Wk2m, ask2m, adk2m, bk2m,
                    seedk, B, Hbuf, aggr, asrc, adst, emax, denom, ebuf);

    // logits + zero labels tail
    logits_kernel<<<B, 256>>>(seedq, seedk, queue, (float*)d_out, B, R);
    size_t written = (size_t)B * (R + 1);
    if ((size_t)out_size > written)
        cudaMemsetAsync((float*)d_out + written, 0,
                        ((size_t)out_size - written) * sizeof(float));
}

// round 2
// speedup vs baseline: 1.9739x; 1.9739x over previous
#include <cuda_runtime.h>
#include <cuda_bf16.h>
#include <mma.h>

using namespace nvcuda;

// ---------------------------------------------------------------------------
// MoCoGraph: two 2-layer GAT encoders + MoCo logits.
// GEMMs: bf16 3-term split on tensor cores (fp32-level accuracy).
// Attention: CSR gather (no atomics), fused softmax+aggregate per dst node.
// ---------------------------------------------------------------------------

#define NMAX   10240
#define ETMAX  180224      // E + N with margin
#define F512   512
#define C128   128
#define CAP    512         // max degree held in smem (fallback recompute if more)

// ------------------------- device scratch (no mallocs) ---------------------
__device__ float g_H   [(size_t)NMAX * F512];   // GEMM output (per layer)
__device__ float g_aggr[(size_t)NMAX * F512];   // attention aggregation
__device__ float g_asrc[NMAX * 4];
__device__ float g_adst[NMAX * 4];
__device__ float g_seedq[(size_t)NMAX * C128];
__device__ float g_seedk[(size_t)NMAX * C128];
// momentum-blended key params
__device__ float g_Wk1m[1024 * F512];
__device__ float g_Wk2m[F512 * F512];
__device__ float g_ask1m[F512], g_adk1m[F512], g_bk1m[F512];
__device__ float g_ask2m[F512], g_adk2m[F512], g_bk2m[C128];
// CSR by destination
__device__ int g_deg[NMAX];
__device__ int g_off[NMAX + 1];
__device__ int g_cur[NMAX];
__device__ int g_csrc[ETMAX];

// ------------------------------ small kernels ------------------------------
__global__ void blend_kernel(const float* __restrict__ pk,
                             const float* __restrict__ pq,
                             float* __restrict__ out, int n) {
    int i = blockIdx.x * blockDim.x + threadIdx.x;
    if (i < n) out[i] = 0.99f * pk[i] + 0.01f * pq[i];
}

// ------------------------------- CSR build ---------------------------------
__global__ void csr_count_kernel(const int* __restrict__ ei, int E, int N,
                                 int* __restrict__ deg) {
    int i = blockIdx.x * blockDim.x + threadIdx.x;
    int ET = E + N;
    if (i >= ET) return;
    int d = (i < E) ? ei[E + i] : (i - E);
    atomicAdd(&deg[d], 1);
}

__global__ void csr_scan_kernel(const int* __restrict__ deg,
                                int* __restrict__ off, int N) {
    __shared__ int sh[1024];
    __shared__ int carry;
    int t = threadIdx.x;
    if (t == 0) carry = 0;
    __syncthreads();
    for (int base = 0; base < N; base += 1024) {
        int v = (base + t < N) ? deg[base + t] : 0;
        sh[t] = v;
        __syncthreads();
        for (int o = 1; o < 1024; o <<= 1) {
            int x = (t >= o) ? sh[t - o] : 0;
            __syncthreads();
            sh[t] += x;
            __syncthreads();
        }
        int excl = sh[t] - v + carry;
        if (base + t < N) off[base + t] = excl;
        __syncthreads();
        if (t == 1023) carry += sh[1023];
        __syncthreads();
    }
    if (t == 0) off[N] = carry;
}

__global__ void csr_fill_kernel(const int* __restrict__ ei, int E, int N,
                                const int* __restrict__ off,
                                int* __restrict__ cur,
                                int* __restrict__ csrc) {
    int i = blockIdx.x * blockDim.x + threadIdx.x;
    int ET = E + N;
    if (i >= ET) return;
    int s, d;
    if (i < E) { s = ei[i]; d = ei[E + i]; } else { s = d = i - E; }
    int pos = atomicAdd(&cur[d], 1);
    csrc[off[d] + pos] = s;
}

// ------------------- bf16 3-term split tensor-core GEMM --------------------
// C[M,N] = A[M,K] @ B[K,N], all fp32 row-major. Requires N % 128 == 0,
// K % 4 == 0. Rows >= M are zero-padded on load; C must have >= ceil128(M)
// rows of writable space (scratch buffers do).
#define BM 128
#define BN 128
#define BKK 32

__device__ __forceinline__ void split_bf16(float v, __nv_bfloat16& h, __nv_bfloat16& l) {
    h = __float2bfloat16(v);
    l = __float2bfloat16(v - __bfloat162float(h));
}

__global__ __launch_bounds__(256)
void gemm_bf16x3_kernel(int M, int Nn, int K,
                        const float* __restrict__ A,
                        const float* __restrict__ B,
                        float* __restrict__ C) {
    __shared__ __nv_bfloat16 Ah[BM][BKK + 8];
    __shared__ __nv_bfloat16 Al[BM][BKK + 8];
    __shared__ __nv_bfloat16 Bh[BKK][BN + 8];
    __shared__ __nv_bfloat16 Bl[BKK][BN + 8];

    const int tid = threadIdx.x;
    const int blockN = blockIdx.x, blockM = blockIdx.y;
    const int warpId = tid >> 5;
    const int wm = warpId & 3;   // 4 row groups of 32
    const int wn = warpId >> 2;  // 2 col groups of 64

    wmma::fragment<wmma::accumulator, 16, 16, 16, float> acc[2][4];
#pragma unroll
    for (int i = 0; i < 2; i++)
#pragma unroll
        for (int j = 0; j < 4; j++) wmma::fill_fragment(acc[i][j], 0.0f);

    // A load mapping: 2 threads per row, 16 floats each
    const int arow = tid >> 1;
    const int acol = (tid & 1) * 16;
    const int grow = blockM * BM + arow;
    // B load mapping: 8 threads per row, 16 floats each
    const int brow = tid >> 3;
    const int bcol = (tid & 7) * 16;

    for (int kt = 0; kt < K; kt += BKK) {
        // ---- load A tile ----
        {
            const float* ap = A + (size_t)grow * K + kt + acol;
#pragma unroll
            for (int q = 0; q < 4; q++) {
                float4 v;
                if (grow < M && (kt + acol + q * 4) < K)
                    v = *(const float4*)(ap + q * 4);
                else
                    v = make_float4(0.f, 0.f, 0.f, 0.f);
                __nv_bfloat16 h0, l0, h1, l1, h2, l2, h3, l3;
                split_bf16(v.x, h0, l0); split_bf16(v.y, h1, l1);
                split_bf16(v.z, h2, l2); split_bf16(v.w, h3, l3);
                int c = acol + q * 4;
                Ah[arow][c + 0] = h0; Al[arow][c + 0] = l0;
                Ah[arow][c + 1] = h1; Al[arow][c + 1] = l1;
                Ah[arow][c + 2] = h2; Al[arow][c + 2] = l2;
                Ah[arow][c + 3] = h3; Al[arow][c + 3] = l3;
            }
        }
        // ---- load B tile ----
        {
            const float* bp = B + (size_t)(kt + brow) * Nn + blockN * BN + bcol;
            bool rowok = (kt + brow) < K;
#pragma unroll
            for (int q = 0; q < 4; q++) {
                float4 v = rowok ? *(const float4*)(bp + q * 4)
                                 : make_float4(0.f, 0.f, 0.f, 0.f);
                __nv_bfloat16 h0, l0, h1, l1, h2, l2, h3, l3;
                split_bf16(v.x, h0, l0); split_bf16(v.y, h1, l1);
                split_bf16(v.z, h2, l2); split_bf16(v.w, h3, l3);
                int c = bcol + q * 4;
                Bh[brow][c + 0] = h0; Bl[brow][c + 0] = l0;
                Bh[brow][c + 1] = h1; Bl[brow][c + 1] = l1;
                Bh[brow][c + 2] = h2; Bl[brow][c + 2] = l2;
                Bh[brow][c + 3] = h3; Bl[brow][c + 3] = l3;
            }
        }
        __syncthreads();

#pragma unroll
        for (int kk = 0; kk < BKK; kk += 16) {
            wmma::fragment<wmma::matrix_a, 16, 16, 16, __nv_bfloat16, wmma::row_major> ah[2], al[2];
            wmma::fragment<wmma::matrix_b, 16, 16, 16, __nv_bfloat16, wmma::row_major> bh[4], bl[4];
#pragma unroll
            for (int i = 0; i < 2; i++) {
                wmma::load_matrix_sync(ah[i], &Ah[wm * 32 + i * 16][kk], BKK + 8);
                wmma::load_matrix_sync(al[i], &Al[wm * 32 + i * 16][kk], BKK + 8);
            }
#pragma unroll
            for (int j = 0; j < 4; j++) {
                wmma::load_matrix_sync(bh[j], &Bh[kk][wn * 64 + j * 16], BN + 8);
                wmma::load_matrix_sync(bl[j], &Bl[kk][wn * 64 + j * 16], BN + 8);
            }
#pragma unroll
            for (int i = 0; i < 2; i++)
#pragma unroll
                for (int j = 0; j < 4; j++) {
                    wmma::mma_sync(acc[i][j], ah[i], bh[j], acc[i][j]);
                    wmma::mma_sync(acc[i][j], ah[i], bl[j], acc[i][j]);
                    wmma::mma_sync(acc[i][j], al[i], bh[j], acc[i][j]);
                }
        }
        __syncthreads();
    }

    // ---- store (C has padded rows; unguarded) ----
#pragma unroll
    for (int i = 0; i < 2; i++) {
        int row = blockM * BM + wm * 32 + i * 16;
#pragma unroll
        for (int j = 0; j < 4; j++) {
            int col = blockN * BN + wn * 64 + j * 16;
            wmma::store_matrix_sync(&C[(size_t)row * Nn + col], acc[i][j],
                                    Nn, wmma::mem_row_major);
        }
    }
}

// ---------------------------- attention scores -----------------------------
__global__ void att_scores_kernel(const float* __restrict__ Hf,
                                  const float* __restrict__ att_s,
                                  const float* __restrict__ att_d,
                                  float* __restrict__ a_s,
                                  float* __restrict__ a_d, int N) {
    int n = blockIdx.x;
    if (n >= N) return;
    int h = threadIdx.y;     // 0..3
    int lane = threadIdx.x;  // 0..31
    const float* row = Hf + (size_t)n * F512 + h * C128;
    float ss = 0.f, sd = 0.f;
#pragma unroll
    for (int j = 0; j < 4; j++) {
        int c = lane + 32 * j;
        float v = row[c];
        ss += v * att_s[h * C128 + c];
        sd += v * att_d[h * C128 + c];
    }
#pragma unroll
    for (int o = 16; o > 0; o >>= 1) {
        ss += __shfl_down_sync(0xffffffffu, ss, o);
        sd += __shfl_down_sync(0xffffffffu, sd, o);
    }
    if (lane == 0) { a_s[n * 4 + h] = ss; a_d[n * 4 + h] = sd; }
}

// ---------------- fused per-dst softmax + aggregation (no atomics) ---------
__device__ __forceinline__ float leaky(float e) { return e > 0.f ? e : 0.2f * e; }

__global__ __launch_bounds__(256)
void gat_attn_kernel(const float* __restrict__ Hf,
                     const float4* __restrict__ a_s4,
                     const float4* __restrict__ a_d4,
                     const int* __restrict__ off,
                     const int* __restrict__ deg_arr,
                     const int* __restrict__ csrc,
                     const float* __restrict__ bias,   // null -> no bias/relu
                     float* __restrict__ outbuf) {
    int d = blockIdx.x;
    int t = threadIdx.x;
    int lane = t & 31, wid = t >> 5;

    __shared__ int   s_list[CAP];
    __shared__ float w[CAP][4];
    __shared__ float red[8][4];
    __shared__ float mx_s[4], invd_s[4];

    const int start = off[d];
    const int deg = deg_arr[d];
    const float4 ad = a_d4[d];

    // ---- phase A: scores + max ----
    float m0 = -1e30f, m1 = -1e30f, m2 = -1e30f, m3 = -1e30f;
    for (int j = t; j < deg; j += 256) {
        int s = csrc[start + j];
        float4 as = a_s4[s];
        float e0 = leaky(as.x + ad.x);
        float e1 = leaky(as.y + ad.y);
        float e2 = leaky(as.z + ad.z);
        float e3 = leaky(as.w + ad.w);
        if (j < CAP) {
            s_list[j] = s;
            w[j][0] = e0; w[j][1] = e1; w[j][2] = e2; w[j][3] = e3;
        }
        m0 = fmaxf(m0, e0); m1 = fmaxf(m1, e1);
        m2 = fmaxf(m2, e2); m3 = fmaxf(m3, e3);
    }
#pragma unroll
    for (int o = 16; o > 0; o >>= 1) {
        m0 = fmaxf(m0, __shfl_xor_sync(0xffffffffu, m0, o));
        m1 = fmaxf(m1, __shfl_xor_sync(0xffffffffu, m1, o));
        m2 = fmaxf(m2, __shfl_xor_sync(0xffffffffu, m2, o));
        m3 = fmaxf(m3, __shfl_xor_sync(0xffffffffu, m3, o));
    }
    if (lane == 0) { red[wid][0] = m0; red[wid][1] = m1; red[wid][2] = m2; red[wid][3] = m3; }
    __syncthreads();
    if (t < 4) {
        float mm = -1e30f;
#pragma unroll
        for (int k = 0; k < 8; k++) mm = fmaxf(mm, red[k][t]);
        mx_s[t] = mm;
    }
    __syncthreads();
    const float mx0 = mx_s[0], mx1 = mx_s[1], mx2 = mx_s[2], mx3 = mx_s[3];

    // ---- phase B: exp + sum ----
    float s0 = 0.f, s1 = 0.f, s2 = 0.f, s3 = 0.f;
    for (int j = t; j < deg; j += 256) {
        float e0, e1, e2, e3;
        if (j < CAP) {
            e0 = w[j][0]; e1 = w[j][1]; e2 = w[j][2]; e3 = w[j][3];
        } else {
            int s = csrc[start + j];
            float4 as = a_s4[s];
            e0 = leaky(as.x + ad.x); e1 = leaky(as.y + ad.y);
            e2 = leaky(as.z + ad.z); e3 = leaky(as.w + ad.w);
        }
        float x0 = expf(e0 - mx0), x1 = expf(e1 - mx1);
        float x2 = expf(e2 - mx2), x3 = expf(e3 - mx3);
        if (j < CAP) { w[j][0] = x0; w[j][1] = x1; w[j][2] = x2; w[j][3] = x3; }
        s0 += x0; s1 += x1; s2 += x2; s3 += x3;
    }
#pragma unroll
    for (int o = 16; o > 0; o >>= 1) {
        s0 += __shfl_xor_sync(0xffffffffu, s0, o);
        s1 += __shfl_xor_sync(0xffffffffu, s1, o);
        s2 += __shfl_xor_sync(0xffffffffu, s2, o);
        s3 += __shfl_xor_sync(0xffffffffu, s3, o);
    }
    __syncthreads();  // protect red[] reuse
    if (lane == 0) { red[wid][0] = s0; red[wid][1] = s1; red[wid][2] = s2; red[wid][3] = s3; }
    __syncthreads();
    if (t < 4) {
        float ssum = 0.f;
#pragma unroll
        for (int k = 0; k < 8; k++) ssum += red[k][t];
        invd_s[t] = 1.0f / (ssum + 1e-16f);
    }
    __syncthreads();

    // ---- phase C: weighted gather of messages ----
    const int c2 = t * 2;            // 0..510
    const int h = c2 >> 7;           // 0..3
    const float inv = invd_s[h];
    const float mxh = mx_s[h];
    float acc0 = 0.f, acc1 = 0.f;
    for (int j = 0; j < deg; j++) {
        int s;
        float ww;
        if (j < CAP) {
            s = s_list[j];
            ww = w[j][h];
        } else {
            s = csrc[start + j];
            const float* asp = (const float*)&a_s4[s];
            const float* adp = (const float*)&ad;
            ww = expf(leaky(asp[h] + adp[h]) - mxh);
        }
        float alpha = ww * inv;
        float2 v = *(const float2*)(Hf + (size_t)s * F512 + c2);
        acc0 += v.x * alpha;
        acc1 += v.y * alpha;
    }
    if (bias) {
        acc0 = fmaxf(acc0 + bias[c2], 0.f);
        acc1 = fmaxf(acc1 + bias[c2 + 1], 0.f);
    }
    *(float2*)(outbuf + (size_t)d * F512 + c2) = make_float2(acc0, acc1);
}

// layer-2 epilogue: mean over 4 heads + bias, then row l2-normalize
__global__ void head_mean_norm_kernel(const float* __restrict__ aggr,
                                      const float* __restrict__ bias,
                                      float* __restrict__ outv, int B) {
    int n = blockIdx.x;
    if (n >= B) return;
    int c = threadIdx.x;  // 128
    size_t base = (size_t)n * F512;
    float v = 0.25f * (aggr[base + c] + aggr[base + 128 + c] +
                       aggr[base + 256 + c] + aggr[base + 384 + c]) + bias[c];
    float s = v * v;
#pragma unroll
    for (int o = 16; o > 0; o >>= 1) s += __shfl_down_sync(0xffffffffu, s, o);
    __shared__ float red[4];
    if ((c & 31) == 0) red[c >> 5] = s;
    __syncthreads();
    float tot = red[0] + red[1] + red[2] + red[3];
    outv[(size_t)n * C128 + c] = v * rsqrtf(tot + 1e-24f);
}

// logits: out[n,0] = q.k/T ; out[n,1+k] = q . queue[:,k] / T
__global__ void logits_kernel(const float* __restrict__ q,
                              const float* __restrict__ kv,
                              const float* __restrict__ queue,
                              float* __restrict__ out, int B, int R) {
    int n = blockIdx.x;
    if (n >= B) return;
    __shared__ float qs[128];
    int tid = threadIdx.x;
    if (tid < 128) qs[tid] = q[(size_t)n * 128 + tid];
    __syncthreads();
    for (int col = tid; col <= R; col += blockDim.x) {
        float acc = 0.f;
        if (col == 0) {
#pragma unroll 4
            for (int c = 0; c < 128; c++) acc += qs[c] * kv[(size_t)n * 128 + c];
        } else {
            int kk = col - 1;
#pragma unroll 4
            for (int c = 0; c < 128; c++) acc += qs[c] * queue[(size_t)c * R + kk];
        }
        out[(size_t)n * (R + 1) + col] = acc / 0.2f;
    }
}

// ------------------------------- host helpers ------------------------------
static void run_gat_encoder(const float* x, int N, int E, int G,
                            const float* W1, const float* as1, const float* ad1, const float* b1,
                            const float* W2, const float* as2, const float* ad2, const float* b2,
                            float* outseed, int B,
                            float* Hbuf, float* aggr, float* asrc, float* adst,
                            int* off, int* deg, int* csrc) {
    // ---- layer 1 ----
    {
        dim3 grid(F512 / BN, (N + BM - 1) / BM);
        gemm_bf16x3_kernel<<<grid, 256>>>(N, F512, G, x, W1, Hbuf);
    }
    att_scores_kernel<<<N, dim3(32, 4)>>>(Hbuf, as1, ad1, asrc, adst, N);
    gat_attn_kernel<<<N, 256>>>(Hbuf, (const float4*)asrc, (const float4*)adst,
                                off, deg, csrc, b1, aggr);

    // ---- layer 2 (only dst < B matters) ----
    {
        dim3 grid(F512 / BN, (N + BM - 1) / BM);
        gemm_bf16x3_kernel<<<grid, 256>>>(N, F512, F512, aggr, W2, Hbuf);
    }
    att_scores_kernel<<<N, dim3(32, 4)>>>(Hbuf, as2, ad2, asrc, adst, N);
    gat_attn_kernel<<<B, 256>>>(Hbuf, (const float4*)asrc, (const float4*)adst,
                                off, deg, csrc, nullptr, aggr);
    head_mean_norm_kernel<<<B, 128>>>(aggr, b2, outseed, B);
}

extern "C" void kernel_launch(void* const* d_in, const int* in_sizes, int n_in,
                              void* d_out, int out_size) {
    int base = n_in - 17;

    const float* im_q = (const float*)d_in[0];
    const float* im_k = (const float*)d_in[1];
    const int*   ei   = (const int*)d_in[2];

    const float* Wq1  = (const float*)d_in[base + 0];
    const float* asq1 = (const float*)d_in[base + 1];
    const float* adq1 = (const float*)d_in[base + 2];
    const float* bq1  = (const float*)d_in[base + 3];
    const float* Wq2  = (const float*)d_in[base + 4];
    const float* asq2 = (const float*)d_in[base + 5];
    const float* adq2 = (const float*)d_in[base + 6];
    const float* bq2  = (const float*)d_in[base + 7];
    const float* Wk1  = (const float*)d_in[base + 8];
    const float* ask1 = (const float*)d_in[base + 9];
    const float* adk1 = (const float*)d_in[base + 10];
    const float* bk1  = (const float*)d_in[base + 11];
    const float* Wk2  = (const float*)d_in[base + 12];
    const float* ask2 = (const float*)d_in[base + 13];
    const float* adk2 = (const float*)d_in[base + 14];
    const float* bk2  = (const float*)d_in[base + 15];
    const float* queue= (const float*)d_in[base + 16];

    int G = in_sizes[base] / F512;
    int N = in_sizes[0] / G;
    int E = in_sizes[2] / 2;
    int R = in_sizes[base + 16] / C128;
    int B = (out_size % (R + 2) == 0) ? out_size / (R + 2) : out_size / (R + 1);
    if (B > N) B = N;
    int ET = E + N;

    float *Hbuf, *aggr, *asrc, *adst, *seedq, *seedk;
    float *Wk1m, *Wk2m, *ask1m, *adk1m, *bk1m, *ask2m, *adk2m, *bk2m;
    int *deg, *off, *cur, *csrc;
    cudaGetSymbolAddress((void**)&Hbuf, g_H);
    cudaGetSymbolAddress((void**)&aggr, g_aggr);
    cudaGetSymbolAddress((void**)&asrc, g_asrc);
    cudaGetSymbolAddress((void**)&adst, g_adst);
    cudaGetSymbolAddress((void**)&seedq, g_seedq);
    cudaGetSymbolAddress((void**)&seedk, g_seedk);
    cudaGetSymbolAddress((void**)&Wk1m, g_Wk1m);
    cudaGetSymbolAddress((void**)&Wk2m, g_Wk2m);
    cudaGetSymbolAddress((void**)&ask1m, g_ask1m);
    cudaGetSymbolAddress((void**)&adk1m, g_adk1m);
    cudaGetSymbolAddress((void**)&bk1m, g_bk1m);
    cudaGetSymbolAddress((void**)&ask2m, g_ask2m);
    cudaGetSymbolAddress((void**)&adk2m, g_adk2m);
    cudaGetSymbolAddress((void**)&bk2m, g_bk2m);
    cudaGetSymbolAddress((void**)&deg, g_deg);
    cudaGetSymbolAddress((void**)&off, g_off);
    cudaGetSymbolAddress((void**)&cur, g_cur);
    cudaGetSymbolAddress((void**)&csrc, g_csrc);

    // ---- CSR build (shared by both encoders & layers) ----
    cudaMemsetAsync(deg, 0, (size_t)N * sizeof(int));
    cudaMemsetAsync(cur, 0, (size_t)N * sizeof(int));
    csr_count_kernel<<<(ET + 255) / 256, 256>>>(ei, E, N, deg);
    csr_scan_kernel<<<1, 1024>>>(deg, off, N);
    csr_fill_kernel<<<(ET + 255) / 256, 256>>>(ei, E, N, off, cur, csrc);

    // ---- momentum blend of key-encoder params: k' = 0.99k + 0.01q ----
    blend_kernel<<<(G * F512 + 255) / 256, 256>>>(Wk1, Wq1, Wk1m, G * F512);
    blend_kernel<<<2, 256>>>(ask1, asq1, ask1m, F512);
    blend_kernel<<<2, 256>>>(adk1, adq1, adk1m, F512);
    blend_kernel<<<2, 256>>>(bk1, bq1, bk1m, F512);
    blend_kernel<<<(F512 * F512 + 255) / 256, 256>>>(Wk2, Wq2, Wk2m, F512 * F512);
    blend_kernel<<<2, 256>>>(ask2, asq2, ask2m, F512);
    blend_kernel<<<2, 256>>>(adk2, adq2, adk2m, F512);
    blend_kernel<<<1, 128>>>(bk2, bq2, bk2m, C128);

    // ---- encoders ----
    run_gat_encoder(im_q, N, E, G, Wq1, asq1, adq1, bq1, Wq2, asq2, adq2, bq2,
                    seedq, B, Hbuf, aggr, asrc, adst, off, deg, csrc);
    run_gat_encoder(im_k, N, E, G, Wk1m, ask1m, adk1m, bk1m, Wk2m, ask2m, adk2m, bk2m,
                    seedk, B, Hbuf, aggr, asrc, adst, off, deg, csrc);

    // ---- logits + zero tail ----
    logits_kernel<<<B, 256>>>(seedq, seedk, queue, (float*)d_out, B, R);
    size_t written = (size_t)B * (R + 1);
    if ((size_t)out_size > written)
        cudaMemsetAsync((float*)d_out + written, 0,
                        ((size_t)out_size - written) * sizeof(float));
}

// round 4
// speedup vs baseline: 2.7023x; 1.3690x over previous
#include <cuda_runtime.h>
#include <cuda_bf16.h>
#include <mma.h>
#include <cstdint>

using namespace nvcuda;

// ---------------------------------------------------------------------------
// MoCoGraph: two 2-layer GAT encoders + MoCo logits.
// GEMMs: bf16 3-term split (hi*hi + hi*lo + lo*hi), pre-split operands,
//        cp.async double-buffered wmma pipeline.
// Attention: CSR gather (no atomics), fused softmax+aggregate per dst node.
// ---------------------------------------------------------------------------

#define NMAX   10240
#define ETMAX  180224
#define F512   512
#define C128   128
#define CAP    512
#define KPAD1  1024

typedef __nv_bfloat16 bf16;

// ------------------------- device scratch (no mallocs) ---------------------
__device__ float g_H   [(size_t)NMAX * F512];
__device__ float g_aggr[(size_t)NMAX * F512];
__device__ float g_asrc[NMAX * 4];
__device__ float g_adst[NMAX * 4];
__device__ float g_seedq[(size_t)NMAX * C128];
__device__ float g_seedk[(size_t)NMAX * C128];
// momentum-blended key params
__device__ float g_Wk1m[1024 * F512];
__device__ float g_Wk2m[F512 * F512];
__device__ float g_ask1m[F512], g_adk1m[F512], g_bk1m[F512];
__device__ float g_ask2m[F512], g_adk2m[F512], g_bk2m[C128];
// CSR
__device__ int g_deg[NMAX];
__device__ int g_off[NMAX + 1];
__device__ int g_cur[NMAX];
__device__ int g_csrc[ETMAX];
// bf16 split operands
__device__ bf16 g_Ah[(size_t)NMAX * KPAD1];
__device__ bf16 g_Al[(size_t)NMAX * KPAD1];
__device__ bf16 g_Ch[(size_t)NMAX * F512];
__device__ bf16 g_Cl[(size_t)NMAX * F512];
__device__ bf16 g_W1h[KPAD1 * F512], g_W1l[KPAD1 * F512];   // [Kp1, 512]
__device__ bf16 g_W2h[F512 * F512],  g_W2l[F512 * F512];    // [512, 512]

// ------------------------------ cp.async helpers ---------------------------
__device__ __forceinline__ uint32_t smem_u32(const void* p) {
    uint32_t a;
    asm("{ .reg .u64 t; cvta.to.shared.u64 t, %1; cvt.u32.u64 %0, t; }" : "=r"(a) : "l"(p));
    return a;
}
__device__ __forceinline__ void cp_async16(uint32_t s, const void* g) {
    asm volatile("cp.async.cg.shared.global [%0], [%1], 16;" :: "r"(s), "l"(g));
}
#define CP_COMMIT() asm volatile("cp.async.commit_group;" ::: "memory")
#define CP_WAIT(n)  asm volatile("cp.async.wait_group %0;" :: "n"(n) : "memory")

// ------------------------------ small kernels ------------------------------
__global__ void blend_kernel(const float* __restrict__ pk,
                             const float* __restrict__ pq,
                             float* __restrict__ out, int n) {
    int i = blockIdx.x * blockDim.x + threadIdx.x;
    if (i < n) out[i] = 0.99f * pk[i] + 0.01f * pq[i];
}

// split fp32 -> bf16 hi/lo, pad to [*, Kp] with zeros; total = Mp*Kp
__global__ void split_pad_kernel(const float* __restrict__ in, int M, int K,
                                 int Kp, long total,
                                 bf16* __restrict__ hi, bf16* __restrict__ lo) {
    long idx = (long)blockIdx.x * blockDim.x + threadIdx.x;
    if (idx >= total) return;
    int r = (int)(idx / Kp), c = (int)(idx % Kp);
    float v = (r < M && c < K) ? in[(size_t)r * K + c] : 0.f;
    bf16 h = __float2bfloat16(v);
    hi[idx] = h;
    lo[idx] = __float2bfloat16(v - __bfloat162float(h));
}

// split weights [K, Nn] -> [Kp, Nn] hi/lo (zero-pad rows >= K)
__global__ void split_padW_kernel(const float* __restrict__ W, int K, int Nn,
                                  int Kp, bf16* __restrict__ hi,
                                  bf16* __restrict__ lo) {
    long idx = (long)blockIdx.x * blockDim.x + threadIdx.x;
    if (idx >= (long)Kp * Nn) return;
    int r = (int)(idx / Nn);
    float v = (r < K) ? W[idx] : 0.f;
    bf16 h = __float2bfloat16(v);
    hi[idx] = h;
    lo[idx] = __float2bfloat16(v - __bfloat162float(h));
}

// ------------------------------- CSR build ---------------------------------
__global__ void csr_count_kernel(const int* __restrict__ ei, int E, int N,
                                 int* __restrict__ deg) {
    int i = blockIdx.x * blockDim.x + threadIdx.x;
    int ET = E + N;
    if (i >= ET) return;
    int d = (i < E) ? ei[E + i] : (i - E);
    atomicAdd(&deg[d], 1);
}

__global__ void csr_scan_kernel(const int* __restrict__ deg,
                                int* __restrict__ off, int N) {
    __shared__ int sh[1024];
    __shared__ int carry;
    int t = threadIdx.x;
    if (t == 0) carry = 0;
    __syncthreads();
    for (int base = 0; base < N; base += 1024) {
        int v = (base + t < N) ? deg[base + t] : 0;
        sh[t] = v;
        __syncthreads();
        for (int o = 1; o < 1024; o <<= 1) {
            int x = (t >= o) ? sh[t - o] : 0;
            __syncthreads();
            sh[t] += x;
            __syncthreads();
        }
        int excl = sh[t] - v + carry;
        if (base + t < N) off[base + t] = excl;
        __syncthreads();
        if (t == 1023) carry += sh[1023];
        __syncthreads();
    }
    if (t == 0) off[N] = carry;
}

__global__ void csr_fill_kernel(const int* __restrict__ ei, int E, int N,
                                const int* __restrict__ off,
                                int* __restrict__ cur,
                                int* __restrict__ csrc) {
    int i = blockIdx.x * blockDim.x + threadIdx.x;
    int ET = E + N;
    if (i >= ET) return;
    int s, d;
    if (i < E) { s = ei[i]; d = ei[E + i]; } else { s = d = i - E; }
    int pos = atomicAdd(&cur[d], 1);
    csrc[off[d] + pos] = s;
}

// --------------- wmma GEMM, pre-split bf16, cp.async pipeline --------------
// A hi/lo: [Mp, K] bf16 (rows padded/zeroed), B hi/lo: [K, Nn] bf16.
// C: [Mp, Nn] fp32 (Mp rows writable). K % 32 == 0, Nn % 128 == 0.
#define BM 128
#define BN 128
#define BK 32
#define A_LD 40              // 32 + 8 pad (bf16 elems)
#define B_LD 136             // 128 + 8 pad
#define ST_AH 0u
#define ST_AL 10240u         // 128*40*2
#define ST_BH 20480u
#define ST_BL 29184u         // + 32*136*2
#define STAGE_B 37888u
#define SMEM_GEMM_BYTES (2 * STAGE_B)

__global__ void __launch_bounds__(256, 1)
gemm_wmma_split_kernel(int K, int Nn,
                       const bf16* __restrict__ Ahg, const bf16* __restrict__ Alg,
                       const bf16* __restrict__ Bhg, const bf16* __restrict__ Blg,
                       float* __restrict__ C) {
    extern __shared__ char smem[];
    const uint32_t sb = smem_u32(smem);
    const int tid = threadIdx.x;
    const int bn = blockIdx.x, bm = blockIdx.y;
    const int warpId = tid >> 5;
    const int wm = warpId & 3;    // 4 row groups of 32
    const int wn = warpId >> 2;   // 2 col groups of 64
    const int nk = K >> 5;

    // load mappings (16B = 8 bf16 chunks)
    // A: 512 chunks per matrix; chunk c: row=c>>2, seg=c&3
    const int ar0 = tid >> 2, as0 = (tid & 3) << 3;
    const int ar1 = (tid + 256) >> 2, as1 = ((tid + 256) & 3) << 3;
    // B: 512 chunks per matrix; chunk c: row=c>>4, seg=c&15
    const int br0 = tid >> 4, bs0 = (tid & 15) << 3;
    const int br1 = (tid + 256) >> 4, bs1 = ((tid + 256) & 15) << 3;

    const size_t aBase = (size_t)(bm * BM);
    const int cCol = bn * BN;

    auto load_stage = [&](int kt, uint32_t stg) {
        const bf16* Ah = Ahg + (aBase + ar0) * K + kt * BK + as0;
        const bf16* Ah1 = Ahg + (aBase + ar1) * K + kt * BK + as1;
        const bf16* Al = Alg + (aBase + ar0) * K + kt * BK + as0;
        const bf16* Al1 = Alg + (aBase + ar1) * K + kt * BK + as1;
        cp_async16(sb + stg + ST_AH + (ar0 * A_LD + as0) * 2, Ah);
        cp_async16(sb + stg + ST_AH + (ar1 * A_LD + as1) * 2, Ah1);
        cp_async16(sb + stg + ST_AL + (ar0 * A_LD + as0) * 2, Al);
        cp_async16(sb + stg + ST_AL + (ar1 * A_LD + as1) * 2, Al1);
        const bf16* Bh = Bhg + (size_t)(kt * BK + br0) * Nn + cCol + bs0;
        const bf16* Bh1 = Bhg + (size_t)(kt * BK + br1) * Nn + cCol + bs1;
        const bf16* Bl = Blg + (size_t)(kt * BK + br0) * Nn + cCol + bs0;
        const bf16* Bl1 = Blg + (size_t)(kt * BK + br1) * Nn + cCol + bs1;
        cp_async16(sb + stg + ST_BH + (br0 * B_LD + bs0) * 2, Bh);
        cp_async16(sb + stg + ST_BH + (br1 * B_LD + bs1) * 2, Bh1);
        cp_async16(sb + stg + ST_BL + (br0 * B_LD + bs0) * 2, Bl);
        cp_async16(sb + stg + ST_BL + (br1 * B_LD + bs1) * 2, Bl1);
        CP_COMMIT();
    };

    wmma::fragment<wmma::accumulator, 16, 16, 16, float> acc[2][4];
#pragma unroll
    for (int i = 0; i < 2; i++)
#pragma unroll
        for (int j = 0; j < 4; j++) wmma::fill_fragment(acc[i][j], 0.0f);

    load_stage(0, 0);

    for (int kt = 0; kt < nk; kt++) {
        const uint32_t stg = (kt & 1) ? STAGE_B : 0u;
        if (kt + 1 < nk) {
            load_stage(kt + 1, (kt & 1) ? 0u : STAGE_B);
            CP_WAIT(1);
        } else {
            CP_WAIT(0);
        }
        __syncthreads();

        const bf16* sAh = (const bf16*)(smem + stg + ST_AH);
        const bf16* sAl = (const bf16*)(smem + stg + ST_AL);
        const bf16* sBh = (const bf16*)(smem + stg + ST_BH);
        const bf16* sBl = (const bf16*)(smem + stg + ST_BL);

#pragma unroll
        for (int kk = 0; kk < BK; kk += 16) {
            wmma::fragment<wmma::matrix_a, 16, 16, 16, bf16, wmma::row_major> ah[2], al[2];
            wmma::fragment<wmma::matrix_b, 16, 16, 16, bf16, wmma::row_major> bh[4], bl[4];
#pragma unroll
            for (int i = 0; i < 2; i++) {
                wmma::load_matrix_sync(ah[i], sAh + (wm * 32 + i * 16) * A_LD + kk, A_LD);
                wmma::load_matrix_sync(al[i], sAl + (wm * 32 + i * 16) * A_LD + kk, A_LD);
            }
#pragma unroll
            for (int j = 0; j < 4; j++) {
                wmma::load_matrix_sync(bh[j], sBh + kk * B_LD + wn * 64 + j * 16, B_LD);
                wmma::load_matrix_sync(bl[j], sBl + kk * B_LD + wn * 64 + j * 16, B_LD);
            }
#pragma unroll
            for (int i = 0; i < 2; i++)
#pragma unroll
                for (int j = 0; j < 4; j++) {
                    wmma::mma_sync(acc[i][j], ah[i], bh[j], acc[i][j]);
                    wmma::mma_sync(acc[i][j], ah[i], bl[j], acc[i][j]);
                    wmma::mma_sync(acc[i][j], al[i], bh[j], acc[i][j]);
                }
        }
        __syncthreads();
    }

#pragma unroll
    for (int i = 0; i < 2; i++) {
        int row = bm * BM + wm * 32 + i * 16;
#pragma unroll
        for (int j = 0; j < 4; j++) {
            int col = cCol + wn * 64 + j * 16;
            wmma::store_matrix_sync(&C[(size_t)row * Nn + col], acc[i][j],
                                    Nn, wmma::mem_row_major);
        }
    }
}

// ---------------------------- attention scores -----------------------------
__global__ void att_scores_kernel(const float* __restrict__ Hf,
                                  const float* __restrict__ att_s,
                                  const float* __restrict__ att_d,
                                  float* __restrict__ a_s,
                                  float* __restrict__ a_d, int N) {
    int n = blockIdx.x;
    if (n >= N) return;
    int h = threadIdx.y;
    int lane = threadIdx.x;
    const float* row = Hf + (size_t)n * F512 + h * C128;
    float ss = 0.f, sd = 0.f;
#pragma unroll
    for (int j = 0; j < 4; j++) {
        int c = lane + 32 * j;
        float v = row[c];
        ss += v * att_s[h * C128 + c];
        sd += v * att_d[h * C128 + c];
    }
#pragma unroll
    for (int o = 16; o > 0; o >>= 1) {
        ss += __shfl_down_sync(0xffffffffu, ss, o);
        sd += __shfl_down_sync(0xffffffffu, sd, o);
    }
    if (lane == 0) { a_s[n * 4 + h] = ss; a_d[n * 4 + h] = sd; }
}

// ---------------- fused per-dst softmax + aggregation ----------------------
__device__ __forceinline__ float leaky(float e) { return e > 0.f ? e : 0.2f * e; }

__global__ __launch_bounds__(256)
void gat_attn_kernel(const float* __restrict__ Hf,
                     const float4* __restrict__ a_s4,
                     const float4* __restrict__ a_d4,
                     const int* __restrict__ off,
                     const int* __restrict__ deg_arr,
                     const int* __restrict__ csrc,
                     const float* __restrict__ bias,
                     float* __restrict__ outbuf) {
    int d = blockIdx.x;
    int t = threadIdx.x;
    int lane = t & 31, wid = t >> 5;

    __shared__ int   s_list[CAP];
    __shared__ float w[CAP][4];
    __shared__ float red[8][4];
    __shared__ float mx_s[4], invd_s[4];

    const int start = off[d];
    const int deg = deg_arr[d];
    const float4 ad = a_d4[d];

    float m0 = -1e30f, m1 = -1e30f, m2 = -1e30f, m3 = -1e30f;
    for (int j = t; j < deg; j += 256) {
        int s = csrc[start + j];
        float4 as = a_s4[s];
        float e0 = leaky(as.x + ad.x);
        float e1 = leaky(as.y + ad.y);
        float e2 = leaky(as.z + ad.z);
        float e3 = leaky(as.w + ad.w);
        if (j < CAP) {
            s_list[j] = s;
            w[j][0] = e0; w[j][1] = e1; w[j][2] = e2; w[j][3] = e3;
        }
        m0 = fmaxf(m0, e0); m1 = fmaxf(m1, e1);
        m2 = fmaxf(m2, e2); m3 = fmaxf(m3, e3);
    }
#pragma unroll
    for (int o = 16; o > 0; o >>= 1) {
        m0 = fmaxf(m0, __shfl_xor_sync(0xffffffffu, m0, o));
        m1 = fmaxf(m1, __shfl_xor_sync(0xffffffffu, m1, o));
        m2 = fmaxf(m2, __shfl_xor_sync(0xffffffffu, m2, o));
        m3 = fmaxf(m3, __shfl_xor_sync(0xffffffffu, m3, o));
    }
    if (lane == 0) { red[wid][0] = m0; red[wid][1] = m1; red[wid][2] = m2; red[wid][3] = m3; }
    __syncthreads();
    if (t < 4) {
        float mm = -1e30f;
#pragma unroll
        for (int k = 0; k < 8; k++) mm = fmaxf(mm, red[k][t]);
        mx_s[t] = mm;
    }
    __syncthreads();
    const float mx0 = mx_s[0], mx1 = mx_s[1], mx2 = mx_s[2], mx3 = mx_s[3];

    float s0 = 0.f, s1 = 0.f, s2 = 0.f, s3 = 0.f;
    for (int j = t; j < deg; j += 256) {
        float e0, e1, e2, e3;
        if (j < CAP) {
            e0 = w[j][0]; e1 = w[j][1]; e2 = w[j][2]; e3 = w[j][3];
        } else {
            int s = csrc[start + j];
            float4 as = a_s4[s];
            e0 = leaky(as.x + ad.x); e1 = leaky(as.y + ad.y);
            e2 = leaky(as.z + ad.z); e3 = leaky(as.w + ad.w);
        }
        float x0 = expf(e0 - mx0), x1 = expf(e1 - mx1);
        float x2 = expf(e2 - mx2), x3 = expf(e3 - mx3);
        if (j < CAP) { w[j][0] = x0; w[j][1] = x1; w[j][2] = x2; w[j][3] = x3; }
        s0 += x0; s1 += x1; s2 += x2; s3 += x3;
    }
#pragma unroll
    for (int o = 16; o > 0; o >>= 1) {
        s0 += __shfl_xor_sync(0xffffffffu, s0, o);
        s1 += __shfl_xor_sync(0xffffffffu, s1, o);
        s2 += __shfl_xor_sync(0xffffffffu, s2, o);
        s3 += __shfl_xor_sync(0xffffffffu, s3, o);
    }
    __syncthreads();
    if (lane == 0) { red[wid][0] = s0; red[wid][1] = s1; red[wid][2] = s2; red[wid][3] = s3; }
    __syncthreads();
    if (t < 4) {
        float ssum = 0.f;
#pragma unroll
        for (int k = 0; k < 8; k++) ssum += red[k][t];
        invd_s[t] = 1.0f / (ssum + 1e-16f);
    }
    __syncthreads();

    const int c2 = t * 2;
    const int h = c2 >> 7;
    const float inv = invd_s[h];
    const float mxh = mx_s[h];
    float acc0 = 0.f, acc1 = 0.f;
    for (int j = 0; j < deg; j++) {
        int s;
        float ww;
        if (j < CAP) {
            s = s_list[j];
            ww = w[j][h];
        } else {
            s = csrc[start + j];
            const float* asp = (const float*)&a_s4[s];
            const float* adp = (const float*)&ad;
            ww = expf(leaky(asp[h] + adp[h]) - mxh);
        }
        float alpha = ww * inv;
        float2 v = *(const float2*)(Hf + (size_t)s * F512 + c2);
        acc0 += v.x * alpha;
        acc1 += v.y * alpha;
    }
    if (bias) {
        acc0 = fmaxf(acc0 + bias[c2], 0.f);
        acc1 = fmaxf(acc1 + bias[c2 + 1], 0.f);
    }
    *(float2*)(outbuf + (size_t)d * F512 + c2) = make_float2(acc0, acc1);
}

// layer-2 epilogue
__global__ void head_mean_norm_kernel(const float* __restrict__ aggr,
                                      const float* __restrict__ bias,
                                      float* __restrict__ outv, int B) {
    int n = blockIdx.x;
    if (n >= B) return;
    int c = threadIdx.x;
    size_t base = (size_t)n * F512;
    float v = 0.25f * (aggr[base + c] + aggr[base + 128 + c] +
                       aggr[base + 256 + c] + aggr[base + 384 + c]) + bias[c];
    float s = v * v;
#pragma unroll
    for (int o = 16; o > 0; o >>= 1) s += __shfl_down_sync(0xffffffffu, s, o);
    __shared__ float red[4];
    if ((c & 31) == 0) red[c >> 5] = s;
    __syncthreads();
    float tot = red[0] + red[1] + red[2] + red[3];
    outv[(size_t)n * C128 + c] = v * rsqrtf(tot + 1e-24f);
}

__global__ void logits_kernel(const float* __restrict__ q,
                              const float* __restrict__ kv,
                              const float* __restrict__ queue,
                              float* __restrict__ out, int B, int R) {
    int n = blockIdx.x;
    if (n >= B) return;
    __shared__ float qs[128];
    int tid = threadIdx.x;
    if (tid < 128) qs[tid] = q[(size_t)n * 128 + tid];
    __syncthreads();
    for (int col = tid; col <= R; col += blockDim.x) {
        float acc = 0.f;
        if (col == 0) {
#pragma unroll 4
            for (int c = 0; c < 128; c++) acc += qs[c] * kv[(size_t)n * 128 + c];
        } else {
            int kk = col - 1;
#pragma unroll 4
            for (int c = 0; c < 128; c++) acc += qs[c] * queue[(size_t)c * R + kk];
        }
        out[(size_t)n * (R + 1) + col] = acc / 0.2f;
    }
}

// ------------------------------- host helpers ------------------------------
static void run_gemm(int Mp, int K, const bf16* Ah, const bf16* Al,
                     const bf16* Bh, const bf16* Bl, float* C) {
    dim3 grid(F512 / BN, Mp / BM);
    gemm_wmma_split_kernel<<<grid, 256, SMEM_GEMM_BYTES>>>(K, F512, Ah, Al, Bh, Bl, C);
}

static void run_gat_encoder(const float* x, int N, int Mp, int E, int G, int Kp1,
                            const float* W1, const float* as1, const float* ad1, const float* b1,
                            const float* W2, const float* as2, const float* ad2, const float* b2,
                            float* outseed, int B,
                            float* Hbuf, float* aggr, float* asrc, float* adst,
                            int* off, int* deg, int* csrc,
                            bf16* Ah, bf16* Al, bf16* Chs, bf16* Cls,
                            bf16* W1h, bf16* W1l, bf16* W2h, bf16* W2l) {
    long totA = (long)Mp * Kp1;
    // ---- layer 1 ----
    split_pad_kernel<<<(int)((totA + 255) / 256), 256>>>(x, N, G, Kp1, totA, Ah, Al);
    split_padW_kernel<<<(Kp1 * F512 + 255) / 256, 256>>>(W1, G, F512, Kp1, W1h, W1l);
    run_gemm(Mp, Kp1, Ah, Al, W1h, W1l, Hbuf);
    att_scores_kernel<<<N, dim3(32, 4)>>>(Hbuf, as1, ad1, asrc, adst, N);
    gat_attn_kernel<<<N, 256>>>(Hbuf, (const float4*)asrc, (const float4*)adst,
                                off, deg, csrc, b1, aggr);
    // ---- layer 2 ----
    long totC = (long)Mp * F512;
    split_pad_kernel<<<(int)((totC + 255) / 256), 256>>>(aggr, N, F512, F512, totC, Chs, Cls);
    split_padW_kernel<<<(F512 * F512 + 255) / 256, 256>>>(W2, F512, F512, F512, W2h, W2l);
    run_gemm(Mp, F512, Chs, Cls, W2h, W2l, Hbuf);
    att_scores_kernel<<<N, dim3(32, 4)>>>(Hbuf, as2, ad2, asrc, adst, N);
    gat_attn_kernel<<<B, 256>>>(Hbuf, (const float4*)asrc, (const float4*)adst,
                                off, deg, csrc, nullptr, aggr);
    head_mean_norm_kernel<<<B, 128>>>(aggr, b2, outseed, B);
}

extern "C" void kernel_launch(void* const* d_in, const int* in_sizes, int n_in,
                              void* d_out, int out_size) {
    int base = n_in - 17;

    const float* im_q = (const float*)d_in[0];
    const float* im_k = (const float*)d_in[1];
    const int*   ei   = (const int*)d_in[2];

    const float* Wq1  = (const float*)d_in[base + 0];
    const float* asq1 = (const float*)d_in[base + 1];
    const float* adq1 = (const float*)d_in[base + 2];
    const float* bq1  = (const float*)d_in[base + 3];
    const float* Wq2  = (const float*)d_in[base + 4];
    const float* asq2 = (const float*)d_in[base + 5];
    const float* adq2 = (const float*)d_in[base + 6];
    const float* bq2  = (const float*)d_in[base + 7];
    const float* Wk1  = (const float*)d_in[base + 8];
    const float* ask1 = (const float*)d_in[base + 9];
    const float* adk1 = (const float*)d_in[base + 10];
    const float* bk1  = (const float*)d_in[base + 11];
    const float* Wk2  = (const float*)d_in[base + 12];
    const float* ask2 = (const float*)d_in[base + 13];
    const float* adk2 = (const float*)d_in[base + 14];
    const float* bk2  = (const float*)d_in[base + 15];
    const float* queue= (const float*)d_in[base + 16];

    int G = in_sizes[base] / F512;
    int N = in_sizes[0] / G;
    int E = in_sizes[2] / 2;
    int R = in_sizes[base + 16] / C128;
    int B = (out_size % (R + 2) == 0) ? out_size / (R + 2) : out_size / (R + 1);
    if (B > N) B = N;
    int ET = E + N;
    int Mp = (N + 127) & ~127;
    int Kp1 = (G + 31) & ~31;

    float *Hbuf, *aggr, *asrc, *adst, *seedq, *seedk;
    float *Wk1m, *Wk2m, *ask1m, *adk1m, *bk1m, *ask2m, *adk2m, *bk2m;
    int *deg, *off, *cur, *csrc;
    bf16 *Ah, *Al, *Chs, *Cls, *W1h, *W1l, *W2h, *W2l;
    cudaGetSymbolAddress((void**)&Hbuf, g_H);
    cudaGetSymbolAddress((void**)&aggr, g_aggr);
    cudaGetSymbolAddress((void**)&asrc, g_asrc);
    cudaGetSymbolAddress((void**)&adst, g_adst);
    cudaGetSymbolAddress((void**)&seedq, g_seedq);
    cudaGetSymbolAddress((void**)&seedk, g_seedk);
    cudaGetSymbolAddress((void**)&Wk1m, g_Wk1m);
    cudaGetSymbolAddress((void**)&Wk2m, g_Wk2m);
    cudaGetSymbolAddress((void**)&ask1m, g_ask1m);
    cudaGetSymbolAddress((void**)&adk1m, g_adk1m);
    cudaGetSymbolAddress((void**)&bk1m, g_bk1m);
    cudaGetSymbolAddress((void**)&ask2m, g_ask2m);
    cudaGetSymbolAddress((void**)&adk2m, g_adk2m);
    cudaGetSymbolAddress((void**)&bk2m, g_bk2m);
    cudaGetSymbolAddress((void**)&deg, g_deg);
    cudaGetSymbolAddress((void**)&off, g_off);
    cudaGetSymbolAddress((void**)&cur, g_cur);
    cudaGetSymbolAddress((void**)&csrc, g_csrc);
    cudaGetSymbolAddress((void**)&Ah, g_Ah);
    cudaGetSymbolAddress((void**)&Al, g_Al);
    cudaGetSymbolAddress((void**)&Chs, g_Ch);
    cudaGetSymbolAddress((void**)&Cls, g_Cl);
    cudaGetSymbolAddress((void**)&W1h, g_W1h);
    cudaGetSymbolAddress((void**)&W1l, g_W1l);
    cudaGetSymbolAddress((void**)&W2h, g_W2h);
    cudaGetSymbolAddress((void**)&W2l, g_W2l);

    cudaFuncSetAttribute(gemm_wmma_split_kernel,
                         cudaFuncAttributeMaxDynamicSharedMemorySize, SMEM_GEMM_BYTES);

    // ---- CSR build ----
    cudaMemsetAsync(deg, 0, (size_t)N * sizeof(int));
    cudaMemsetAsync(cur, 0, (size_t)N * sizeof(int));
    csr_count_kernel<<<(ET + 255) / 256, 256>>>(ei, E, N, deg);
    csr_scan_kernel<<<1, 1024>>>(deg, off, N);
    csr_fill_kernel<<<(ET + 255) / 256, 256>>>(ei, E, N, off, cur, csrc);

    // ---- momentum blend ----
    blend_kernel<<<(G * F512 + 255) / 256, 256>>>(Wk1, Wq1, Wk1m, G * F512);
    blend_kernel<<<2, 256>>>(ask1, asq1, ask1m, F512);
    blend_kernel<<<2, 256>>>(adk1, adq1, adk1m, F512);
    blend_kernel<<<2, 256>>>(bk1, bq1, bk1m, F512);
    blend_kernel<<<(F512 * F512 + 255) / 256, 256>>>(Wk2, Wq2, Wk2m, F512 * F512);
    blend_kernel<<<2, 256>>>(ask2, asq2, ask2m, F512);
    blend_kernel<<<2, 256>>>(adk2, adq2, adk2m, F512);
    blend_kernel<<<1, 128>>>(bk2, bq2, bk2m, C128);

    // ---- encoders ----
    run_gat_encoder(im_q, N, Mp, E, G, Kp1, Wq1, asq1, adq1, bq1, Wq2, asq2, adq2, bq2,
                    seedq, B, Hbuf, aggr, asrc, adst, off, deg, csrc,
                    Ah, Al, Chs, Cls, W1h, W1l, W2h, W2l);
    run_gat_encoder(im_k, N, Mp, E, G, Kp1, Wk1m, ask1m, adk1m, bk1m, Wk2m, ask2m, adk2m, bk2m,
                    seedk, B, Hbuf, aggr, asrc, adst, off, deg, csrc,
                    Ah, Al, Chs, Cls, W1h, W1l, W2h, W2l);

    // ---- logits + zero tail ----
    logits_kernel<<<B, 256>>>(seedq, seedk, queue, (float*)d_out, B, R);
    size_t written = (size_t)B * (R + 1);
    if ((size_t)out_size > written)
        cudaMemsetAsync((float*)d_out + written, 0,
                        ((size_t)out_size - written) * sizeof(float));
}

// round 5
// speedup vs baseline: 3.1469x; 1.1645x over previous
#include <cuda_runtime.h>
#include <cuda_bf16.h>
#include <mma.h>
#include <cstdint>

using namespace nvcuda;

// ---------------------------------------------------------------------------
// MoCoGraph: two 2-layer GAT encoders + MoCo logits.
// GEMMs: bf16 3-term split, pre-split operands, cp.async pipeline, batched
//        over both encoders (grid.z=2). Attention: CSR gather, fused softmax
//        + aggregate + bias/relu + bf16-split epilogue, batched (grid.y=2).
// ---------------------------------------------------------------------------

#define NMAX   10240
#define ETMAX  180224
#define F512   512
#define C128   128
#define CAP    512
#define KPAD1  1024

typedef __nv_bfloat16 bf16;

// ------------------------- device scratch (no mallocs) ---------------------
__device__ float g_H   [2 * (size_t)NMAX * F512];       // GEMM outputs (q,k)
__device__ bf16  g_A1h [2 * (size_t)NMAX * KPAD1];      // layer-1 A split
__device__ bf16  g_A1l [2 * (size_t)NMAX * KPAD1];
__device__ bf16  g_A2h [2 * (size_t)NMAX * F512];       // layer-2 A split
__device__ bf16  g_A2l [2 * (size_t)NMAX * F512];
__device__ bf16  g_W1h [2 * KPAD1 * F512], g_W1l[2 * KPAD1 * F512];
__device__ bf16  g_W2h [2 * F512 * F512],  g_W2l[2 * F512 * F512];
__device__ float g_asrc[2 * NMAX * 4];
__device__ float g_adst[2 * NMAX * 4];
__device__ float g_seedq[(size_t)NMAX * C128];
__device__ float g_seedk[(size_t)NMAX * C128];
// blended key-encoder attention/bias vectors
__device__ float g_ask1m[F512], g_adk1m[F512], g_bk1m[F512];
__device__ float g_ask2m[F512], g_adk2m[F512], g_bk2m[C128];
// CSR
__device__ int g_deg[NMAX];
__device__ int g_off[NMAX + 1];
__device__ int g_cur[NMAX];
__device__ int g_csrc[ETMAX];

// ------------------------------ helpers ------------------------------------
__device__ __forceinline__ uint32_t smem_u32(const void* p) {
    uint32_t a;
    asm("{ .reg .u64 t; cvta.to.shared.u64 t, %1; cvt.u32.u64 %0, t; }" : "=r"(a) : "l"(p));
    return a;
}
__device__ __forceinline__ void cp_async16(uint32_t s, const void* g) {
    asm volatile("cp.async.cg.shared.global [%0], [%1], 16;" :: "r"(s), "l"(g));
}
#define CP_COMMIT() asm volatile("cp.async.commit_group;" ::: "memory")
#define CP_WAIT(n)  asm volatile("cp.async.wait_group %0;" :: "n"(n) : "memory")

__device__ __forceinline__ void split2(float v, bf16& h, bf16& l) {
    h = __float2bfloat16(v);
    l = __float2bfloat16(v - __bfloat162float(h));
}

// ------------------------------ small kernels ------------------------------
__global__ void blend_kernel(const float* __restrict__ pk,
                             const float* __restrict__ pq,
                             float* __restrict__ out, int n) {
    int i = blockIdx.x * blockDim.x + threadIdx.x;
    if (i < n) out[i] = 0.99f * pk[i] + 0.01f * pq[i];
}

// split fp32 -> bf16 hi/lo, pad to [*, Kp] with zeros; total = Mp*Kp
__global__ void split_pad_kernel(const float* __restrict__ in, int M, int K,
                                 int Kp, long total,
                                 bf16* __restrict__ hi, bf16* __restrict__ lo) {
    long idx = (long)blockIdx.x * blockDim.x + threadIdx.x;
    if (idx >= total) return;
    int r = (int)(idx / Kp), c = (int)(idx % Kp);
    float v = (r < M && c < K) ? in[(size_t)r * K + c] : 0.f;
    bf16 h, l; split2(v, h, l);
    hi[idx] = h; lo[idx] = l;
}

// split weights [K, Nn] -> [Kp, Nn] hi/lo (zero-pad rows >= K)
__global__ void split_padW_kernel(const float* __restrict__ W, int K, int Nn,
                                  int Kp, bf16* __restrict__ hi,
                                  bf16* __restrict__ lo) {
    long idx = (long)blockIdx.x * blockDim.x + threadIdx.x;
    if (idx >= (long)Kp * Nn) return;
    int r = (int)(idx / Nn);
    float v = (r < K) ? W[idx] : 0.f;
    bf16 h, l; split2(v, h, l);
    hi[idx] = h; lo[idx] = l;
}

// momentum blend + split + pad in one pass (key-encoder weights)
__global__ void blend_splitW_kernel(const float* __restrict__ Wk,
                                    const float* __restrict__ Wq,
                                    int K, int Nn, int Kp,
                                    bf16* __restrict__ hi, bf16* __restrict__ lo) {
    long idx = (long)blockIdx.x * blockDim.x + threadIdx.x;
    if (idx >= (long)Kp * Nn) return;
    int r = (int)(idx / Nn);
    float v = (r < K) ? (0.99f * Wk[idx] + 0.01f * Wq[idx]) : 0.f;
    bf16 h, l; split2(v, h, l);
    hi[idx] = h; lo[idx] = l;
}

// ------------------------------- CSR build ---------------------------------
__global__ void csr_count_kernel(const int* __restrict__ ei, int E, int N,
                                 int* __restrict__ deg) {
    int i = blockIdx.x * blockDim.x + threadIdx.x;
    int ET = E + N;
    if (i >= ET) return;
    int d = (i < E) ? ei[E + i] : (i - E);
    atomicAdd(&deg[d], 1);
}

__global__ void csr_scan_kernel(const int* __restrict__ deg,
                                int* __restrict__ off, int N) {
    __shared__ int sh[1024];
    __shared__ int carry;
    int t = threadIdx.x;
    if (t == 0) carry = 0;
    __syncthreads();
    for (int base = 0; base < N; base += 1024) {
        int v = (base + t < N) ? deg[base + t] : 0;
        sh[t] = v;
        __syncthreads();
        for (int o = 1; o < 1024; o <<= 1) {
            int x = (t >= o) ? sh[t - o] : 0;
            __syncthreads();
            sh[t] += x;
            __syncthreads();
        }
        int excl = sh[t] - v + carry;
        if (base + t < N) off[base + t] = excl;
        __syncthreads();
        if (t == 1023) carry += sh[1023];
        __syncthreads();
    }
    if (t == 0) off[N] = carry;
}

__global__ void csr_fill_kernel(const int* __restrict__ ei, int E, int N,
                                const int* __restrict__ off,
                                int* __restrict__ cur,
                                int* __restrict__ csrc) {
    int i = blockIdx.x * blockDim.x + threadIdx.x;
    int ET = E + N;
    if (i >= ET) return;
    int s, d;
    if (i < E) { s = ei[i]; d = ei[E + i]; } else { s = d = i - E; }
    int pos = atomicAdd(&cur[d], 1);
    csrc[off[d] + pos] = s;
}

// --------------- batched wmma GEMM, pre-split bf16, cp.async ---------------
#define BM 128
#define BN 128
#define BK 32
#define A_LD 40
#define B_LD 136
#define ST_AH 0u
#define ST_AL 10240u
#define ST_BH 20480u
#define ST_BL 29184u
#define STAGE_B 37888u
#define SMEM_GEMM_BYTES (2 * STAGE_B)

__global__ void __launch_bounds__(256, 1)
gemm_wmma_split_kernel(int K, int Nn,
                       const bf16* __restrict__ Ahg0, const bf16* __restrict__ Alg0,
                       const bf16* __restrict__ Bhg0, const bf16* __restrict__ Blg0,
                       float* __restrict__ C0,
                       size_t strideA, size_t strideB, size_t strideC) {
    extern __shared__ char smem[];
    const uint32_t sb = smem_u32(smem);
    const int tid = threadIdx.x;
    const int bn = blockIdx.x, bm = blockIdx.y;
    const size_t z = blockIdx.z;
    const bf16* Ahg = Ahg0 + z * strideA;
    const bf16* Alg = Alg0 + z * strideA;
    const bf16* Bhg = Bhg0 + z * strideB;
    const bf16* Blg = Blg0 + z * strideB;
    float* C = C0 + z * strideC;

    const int warpId = tid >> 5;
    const int wm = warpId & 3;
    const int wn = warpId >> 2;
    const int nk = K >> 5;

    const int ar0 = tid >> 2, as0 = (tid & 3) << 3;
    const int ar1 = (tid + 256) >> 2, as1 = ((tid + 256) & 3) << 3;
    const int br0 = tid >> 4, bs0 = (tid & 15) << 3;
    const int br1 = (tid + 256) >> 4, bs1 = ((tid + 256) & 15) << 3;

    const size_t aBase = (size_t)(bm * BM);
    const int cCol = bn * BN;

    auto load_stage = [&](int kt, uint32_t stg) {
        cp_async16(sb + stg + ST_AH + (ar0 * A_LD + as0) * 2,
                   Ahg + (aBase + ar0) * K + kt * BK + as0);
        cp_async16(sb + stg + ST_AH + (ar1 * A_LD + as1) * 2,
                   Ahg + (aBase + ar1) * K + kt * BK + as1);
        cp_async16(sb + stg + ST_AL + (ar0 * A_LD + as0) * 2,
                   Alg + (aBase + ar0) * K + kt * BK + as0);
        cp_async16(sb + stg + ST_AL + (ar1 * A_LD + as1) * 2,
                   Alg + (aBase + ar1) * K + kt * BK + as1);
        cp_async16(sb + stg + ST_BH + (br0 * B_LD + bs0) * 2,
                   Bhg + (size_t)(kt * BK + br0) * Nn + cCol + bs0);
        cp_async16(sb + stg + ST_BH + (br1 * B_LD + bs1) * 2,
                   Bhg + (size_t)(kt * BK + br1) * Nn + cCol + bs1);
        cp_async16(sb + stg + ST_BL + (br0 * B_LD + bs0) * 2,
                   Blg + (size_t)(kt * BK + br0) * Nn + cCol + bs0);
        cp_async16(sb + stg + ST_BL + (br1 * B_LD + bs1) * 2,
                   Blg + (size_t)(kt * BK + br1) * Nn + cCol + bs1);
        CP_COMMIT();
    };

    wmma::fragment<wmma::accumulator, 16, 16, 16, float> acc[2][4];
#pragma unroll
    for (int i = 0; i < 2; i++)
#pragma unroll
        for (int j = 0; j < 4; j++) wmma::fill_fragment(acc[i][j], 0.0f);

    load_stage(0, 0);

    for (int kt = 0; kt < nk; kt++) {
        const uint32_t stg = (kt & 1) ? STAGE_B : 0u;
        if (kt + 1 < nk) {
            load_stage(kt + 1, (kt & 1) ? 0u : STAGE_B);
            CP_WAIT(1);
        } else {
            CP_WAIT(0);
        }
        __syncthreads();

        const bf16* sAh = (const bf16*)(smem + stg + ST_AH);
        const bf16* sAl = (const bf16*)(smem + stg + ST_AL);
        const bf16* sBh = (const bf16*)(smem + stg + ST_BH);
        const bf16* sBl = (const bf16*)(smem + stg + ST_BL);

#pragma unroll
        for (int kk = 0; kk < BK; kk += 16) {
            wmma::fragment<wmma::matrix_a, 16, 16, 16, bf16, wmma::row_major> ah[2], al[2];
            wmma::fragment<wmma::matrix_b, 16, 16, 16, bf16, wmma::row_major> bh[4], bl[4];
#pragma unroll
            for (int i = 0; i < 2; i++) {
                wmma::load_matrix_sync(ah[i], sAh + (wm * 32 + i * 16) * A_LD + kk, A_LD);
                wmma::load_matrix_sync(al[i], sAl + (wm * 32 + i * 16) * A_LD + kk, A_LD);
            }
#pragma unroll
            for (int j = 0; j < 4; j++) {
                wmma::load_matrix_sync(bh[j], sBh + kk * B_LD + wn * 64 + j * 16, B_LD);
                wmma::load_matrix_sync(bl[j], sBl + kk * B_LD + wn * 64 + j * 16, B_LD);
            }
#pragma unroll
            for (int i = 0; i < 2; i++)
#pragma unroll
                for (int j = 0; j < 4; j++) {
                    wmma::mma_sync(acc[i][j], ah[i], bh[j], acc[i][j]);
                    wmma::mma_sync(acc[i][j], ah[i], bl[j], acc[i][j]);
                    wmma::mma_sync(acc[i][j], al[i], bh[j], acc[i][j]);
                }
        }
        __syncthreads();
    }

#pragma unroll
    for (int i = 0; i < 2; i++) {
        int row = bm * BM + wm * 32 + i * 16;
#pragma unroll
        for (int j = 0; j < 4; j++) {
            int col = cCol + wn * 64 + j * 16;
            wmma::store_matrix_sync(&C[(size_t)row * Nn + col], acc[i][j],
                                    Nn, wmma::mem_row_major);
        }
    }
}

// ---------------------------- attention scores (batched) -------------------
__global__ void att_scores_kernel(const float* __restrict__ Hbase, size_t hstride,
                                  const float* __restrict__ s0, const float* __restrict__ d0,
                                  const float* __restrict__ s1, const float* __restrict__ d1,
                                  float* __restrict__ a_s_base,
                                  float* __restrict__ a_d_base, int N) {
    int n = blockIdx.x;
    if (n >= N) return;
    int z = blockIdx.y;
    const float* Hf = Hbase + (size_t)z * hstride;
    const float* att_s = z ? s1 : s0;
    const float* att_d = z ? d1 : d0;
    float* a_s = a_s_base + (size_t)z * NMAX * 4;
    float* a_d = a_d_base + (size_t)z * NMAX * 4;

    int h = threadIdx.y;
    int lane = threadIdx.x;
    const float* row = Hf + (size_t)n * F512 + h * C128;
    float ss = 0.f, sd = 0.f;
#pragma unroll
    for (int j = 0; j < 4; j++) {
        int c = lane + 32 * j;
        float v = row[c];
        ss += v * att_s[h * C128 + c];
        sd += v * att_d[h * C128 + c];
    }
#pragma unroll
    for (int o = 16; o > 0; o >>= 1) {
        ss += __shfl_down_sync(0xffffffffu, ss, o);
        sd += __shfl_down_sync(0xffffffffu, sd, o);
    }
    if (lane == 0) { a_s[n * 4 + h] = ss; a_d[n * 4 + h] = sd; }
}

// ---------------- fused per-dst softmax + aggregation (batched) ------------
// If outh != null: apply bias+relu, write bf16 hi/lo (layer-1 path).
// Else: write fp32 to outf (layer-2 path).
__device__ __forceinline__ float leaky(float e) { return e > 0.f ? e : 0.2f * e; }

__global__ __launch_bounds__(256)
void gat_attn_kernel(const float* __restrict__ Hbase, size_t hstride,
                     const float4* __restrict__ a_s_base,
                     const float4* __restrict__ a_d_base,
                     const int* __restrict__ off,
                     const int* __restrict__ deg_arr,
                     const int* __restrict__ csrc,
                     const float* __restrict__ bias0,
                     const float* __restrict__ bias1,
                     bf16* __restrict__ outh, bf16* __restrict__ outl,
                     float* __restrict__ outf, size_t ostride) {
    int d = blockIdx.x;
    int z = blockIdx.y;
    int t = threadIdx.x;
    int lane = t & 31, wid = t >> 5;

    const float* Hf = Hbase + (size_t)z * hstride;
    const float4* a_s4 = a_s_base + (size_t)z * NMAX;
    const float4* a_d4 = a_d_base + (size_t)z * NMAX;
    const float* bias = z ? bias1 : bias0;

    __shared__ int   s_list[CAP];
    __shared__ float w[CAP][4];
    __shared__ float red[8][4];
    __shared__ float mx_s[4], invd_s[4];

    const int start = off[d];
    const int deg = deg_arr[d];
    const float4 ad = a_d4[d];

    float m0 = -1e30f, m1 = -1e30f, m2 = -1e30f, m3 = -1e30f;
    for (int j = t; j < deg; j += 256) {
        int s = csrc[start + j];
        float4 as = a_s4[s];
        float e0 = leaky(as.x + ad.x);
        float e1 = leaky(as.y + ad.y);
        float e2 = leaky(as.z + ad.z);
        float e3 = leaky(as.w + ad.w);
        if (j < CAP) {
            s_list[j] = s;
            w[j][0] = e0; w[j][1] = e1; w[j][2] = e2; w[j][3] = e3;
        }
        m0 = fmaxf(m0, e0); m1 = fmaxf(m1, e1);
        m2 = fmaxf(m2, e2); m3 = fmaxf(m3, e3);
    }
#pragma unroll
    for (int o = 16; o > 0; o >>= 1) {
        m0 = fmaxf(m0, __shfl_xor_sync(0xffffffffu, m0, o));
        m1 = fmaxf(m1, __shfl_xor_sync(0xffffffffu, m1, o));
        m2 = fmaxf(m2, __shfl_xor_sync(0xffffffffu, m2, o));
        m3 = fmaxf(m3, __shfl_xor_sync(0xffffffffu, m3, o));
    }
    if (lane == 0) { red[wid][0] = m0; red[wid][1] = m1; red[wid][2] = m2; red[wid][3] = m3; }
    __syncthreads();
    if (t < 4) {
        float mm = -1e30f;
#pragma unroll
        for (int k = 0; k < 8; k++) mm = fmaxf(mm, red[k][t]);
        mx_s[t] = mm;
    }
    __syncthreads();
    const float mx0 = mx_s[0], mx1 = mx_s[1], mx2 = mx_s[2], mx3 = mx_s[3];

    float s0 = 0.f, s1 = 0.f, s2 = 0.f, s3 = 0.f;
    for (int j = t; j < deg; j += 256) {
        float e0, e1, e2, e3;
        if (j < CAP) {
            e0 = w[j][0]; e1 = w[j][1]; e2 = w[j][2]; e3 = w[j][3];
        } else {
            int s = csrc[start + j];
            float4 as = a_s4[s];
            e0 = leaky(as.x + ad.x); e1 = leaky(as.y + ad.y);
            e2 = leaky(as.z + ad.z); e3 = leaky(as.w + ad.w);
        }
        float x0 = expf(e0 - mx0), x1 = expf(e1 - mx1);
        float x2 = expf(e2 - mx2), x3 = expf(e3 - mx3);
        if (j < CAP) { w[j][0] = x0; w[j][1] = x1; w[j][2] = x2; w[j][3] = x3; }
        s0 += x0; s1 += x1; s2 += x2; s3 += x3;
    }
#pragma unroll
    for (int o = 16; o > 0; o >>= 1) {
        s0 += __shfl_xor_sync(0xffffffffu, s0, o);
        s1 += __shfl_xor_sync(0xffffffffu, s1, o);
        s2 += __shfl_xor_sync(0xffffffffu, s2, o);
        s3 += __shfl_xor_sync(0xffffffffu, s3, o);
    }
    __syncthreads();
    if (lane == 0) { red[wid][0] = s0; red[wid][1] = s1; red[wid][2] = s2; red[wid][3] = s3; }
    __syncthreads();
    if (t < 4) {
        float ssum = 0.f;
#pragma unroll
        for (int k = 0; k < 8; k++) ssum += red[k][t];
        invd_s[t] = 1.0f / (ssum + 1e-16f);
    }
    __syncthreads();

    const int c2 = t * 2;
    const int h = c2 >> 7;
    const float inv = invd_s[h];
    const float mxh = mx_s[h];
    float acc0 = 0.f, acc1 = 0.f;
    for (int j = 0; j < deg; j++) {
        int s;
        float ww;
        if (j < CAP) {
            s = s_list[j];
            ww = w[j][h];
        } else {
            s = csrc[start + j];
            const float* asp = (const float*)&a_s4[s];
            const float* adp = (const float*)&ad;
            ww = expf(leaky(asp[h] + adp[h]) - mxh);
        }
        float alpha = ww * inv;
        float2 v = *(const float2*)(Hf + (size_t)s * F512 + c2);
        acc0 += v.x * alpha;
        acc1 += v.y * alpha;
    }
    if (outh) {
        acc0 = fmaxf(acc0 + bias[c2], 0.f);
        acc1 = fmaxf(acc1 + bias[c2 + 1], 0.f);
        bf16 h0, l0, h1, l1;
        split2(acc0, h0, l0);
        split2(acc1, h1, l1);
        size_t o = (size_t)z * NMAX * F512 + (size_t)d * F512 + c2;
        *(uint32_t*)(outh + o) = (uint32_t)__bfloat16_as_ushort(h0) |
                                 ((uint32_t)__bfloat16_as_ushort(h1) << 16);
        *(uint32_t*)(outl + o) = (uint32_t)__bfloat16_as_ushort(l0) |
                                 ((uint32_t)__bfloat16_as_ushort(l1) << 16);
    } else {
        size_t o = (size_t)z * ostride + (size_t)d * F512 + c2;
        *(float2*)(outf + o) = make_float2(acc0, acc1);
    }
}

// layer-2 epilogue (batched)
__global__ void head_mean_norm_kernel(const float* __restrict__ aggr_base, size_t astride,
                                      const float* __restrict__ bias0,
                                      const float* __restrict__ bias1,
                                      float* __restrict__ outq,
                                      float* __restrict__ outk, int B) {
    int n = blockIdx.x;
    if (n >= B) return;
    int z = blockIdx.y;
    const float* aggr = aggr_base + (size_t)z * astride;
    const float* bias = z ? bias1 : bias0;
    float* outv = z ? outk : outq;
    int c = threadIdx.x;
    size_t base = (size_t)n * F512;
    float v = 0.25f * (aggr[base + c] + aggr[base + 128 + c] +
                       aggr[base + 256 + c] + aggr[base + 384 + c]) + bias[c];
    float s = v * v;
#pragma unroll
    for (int o = 16; o > 0; o >>= 1) s += __shfl_down_sync(0xffffffffu, s, o);
    __shared__ float red[4];
    if ((c & 31) == 0) red[c >> 5] = s;
    __syncthreads();
    float tot = red[0] + red[1] + red[2] + red[3];
    outv[(size_t)n * C128 + c] = v * rsqrtf(tot + 1e-24f);
}

__global__ void logits_kernel(const float* __restrict__ q,
                              const float* __restrict__ kv,
                              const float* __restrict__ queue,
                              float* __restrict__ out, int B, int R) {
    int n = blockIdx.x;
    if (n >= B) return;
    __shared__ float qs[128];
    int tid = threadIdx.x;
    if (tid < 128) qs[tid] = q[(size_t)n * 128 + tid];
    __syncthreads();
    for (int col = tid; col <= R; col += blockDim.x) {
        float acc = 0.f;
        if (col == 0) {
#pragma unroll 4
            for (int c = 0; c < 128; c++) acc += qs[c] * kv[(size_t)n * 128 + c];
        } else {
            int kk = col - 1;
#pragma unroll 4
            for (int c = 0; c < 128; c++) acc += qs[c] * queue[(size_t)c * R + kk];
        }
        out[(size_t)n * (R + 1) + col] = acc / 0.2f;
    }
}

// ------------------------------- launch ------------------------------------
extern "C" void kernel_launch(void* const* d_in, const int* in_sizes, int n_in,
                              void* d_out, int out_size) {
    int base = n_in - 17;

    const float* im_q = (const float*)d_in[0];
    const float* im_k = (const float*)d_in[1];
    const int*   ei   = (const int*)d_in[2];

    const float* Wq1  = (const float*)d_in[base + 0];
    const float* asq1 = (const float*)d_in[base + 1];
    const float* adq1 = (const float*)d_in[base + 2];
    const float* bq1  = (const float*)d_in[base + 3];
    const float* Wq2  = (const float*)d_in[base + 4];
    const float* asq2 = (const float*)d_in[base + 5];
    const float* adq2 = (const float*)d_in[base + 6];
    const float* bq2  = (const float*)d_in[base + 7];
    const float* Wk1  = (const float*)d_in[base + 8];
    const float* ask1 = (const float*)d_in[base + 9];
    const float* adk1 = (const float*)d_in[base + 10];
    const float* bk1  = (const float*)d_in[base + 11];
    const float* Wk2  = (const float*)d_in[base + 12];
    const float* ask2 = (const float*)d_in[base + 13];
    const float* adk2 = (const float*)d_in[base + 14];
    const float* bk2  = (const float*)d_in[base + 15];
    const float* queue= (const float*)d_in[base + 16];

    int G = in_sizes[base] / F512;
    int N = in_sizes[0] / G;
    int E = in_sizes[2] / 2;
    int R = in_sizes[base + 16] / C128;
    int B = (out_size % (R + 2) == 0) ? out_size / (R + 2) : out_size / (R + 1);
    if (B > N) B = N;
    int ET = E + N;
    int Mp = (N + 127) & ~127;
    int Kp1 = (G + 31) & ~31;

    float *Hbuf, *asrc, *adst, *seedq, *seedk;
    float *ask1m, *adk1m, *bk1m, *ask2m, *adk2m, *bk2m;
    int *deg, *off, *cur, *csrc;
    bf16 *A1h, *A1l, *A2h, *A2l, *W1h, *W1l, *W2h, *W2l;
    cudaGetSymbolAddress((void**)&Hbuf, g_H);
    cudaGetSymbolAddress((void**)&asrc, g_asrc);
    cudaGetSymbolAddress((void**)&adst, g_adst);
    cudaGetSymbolAddress((void**)&seedq, g_seedq);
    cudaGetSymbolAddress((void**)&seedk, g_seedk);
    cudaGetSymbolAddress((void**)&ask1m, g_ask1m);
    cudaGetSymbolAddress((void**)&adk1m, g_adk1m);
    cudaGetSymbolAddress((void**)&bk1m, g_bk1m);
    cudaGetSymbolAddress((void**)&ask2m, g_ask2m);
    cudaGetSymbolAddress((void**)&adk2m, g_adk2m);
    cudaGetSymbolAddress((void**)&bk2m, g_bk2m);
    cudaGetSymbolAddress((void**)&deg, g_deg);
    cudaGetSymbolAddress((void**)&off, g_off);
    cudaGetSymbolAddress((void**)&cur, g_cur);
    cudaGetSymbolAddress((void**)&csrc, g_csrc);
    cudaGetSymbolAddress((void**)&A1h, g_A1h);
    cudaGetSymbolAddress((void**)&A1l, g_A1l);
    cudaGetSymbolAddress((void**)&A2h, g_A2h);
    cudaGetSymbolAddress((void**)&A2l, g_A2l);
    cudaGetSymbolAddress((void**)&W1h, g_W1h);
    cudaGetSymbolAddress((void**)&W1l, g_W1l);
    cudaGetSymbolAddress((void**)&W2h, g_W2h);
    cudaGetSymbolAddress((void**)&W2l, g_W2l);

    cudaFuncSetAttribute(gemm_wmma_split_kernel,
                         cudaFuncAttributeMaxDynamicSharedMemorySize, SMEM_GEMM_BYTES);

    const size_t a1slot = (size_t)NMAX * KPAD1;     // bf16 elems per encoder
    const size_t a2slot = (size_t)NMAX * F512;
    const size_t hslot  = (size_t)NMAX * F512;      // fp32 elems per encoder
    const size_t w1slot = (size_t)Kp1 * F512;
    const size_t w2slot = (size_t)F512 * F512;
    // layer-2 fp32 attention output reuses A1h storage (exactly NMAX*512 floats/slot)
    float* aggr2 = (float*)A1h;
    const size_t aggr2slot = (size_t)NMAX * F512 / 2 * 2;  // NMAX*512 floats

    long totA1 = (long)Mp * Kp1;

    // ---- launches 1-5 (ncu -s 5 skips these; #6 = layer-1 GEMM) ----
    split_pad_kernel<<<(int)((totA1 + 255) / 256), 256>>>(im_q, N, G, Kp1, totA1, A1h, A1l);
    split_pad_kernel<<<(int)((totA1 + 255) / 256), 256>>>(im_k, N, G, Kp1, totA1,
                                                          A1h + a1slot, A1l + a1slot);
    split_padW_kernel<<<(int)((w1slot + 255) / 256), 256>>>(Wq1, G, F512, Kp1, W1h, W1l);
    blend_splitW_kernel<<<(int)((w1slot + 255) / 256), 256>>>(Wk1, Wq1, G, F512, Kp1,
                                                              W1h + w1slot, W1l + w1slot);
    split_padW_kernel<<<(int)((w2slot + 255) / 256), 256>>>(Wq2, F512, F512, F512, W2h, W2l);

    // ---- #6: batched layer-1 GEMM (ncu capture target) ----
    {
        dim3 grid(F512 / BN, Mp / BM, 2);
        gemm_wmma_split_kernel<<<grid, 256, SMEM_GEMM_BYTES>>>(
            Kp1, F512, A1h, A1l, W1h, W1l, Hbuf, a1slot, w1slot, hslot);
    }

    // ---- remaining prep (independent of layer-1 GEMM result) ----
    blend_splitW_kernel<<<(int)((w2slot + 255) / 256), 256>>>(Wk2, Wq2, F512, F512, F512,
                                                              W2h + w2slot, W2l + w2slot);
    blend_kernel<<<2, 256>>>(ask1, asq1, ask1m, F512);
    blend_kernel<<<2, 256>>>(adk1, adq1, adk1m, F512);
    blend_kernel<<<2, 256>>>(bk1, bq1, bk1m, F512);
    blend_kernel<<<2, 256>>>(ask2, asq2, ask2m, F512);
    blend_kernel<<<2, 256>>>(adk2, adq2, adk2m, F512);
    blend_kernel<<<1, 128>>>(bk2, bq2, bk2m, C128);

    cudaMemsetAsync(deg, 0, (size_t)N * sizeof(int));
    cudaMemsetAsync(cur, 0, (size_t)N * sizeof(int));
    csr_count_kernel<<<(ET + 255) / 256, 256>>>(ei, E, N, deg);
    csr_scan_kernel<<<1, 1024>>>(deg, off, N);
    csr_fill_kernel<<<(ET + 255) / 256, 256>>>(ei, E, N, off, cur, csrc);

    // zero pad rows of layer-2 A (rows N..Mp-1), both hi/lo, both encoders
    if (Mp > N) {
        size_t padElems = (size_t)(Mp - N) * F512;
        cudaMemsetAsync(A2h + (size_t)N * F512, 0, padElems * sizeof(bf16));
        cudaMemsetAsync(A2l + (size_t)N * F512, 0, padElems * sizeof(bf16));
        cudaMemsetAsync(A2h + a2slot + (size_t)N * F512, 0, padElems * sizeof(bf16));
        cudaMemsetAsync(A2l + a2slot + (size_t)N * F512, 0, padElems * sizeof(bf16));
    }

    // ---- layer-1 attention (batched): writes bf16 A2 hi/lo with bias+relu ----
    att_scores_kernel<<<dim3(N, 2), dim3(32, 4)>>>(Hbuf, hslot, asq1, adq1, ask1m, adk1m,
                                                   asrc, adst, N);
    gat_attn_kernel<<<dim3(N, 2), 256>>>(Hbuf, hslot, (const float4*)asrc,
                                         (const float4*)adst, off, deg, csrc,
                                         bq1, bk1m, A2h, A2l, nullptr, 0);

    // ---- layer-2 GEMM (batched) ----
    {
        dim3 grid(F512 / BN, Mp / BM, 2);
        gemm_wmma_split_kernel<<<grid, 256, SMEM_GEMM_BYTES>>>(
            F512, F512, A2h, A2l, W2h, W2l, Hbuf, a2slot, w2slot, hslot);
    }

    // ---- layer-2 attention (batched, only dst < B), fp32 out ----
    att_scores_kernel<<<dim3(N, 2), dim3(32, 4)>>>(Hbuf, hslot, asq2, adq2, ask2m, adk2m,
                                                   asrc, adst, N);
    gat_attn_kernel<<<dim3(B, 2), 256>>>(Hbuf, hslot, (const float4*)asrc,
                                         (const float4*)adst, off, deg, csrc,
                                         nullptr, nullptr, nullptr, nullptr,
                                         aggr2, aggr2slot);

    head_mean_norm_kernel<<<dim3(B, 2), 128>>>(aggr2, aggr2slot, bq2, bk2m,
                                               seedq, seedk, B);

    // ---- logits + zero tail ----
    logits_kernel<<<B, 256>>>(seedq, seedk, queue, (float*)d_out, B, R);
    size_t written = (size_t)B * (R + 1);
    if ((size_t)out_size > written)
        cudaMemsetAsync((float*)d_out + written, 0,
                        ((size_t)out_size - written) * sizeof(float));
}

// round 6
// speedup vs baseline: 3.3030x; 1.0496x over previous
#include <cuda_runtime.h>
#include <cuda_bf16.h>
#include <mma.h>
#include <cstdint>

using namespace nvcuda;

// ---------------------------------------------------------------------------
// MoCoGraph: two 2-layer GAT encoders + MoCo logits.
// GEMMs: bf16 3-term split, pre-split operands, BK=64 cp.async double-buffer,
//        batched over both encoders (grid.z=2).
// Attention: CSR gather, fused softmax+aggregate+bias/relu+bf16-split epilogue,
//        batched (grid.y=2).
// ---------------------------------------------------------------------------

#define NMAX   10240
#define ETMAX  180224
#define F512   512
#define C128   128
#define CAP    512
#define KPAD1  1024

typedef __nv_bfloat16 bf16;

// ------------------------- device scratch (no mallocs) ---------------------
__device__ float g_H   [2 * (size_t)NMAX * F512];       // GEMM outputs (q,k)
__device__ bf16  g_A1h [2 * (size_t)NMAX * KPAD1];      // layer-1 A split
__device__ bf16  g_A1l [2 * (size_t)NMAX * KPAD1];
__device__ bf16  g_A2h [2 * (size_t)NMAX * F512];       // layer-2 A split
__device__ bf16  g_A2l [2 * (size_t)NMAX * F512];
__device__ bf16  g_W1h [2 * KPAD1 * F512], g_W1l[2 * KPAD1 * F512];
__device__ bf16  g_W2h [2 * F512 * F512],  g_W2l[2 * F512 * F512];
__device__ float g_asrc[2 * NMAX * 4];
__device__ float g_adst[2 * NMAX * 4];
__device__ float g_seedq[(size_t)NMAX * C128];
__device__ float g_seedk[(size_t)NMAX * C128];
// blended key-encoder attention/bias vectors
__device__ float g_ask1m[F512], g_adk1m[F512], g_bk1m[F512];
__device__ float g_ask2m[F512], g_adk2m[F512], g_bk2m[C128];
// CSR
__device__ int g_deg[NMAX];
__device__ int g_off[NMAX + 1];
__device__ int g_cur[NMAX];
__device__ int g_csrc[ETMAX];

// ------------------------------ helpers ------------------------------------
__device__ __forceinline__ uint32_t smem_u32(const void* p) {
    uint32_t a;
    asm("{ .reg .u64 t; cvta.to.shared.u64 t, %1; cvt.u32.u64 %0, t; }" : "=r"(a) : "l"(p));
    return a;
}
__device__ __forceinline__ void cp_async16(uint32_t s, const void* g) {
    asm volatile("cp.async.cg.shared.global [%0], [%1], 16;" :: "r"(s), "l"(g));
}
#define CP_COMMIT() asm volatile("cp.async.commit_group;" ::: "memory")
#define CP_WAIT(n)  asm volatile("cp.async.wait_group %0;" :: "n"(n) : "memory")

__device__ __forceinline__ void split2(float v, bf16& h, bf16& l) {
    h = __float2bfloat16(v);
    l = __float2bfloat16(v - __bfloat162float(h));
}

// ------------------------------ small kernels ------------------------------
__global__ void blend_kernel(const float* __restrict__ pk,
                             const float* __restrict__ pq,
                             float* __restrict__ out, int n) {
    int i = blockIdx.x * blockDim.x + threadIdx.x;
    if (i < n) out[i] = 0.99f * pk[i] + 0.01f * pq[i];
}

// batched split: z=0 -> in0, z=1 -> in1; out slot stride = Mp*Kp
__global__ void split_pad2_kernel(const float* __restrict__ in0,
                                  const float* __restrict__ in1,
                                  int M, int K, int Kp, long total,
                                  bf16* __restrict__ hi, bf16* __restrict__ lo) {
    long idx = (long)blockIdx.x * blockDim.x + threadIdx.x;
    if (idx >= total) return;
    const float* in = blockIdx.y ? in1 : in0;
    size_t o = (size_t)blockIdx.y * total + idx;
    int r = (int)(idx / Kp), c = (int)(idx % Kp);
    float v = (r < M && c < K) ? in[(size_t)r * K + c] : 0.f;
    bf16 h, l; split2(v, h, l);
    hi[o] = h; lo[o] = l;
}

// split weights [K, Nn] -> [Kp, Nn] hi/lo (zero-pad rows >= K)
__global__ void split_padW_kernel(const float* __restrict__ W, int K, int Nn,
                                  int Kp, bf16* __restrict__ hi,
                                  bf16* __restrict__ lo) {
    long idx = (long)blockIdx.x * blockDim.x + threadIdx.x;
    if (idx >= (long)Kp * Nn) return;
    int r = (int)(idx / Nn);
    float v = (r < K) ? W[idx] : 0.f;
    bf16 h, l; split2(v, h, l);
    hi[idx] = h; lo[idx] = l;
}

// momentum blend + split + pad in one pass (key-encoder weights)
__global__ void blend_splitW_kernel(const float* __restrict__ Wk,
                                    const float* __restrict__ Wq,
                                    int K, int Nn, int Kp,
                                    bf16* __restrict__ hi, bf16* __restrict__ lo) {
    long idx = (long)blockIdx.x * blockDim.x + threadIdx.x;
    if (idx >= (long)Kp * Nn) return;
    int r = (int)(idx / Nn);
    float v = (r < K) ? (0.99f * Wk[idx] + 0.01f * Wq[idx]) : 0.f;
    bf16 h, l; split2(v, h, l);
    hi[idx] = h; lo[idx] = l;
}

// ------------------------------- CSR build ---------------------------------
__global__ void csr_count_kernel(const int* __restrict__ ei, int E, int N,
                                 int* __restrict__ deg) {
    int i = blockIdx.x * blockDim.x + threadIdx.x;
    int ET = E + N;
    if (i >= ET) return;
    int d = (i < E) ? ei[E + i] : (i - E);
    atomicAdd(&deg[d], 1);
}

__global__ void csr_scan_kernel(const int* __restrict__ deg,
                                int* __restrict__ off, int N) {
    __shared__ int sh[1024];
    __shared__ int carry;
    int t = threadIdx.x;
    if (t == 0) carry = 0;
    __syncthreads();
    for (int base = 0; base < N; base += 1024) {
        int v = (base + t < N) ? deg[base + t] : 0;
        sh[t] = v;
        __syncthreads();
        for (int o = 1; o < 1024; o <<= 1) {
            int x = (t >= o) ? sh[t - o] : 0;
            __syncthreads();
            sh[t] += x;
            __syncthreads();
        }
        int excl = sh[t] - v + carry;
        if (base + t < N) off[base + t] = excl;
        __syncthreads();
        if (t == 1023) carry += sh[1023];
        __syncthreads();
    }
    if (t == 0) off[N] = carry;
}

__global__ void csr_fill_kernel(const int* __restrict__ ei, int E, int N,
                                const int* __restrict__ off,
                                int* __restrict__ cur,
                                int* __restrict__ csrc) {
    int i = blockIdx.x * blockDim.x + threadIdx.x;
    int ET = E + N;
    if (i >= ET) return;
    int s, d;
    if (i < E) { s = ei[i]; d = ei[E + i]; } else { s = d = i - E; }
    int pos = atomicAdd(&cur[d], 1);
    csrc[off[d] + pos] = s;
}

// --------------- batched wmma GEMM, pre-split bf16, BK=64 ------------------
#define BM 128
#define BN 128
#define BK 64
#define A_LD 72              // 64 + 8 pad (bf16)
#define B_LD 136             // 128 + 8 pad
#define A_TILE_B 18432u      // 128*72*2
#define B_TILE_B 17408u      // 64*136*2
#define ST_AH 0u
#define ST_AL A_TILE_B
#define ST_BH (2u * A_TILE_B)
#define ST_BL (2u * A_TILE_B + B_TILE_B)
#define STAGE_B (2u * A_TILE_B + 2u * B_TILE_B)   // 71680
#define SMEM_GEMM_BYTES (2 * STAGE_B)             // 143360

__global__ void __launch_bounds__(256, 1)
gemm_wmma_split_kernel(int K, int Nn,
                       const bf16* __restrict__ Ahg0, const bf16* __restrict__ Alg0,
                       const bf16* __restrict__ Bhg0, const bf16* __restrict__ Blg0,
                       float* __restrict__ C0,
                       size_t strideA, size_t strideB, size_t strideC) {
    extern __shared__ char smem[];
    const uint32_t sb = smem_u32(smem);
    const int tid = threadIdx.x;
    const int bn = blockIdx.x, bm = blockIdx.y;
    const size_t z = blockIdx.z;
    const bf16* Ahg = Ahg0 + z * strideA;
    const bf16* Alg = Alg0 + z * strideA;
    const bf16* Bhg = Bhg0 + z * strideB;
    const bf16* Blg = Blg0 + z * strideB;
    float* C = C0 + z * strideC;

    const int warpId = tid >> 5;
    const int wm = warpId & 3;
    const int wn = warpId >> 2;
    const int nk = K >> 6;

    const size_t aBase = (size_t)(bm * BM);
    const int cCol = bn * BN;

    // A: 1024 16B-chunks per h/l tile: row = idx>>3, seg = (idx&7)*8
    // B: 1024 16B-chunks per h/l tile: row = idx>>4, seg = (idx&15)*8
    auto load_stage = [&](int kt, uint32_t stg) {
#pragma unroll
        for (int i = 0; i < 4; i++) {
            int idx = tid + (i << 8);
            int ar = idx >> 3, as = (idx & 7) << 3;
            const size_t ago = (aBase + ar) * K + kt * BK + as;
            uint32_t aso = (uint32_t)(ar * A_LD + as) * 2;
            cp_async16(sb + stg + ST_AH + aso, Ahg + ago);
            cp_async16(sb + stg + ST_AL + aso, Alg + ago);
            int br = idx >> 4, bs = (idx & 15) << 3;
            const size_t bgo = (size_t)(kt * BK + br) * Nn + cCol + bs;
            uint32_t bso = (uint32_t)(br * B_LD + bs) * 2;
            cp_async16(sb + stg + ST_BH + bso, Bhg + bgo);
            cp_async16(sb + stg + ST_BL + bso, Blg + bgo);
        }
        CP_COMMIT();
    };

    wmma::fragment<wmma::accumulator, 16, 16, 16, float> acc[2][4];
#pragma unroll
    for (int i = 0; i < 2; i++)
#pragma unroll
        for (int j = 0; j < 4; j++) wmma::fill_fragment(acc[i][j], 0.0f);

    load_stage(0, 0);

    for (int kt = 0; kt < nk; kt++) {
        const uint32_t stg = (kt & 1) ? STAGE_B : 0u;
        if (kt + 1 < nk) {
            load_stage(kt + 1, (kt & 1) ? 0u : STAGE_B);
            CP_WAIT(1);
        } else {
            CP_WAIT(0);
        }
        __syncthreads();

        const bf16* sAh = (const bf16*)(smem + stg + ST_AH);
        const bf16* sAl = (const bf16*)(smem + stg + ST_AL);
        const bf16* sBh = (const bf16*)(smem + stg + ST_BH);
        const bf16* sBl = (const bf16*)(smem + stg + ST_BL);

#pragma unroll
        for (int kk = 0; kk < BK; kk += 16) {
            wmma::fragment<wmma::matrix_a, 16, 16, 16, bf16, wmma::row_major> ah[2], al[2];
            wmma::fragment<wmma::matrix_b, 16, 16, 16, bf16, wmma::row_major> bh[4], bl[4];
#pragma unroll
            for (int i = 0; i < 2; i++) {
                wmma::load_matrix_sync(ah[i], sAh + (wm * 32 + i * 16) * A_LD + kk, A_LD);
                wmma::load_matrix_sync(al[i], sAl + (wm * 32 + i * 16) * A_LD + kk, A_LD);
            }
#pragma unroll
            for (int j = 0; j < 4; j++) {
                wmma::load_matrix_sync(bh[j], sBh + kk * B_LD + wn * 64 + j * 16, B_LD);
                wmma::load_matrix_sync(bl[j], sBl + kk * B_LD + wn * 64 + j * 16, B_LD);
            }
#pragma unroll
            for (int i = 0; i < 2; i++)
#pragma unroll
                for (int j = 0; j < 4; j++) {
                    wmma::mma_sync(acc[i][j], ah[i], bh[j], acc[i][j]);
                    wmma::mma_sync(acc[i][j], ah[i], bl[j], acc[i][j]);
                    wmma::mma_sync(acc[i][j], al[i], bh[j], acc[i][j]);
                }
        }
        __syncthreads();
    }

#pragma unroll
    for (int i = 0; i < 2; i++) {
        int row = bm * BM + wm * 32 + i * 16;
#pragma unroll
        for (int j = 0; j < 4; j++) {
            int col = cCol + wn * 64 + j * 16;
            wmma::store_matrix_sync(&C[(size_t)row * Nn + col], acc[i][j],
                                    Nn, wmma::mem_row_major);
        }
    }
}

// ---------------------------- attention scores (batched) -------------------
__global__ void att_scores_kernel(const float* __restrict__ Hbase, size_t hstride,
                                  const float* __restrict__ s0, const float* __restrict__ d0,
                                  const float* __restrict__ s1, const float* __restrict__ d1,
                                  float* __restrict__ a_s_base,
                                  float* __restrict__ a_d_base, int N) {
    int n = blockIdx.x;
    if (n >= N) return;
    int z = blockIdx.y;
    const float* Hf = Hbase + (size_t)z * hstride;
    const float* att_s = z ? s1 : s0;
    const float* att_d = z ? d1 : d0;
    float* a_s = a_s_base + (size_t)z * NMAX * 4;
    float* a_d = a_d_base + (size_t)z * NMAX * 4;

    int h = threadIdx.y;
    int lane = threadIdx.x;
    const float* row = Hf + (size_t)n * F512 + h * C128;
    float ss = 0.f, sd = 0.f;
#pragma unroll
    for (int j = 0; j < 4; j++) {
        int c = lane + 32 * j;
        float v = row[c];
        ss += v * att_s[h * C128 + c];
        sd += v * att_d[h * C128 + c];
    }
#pragma unroll
    for (int o = 16; o > 0; o >>= 1) {
        ss += __shfl_down_sync(0xffffffffu, ss, o);
        sd += __shfl_down_sync(0xffffffffu, sd, o);
    }
    if (lane == 0) { a_s[n * 4 + h] = ss; a_d[n * 4 + h] = sd; }
}

// ---------------- fused per-dst softmax + aggregation (batched) ------------
__device__ __forceinline__ float leaky(float e) { return e > 0.f ? e : 0.2f * e; }

__global__ __launch_bounds__(256)
void gat_attn_kernel(const float* __restrict__ Hbase, size_t hstride,
                     const float4* __restrict__ a_s_base,
                     const float4* __restrict__ a_d_base,
                     const int* __restrict__ off,
                     const int* __restrict__ deg_arr,
                     const int* __restrict__ csrc,
                     const float* __restrict__ bias0,
                     const float* __restrict__ bias1,
                     bf16* __restrict__ outh, bf16* __restrict__ outl,
                     float* __restrict__ outf, size_t ostride) {
    int d = blockIdx.x;
    int z = blockIdx.y;
    int t = threadIdx.x;
    int lane = t & 31, wid = t >> 5;

    const float* Hf = Hbase + (size_t)z * hstride;
    const float4* a_s4 = a_s_base + (size_t)z * NMAX;
    const float4* a_d4 = a_d_base + (size_t)z * NMAX;
    const float* bias = z ? bias1 : bias0;

    __shared__ int   s_list[CAP];
    __shared__ float w[CAP][4];
    __shared__ float red[8][4];
    __shared__ float mx_s[4], invd_s[4];

    const int start = off[d];
    const int deg = deg_arr[d];
    const float4 ad = a_d4[d];

    float m0 = -1e30f, m1 = -1e30f, m2 = -1e30f, m3 = -1e30f;
    for (int j = t; j < deg; j += 256) {
        int s = csrc[start + j];
        float4 as = a_s4[s];
        float e0 = leaky(as.x + ad.x);
        float e1 = leaky(as.y + ad.y);
        float e2 = leaky(as.z + ad.z);
        float e3 = leaky(as.w + ad.w);
        if (j < CAP) {
            s_list[j] = s;
            w[j][0] = e0; w[j][1] = e1; w[j][2] = e2; w[j][3] = e3;
        }
        m0 = fmaxf(m0, e0); m1 = fmaxf(m1, e1);
        m2 = fmaxf(m2, e2); m3 = fmaxf(m3, e3);
    }
#pragma unroll
    for (int o = 16; o > 0; o >>= 1) {
        m0 = fmaxf(m0, __shfl_xor_sync(0xffffffffu, m0, o));
        m1 = fmaxf(m1, __shfl_xor_sync(0xffffffffu, m1, o));
        m2 = fmaxf(m2, __shfl_xor_sync(0xffffffffu, m2, o));
        m3 = fmaxf(m3, __shfl_xor_sync(0xffffffffu, m3, o));
    }
    if (lane == 0) { red[wid][0] = m0; red[wid][1] = m1; red[wid][2] = m2; red[wid][3] = m3; }
    __syncthreads();
    if (t < 4) {
        float mm = -1e30f;
#pragma unroll
        for (int k = 0; k < 8; k++) mm = fmaxf(mm, red[k][t]);
        mx_s[t] = mm;
    }
    __syncthreads();
    const float mx0 = mx_s[0], mx1 = mx_s[1], mx2 = mx_s[2], mx3 = mx_s[3];

    float s0 = 0.f, s1 = 0.f, s2 = 0.f, s3 = 0.f;
    for (int j = t; j < deg; j += 256) {
        float e0, e1, e2, e3;
        if (j < CAP) {
            e0 = w[j][0]; e1 = w[j][1]; e2 = w[j][2]; e3 = w[j][3];
        } else {
            int s = csrc[start + j];
            float4 as = a_s4[s];
            e0 = leaky(as.x + ad.x); e1 = leaky(as.y + ad.y);
            e2 = leaky(as.z + ad.z); e3 = leaky(as.w + ad.w);
        }
        float x0 = expf(e0 - mx0), x1 = expf(e1 - mx1);
        float x2 = expf(e2 - mx2), x3 = expf(e3 - mx3);
        if (j < CAP) { w[j][0] = x0; w[j][1] = x1; w[j][2] = x2; w[j][3] = x3; }
        s0 += x0; s1 += x1; s2 += x2; s3 += x3;
    }
#pragma unroll
    for (int o = 16; o > 0; o >>= 1) {
        s0 += __shfl_xor_sync(0xffffffffu, s0, o);
        s1 += __shfl_xor_sync(0xffffffffu, s1, o);
        s2 += __shfl_xor_sync(0xffffffffu, s2, o);
        s3 += __shfl_xor_sync(0xffffffffu, s3, o);
    }
    __syncthreads();
    if (lane == 0) { red[wid][0] = s0; red[wid][1] = s1; red[wid][2] = s2; red[wid][3] = s3; }
    __syncthreads();
    if (t < 4) {
        float ssum = 0.f;
#pragma unroll
        for (int k = 0; k < 8; k++) ssum += red[k][t];
        invd_s[t] = 1.0f / (ssum + 1e-16f);
    }
    __syncthreads();

    const int c2 = t * 2;
    const int h = c2 >> 7;
    const float inv = invd_s[h];
    const float mxh = mx_s[h];
    float acc0 = 0.f, acc1 = 0.f;
    for (int j = 0; j < deg; j++) {
        int s;
        float ww;
        if (j < CAP) {
            s = s_list[j];
            ww = w[j][h];
        } else {
            s = csrc[start + j];
            const float* asp = (const float*)&a_s4[s];
            const float* adp = (const float*)&ad;
            ww = expf(leaky(asp[h] + adp[h]) - mxh);
        }
        float alpha = ww * inv;
        float2 v = *(const float2*)(Hf + (size_t)s * F512 + c2);
        acc0 += v.x * alpha;
        acc1 += v.y * alpha;
    }
    if (outh) {
        acc0 = fmaxf(acc0 + bias[c2], 0.f);
        acc1 = fmaxf(acc1 + bias[c2 + 1], 0.f);
        bf16 h0, l0, h1, l1;
        split2(acc0, h0, l0);
        split2(acc1, h1, l1);
        size_t o = (size_t)z * NMAX * F512 + (size_t)d * F512 + c2;
        *(uint32_t*)(outh + o) = (uint32_t)__bfloat16_as_ushort(h0) |
                                 ((uint32_t)__bfloat16_as_ushort(h1) << 16);
        *(uint32_t*)(outl + o) = (uint32_t)__bfloat16_as_ushort(l0) |
                                 ((uint32_t)__bfloat16_as_ushort(l1) << 16);
    } else {
        size_t o = (size_t)z * ostride + (size_t)d * F512 + c2;
        *(float2*)(outf + o) = make_float2(acc0, acc1);
    }
}

// layer-2 epilogue (batched)
__global__ void head_mean_norm_kernel(const float* __restrict__ aggr_base, size_t astride,
                                      const float* __restrict__ bias0,
                                      const float* __restrict__ bias1,
                                      float* __restrict__ outq,
                                      float* __restrict__ outk, int B) {
    int n = blockIdx.x;
    if (n >= B) return;
    int z = blockIdx.y;
    const float* aggr = aggr_base + (size_t)z * astride;
    const float* bias = z ? bias1 : bias0;
    float* outv = z ? outk : outq;
    int c = threadIdx.x;
    size_t base = (size_t)n * F512;
    float v = 0.25f * (aggr[base + c] + aggr[base + 128 + c] +
                       aggr[base + 256 + c] + aggr[base + 384 + c]) + bias[c];
    float s = v * v;
#pragma unroll
    for (int o = 16; o > 0; o >>= 1) s += __shfl_down_sync(0xffffffffu, s, o);
    __shared__ float red[4];
    if ((c & 31) == 0) red[c >> 5] = s;
    __syncthreads();
    float tot = red[0] + red[1] + red[2] + red[3];
    outv[(size_t)n * C128 + c] = v * rsqrtf(tot + 1e-24f);
}

__global__ void logits_kernel(const float* __restrict__ q,
                              const float* __restrict__ kv,
                              const float* __restrict__ queue,
                              float* __restrict__ out, int B, int R) {
    int n = blockIdx.x;
    if (n >= B) return;
    __shared__ float qs[128];
    int tid = threadIdx.x;
    if (tid < 128) qs[tid] = q[(size_t)n * 128 + tid];
    __syncthreads();
    for (int col = tid; col <= R; col += blockDim.x) {
        float acc = 0.f;
        if (col == 0) {
#pragma unroll 4
            for (int c = 0; c < 128; c++) acc += qs[c] * kv[(size_t)n * 128 + c];
        } else {
            int kk = col - 1;
#pragma unroll 4
            for (int c = 0; c < 128; c++) acc += qs[c] * queue[(size_t)c * R + kk];
        }
        out[(size_t)n * (R + 1) + col] = acc / 0.2f;
    }
}

// ------------------------------- launch ------------------------------------
extern "C" void kernel_launch(void* const* d_in, const int* in_sizes, int n_in,
                              void* d_out, int out_size) {
    int base = n_in - 17;

    const float* im_q = (const float*)d_in[0];
    const float* im_k = (const float*)d_in[1];
    const int*   ei   = (const int*)d_in[2];

    const float* Wq1  = (const float*)d_in[base + 0];
    const float* asq1 = (const float*)d_in[base + 1];
    const float* adq1 = (const float*)d_in[base + 2];
    const float* bq1  = (const float*)d_in[base + 3];
    const float* Wq2  = (const float*)d_in[base + 4];
    const float* asq2 = (const float*)d_in[base + 5];
    const float* adq2 = (const float*)d_in[base + 6];
    const float* bq2  = (const float*)d_in[base + 7];
    const float* Wk1  = (const float*)d_in[base + 8];
    const float* ask1 = (const float*)d_in[base + 9];
    const float* adk1 = (const float*)d_in[base + 10];
    const float* bk1  = (const float*)d_in[base + 11];
    const float* Wk2  = (const float*)d_in[base + 12];
    const float* ask2 = (const float*)d_in[base + 13];
    const float* adk2 = (const float*)d_in[base + 14];
    const float* bk2  = (const float*)d_in[base + 15];
    const float* queue= (const float*)d_in[base + 16];

    int G = in_sizes[base] / F512;
    int N = in_sizes[0] / G;
    int E = in_sizes[2] / 2;
    int R = in_sizes[base + 16] / C128;
    int B = (out_size % (R + 2) == 0) ? out_size / (R + 2) : out_size / (R + 1);
    if (B > N) B = N;
    int ET = E + N;
    int Mp = (N + 127) & ~127;
    int Kp1 = (G + 63) & ~63;

    float *Hbuf, *asrc, *adst, *seedq, *seedk;
    float *ask1m, *adk1m, *bk1m, *ask2m, *adk2m, *bk2m;
    int *deg, *off, *cur, *csrc;
    bf16 *A1h, *A1l, *A2h, *A2l, *W1h, *W1l, *W2h, *W2l;
    cudaGetSymbolAddress((void**)&Hbuf, g_H);
    cudaGetSymbolAddress((void**)&asrc, g_asrc);
    cudaGetSymbolAddress((void**)&adst, g_adst);
    cudaGetSymbolAddress((void**)&seedq, g_seedq);
    cudaGetSymbolAddress((void**)&seedk, g_seedk);
    cudaGetSymbolAddress((void**)&ask1m, g_ask1m);
    cudaGetSymbolAddress((void**)&adk1m, g_adk1m);
    cudaGetSymbolAddress((void**)&bk1m, g_bk1m);
    cudaGetSymbolAddress((void**)&ask2m, g_ask2m);
    cudaGetSymbolAddress((void**)&adk2m, g_adk2m);
    cudaGetSymbolAddress((void**)&bk2m, g_bk2m);
    cudaGetSymbolAddress((void**)&deg, g_deg);
    cudaGetSymbolAddress((void**)&off, g_off);
    cudaGetSymbolAddress((void**)&cur, g_cur);
    cudaGetSymbolAddress((void**)&csrc, g_csrc);
    cudaGetSymbolAddress((void**)&A1h, g_A1h);
    cudaGetSymbolAddress((void**)&A1l, g_A1l);
    cudaGetSymbolAddress((void**)&A2h, g_A2h);
    cudaGetSymbolAddress((void**)&A2l, g_A2l);
    cudaGetSymbolAddress((void**)&W1h, g_W1h);
    cudaGetSymbolAddress((void**)&W1l, g_W1l);
    cudaGetSymbolAddress((void**)&W2h, g_W2h);
    cudaGetSymbolAddress((void**)&W2l, g_W2l);

    cudaFuncSetAttribute(gemm_wmma_split_kernel,
                         cudaFuncAttributeMaxDynamicSharedMemorySize, SMEM_GEMM_BYTES);

    const size_t a1slot = (size_t)Mp * Kp1;         // bf16 elems per encoder
    const size_t a2slot = (size_t)NMAX * F512;
    const size_t hslot  = (size_t)NMAX * F512;      // fp32 elems per encoder
    const size_t w1slot = (size_t)Kp1 * F512;
    const size_t w2slot = (size_t)F512 * F512;
    float* aggr2 = (float*)A1h;                     // reuse (40MB >= needed)
    const size_t aggr2slot = (size_t)NMAX * F512;

    long totA1 = (long)Mp * Kp1;

    // ---- prep launches ----
    split_pad2_kernel<<<dim3((unsigned)((totA1 + 255) / 256), 2), 256>>>(
        im_q, im_k, N, G, Kp1, totA1, A1h, A1l);
    split_padW_kernel<<<(int)((w1slot + 255) / 256), 256>>>(Wq1, G, F512, Kp1, W1h, W1l);
    blend_splitW_kernel<<<(int)((w1slot + 255) / 256), 256>>>(Wk1, Wq1, G, F512, Kp1,
                                                              W1h + w1slot, W1l + w1slot);
    split_padW_kernel<<<(int)((w2slot + 255) / 256), 256>>>(Wq2, F512, F512, F512, W2h, W2l);
    blend_splitW_kernel<<<(int)((w2slot + 255) / 256), 256>>>(Wk2, Wq2, F512, F512, F512,
                                                              W2h + w2slot, W2l + w2slot);

    // ---- batched layer-1 GEMM ----
    {
        dim3 grid(F512 / BN, Mp / BM, 2);
        gemm_wmma_split_kernel<<<grid, 256, SMEM_GEMM_BYTES>>>(
            Kp1, F512, A1h, A1l, W1h, W1l, Hbuf, a1slot, w1slot, hslot);
    }

    // ---- remaining prep ----
    blend_kernel<<<2, 256>>>(ask1, asq1, ask1m, F512);
    blend_kernel<<<2, 256>>>(adk1, adq1, adk1m, F512);
    blend_kernel<<<2, 256>>>(bk1, bq1, bk1m, F512);
    blend_kernel<<<2, 256>>>(ask2, asq2, ask2m, F512);
    blend_kernel<<<2, 256>>>(adk2, adq2, adk2m, F512);
    blend_kernel<<<1, 128>>>(bk2, bq2, bk2m, C128);

    cudaMemsetAsync(deg, 0, (size_t)N * sizeof(int));
    cudaMemsetAsync(cur, 0, (size_t)N * sizeof(int));
    csr_count_kernel<<<(ET + 255) / 256, 256>>>(ei, E, N, deg);
    csr_scan_kernel<<<1, 1024>>>(deg, off, N);
    csr_fill_kernel<<<(ET + 255) / 256, 256>>>(ei, E, N, off, cur, csrc);

    // zero pad rows of layer-2 A (rows N..Mp-1), both hi/lo, both encoders
    if (Mp > N) {
        size_t padElems = (size_t)(Mp - N) * F512;
        cudaMemsetAsync(A2h + (size_t)N * F512, 0, padElems * sizeof(bf16));
        cudaMemsetAsync(A2l + (size_t)N * F512, 0, padElems * sizeof(bf16));
        cudaMemsetAsync(A2h + a2slot + (size_t)N * F512, 0, padElems * sizeof(bf16));
        cudaMemsetAsync(A2l + a2slot + (size_t)N * F512, 0, padElems * sizeof(bf16));
    }

    // ---- layer-1 attention (batched): writes bf16 A2 hi/lo with bias+relu ----
    att_scores_kernel<<<dim3(N, 2), dim3(32, 4)>>>(Hbuf, hslot, asq1, adq1, ask1m, adk1m,
                                                   asrc, adst, N);
    gat_attn_kernel<<<dim3(N, 2), 256>>>(Hbuf, hslot, (const float4*)asrc,
                                         (const float4*)adst, off, deg, csrc,
                                         bq1, bk1m, A2h, A2l, nullptr, 0);

    // ---- layer-2 GEMM (batched) ----
    {
        dim3 grid(F512 / BN, Mp / BM, 2);
        gemm_wmma_split_kernel<<<grid, 256, SMEM_GEMM_BYTES>>>(
            F512, F512, A2h, A2l, W2h, W2l, Hbuf, a2slot, w2slot, hslot);
    }

    // ---- layer-2 attention (batched, only dst < B), fp32 out ----
    att_scores_kernel<<<dim3(N, 2), dim3(32, 4)>>>(Hbuf, hslot, asq2, adq2, ask2m, adk2m,
                                                   asrc, adst, N);
    gat_attn_kernel<<<dim3(B, 2), 256>>>(Hbuf, hslot, (const float4*)asrc,
                                         (const float4*)adst, off, deg, csrc,
                                         nullptr, nullptr, nullptr, nullptr,
                                         aggr2, aggr2slot);

    head_mean_norm_kernel<<<dim3(B, 2), 128>>>(aggr2, aggr2slot, bq2, bk2m,
                                               seedq, seedk, B);

    // ---- logits + zero tail ----
    logits_kernel<<<B, 256>>>(seedq, seedk, queue, (float*)d_out, B, R);
    size_t written = (size_t)B * (R + 1);
    if ((size_t)out_size > written)
        cudaMemsetAsync((float*)d_out + written, 0,
                        ((size_t)out_size - written) * sizeof(float));
}

// round 7
// speedup vs baseline: 3.5949x; 1.0884x over previous
#include <cuda_runtime.h>
#include <cuda_bf16.h>
#include <mma.h>
#include <cstdint>

using namespace nvcuda;

// ---------------------------------------------------------------------------
// MoCoGraph: two 2-layer GAT encoders + MoCo logits.
// GEMMs: bf16 3-term split, pre-split operands, BK=64 cp.async double-buffer,
//        batched over both encoders (grid.z=2).
// Attention: CSR gather, fused softmax+aggregate+bias/relu+bf16-split epilogue.
// Logits: smem-tiled fp32 GEMM (queue stays tiled in smem, not re-streamed).
// ---------------------------------------------------------------------------

#define NMAX   10240
#define ETMAX  180224
#define F512   512
#define C128   128
#define CAP    512
#define KPAD1  1024

typedef __nv_bfloat16 bf16;

// ------------------------- device scratch (no mallocs) ---------------------
__device__ float g_H   [2 * (size_t)NMAX * F512];
__device__ bf16  g_A1h [2 * (size_t)NMAX * KPAD1];
__device__ bf16  g_A1l [2 * (size_t)NMAX * KPAD1];
__device__ bf16  g_A2h [2 * (size_t)NMAX * F512];   // pad rows stay 0 (zero-init)
__device__ bf16  g_A2l [2 * (size_t)NMAX * F512];
__device__ bf16  g_W1h [2 * KPAD1 * F512], g_W1l[2 * KPAD1 * F512];
__device__ bf16  g_W2h [2 * F512 * F512],  g_W2l[2 * F512 * F512];
__device__ float g_asrc[2 * NMAX * 4];
__device__ float g_adst[2 * NMAX * 4];
__device__ float g_seedq[(size_t)NMAX * C128];
__device__ float g_seedk[(size_t)NMAX * C128];
__device__ float g_ask1m[F512], g_adk1m[F512], g_bk1m[F512];
__device__ float g_ask2m[F512], g_adk2m[F512], g_bk2m[C128];
__device__ int g_deg[NMAX];
__device__ int g_off[NMAX + 1];
__device__ int g_cur[NMAX];
__device__ int g_csrc[ETMAX];

// ------------------------------ helpers ------------------------------------
__device__ __forceinline__ uint32_t smem_u32(const void* p) {
    uint32_t a;
    asm("{ .reg .u64 t; cvta.to.shared.u64 t, %1; cvt.u32.u64 %0, t; }" : "=r"(a) : "l"(p));
    return a;
}
__device__ __forceinline__ void cp_async16(uint32_t s, const void* g) {
    asm volatile("cp.async.cg.shared.global [%0], [%1], 16;" :: "r"(s), "l"(g));
}
#define CP_COMMIT() asm volatile("cp.async.commit_group;" ::: "memory")
#define CP_WAIT(n)  asm volatile("cp.async.wait_group %0;" :: "n"(n) : "memory")

__device__ __forceinline__ void split2(float v, bf16& h, bf16& l) {
    h = __float2bfloat16(v);
    l = __float2bfloat16(v - __bfloat162float(h));
}

// ------------------------------ prep kernels -------------------------------
// batched input split: z=0 -> in0, z=1 -> in1; out slot stride = total
__global__ void split_pad2_kernel(const float* __restrict__ in0,
                                  const float* __restrict__ in1,
                                  int M, int K, int Kp, long total,
                                  bf16* __restrict__ hi, bf16* __restrict__ lo) {
    long idx = (long)blockIdx.x * blockDim.x + threadIdx.x;
    if (idx >= total) return;
    const float* in = blockIdx.y ? in1 : in0;
    size_t o = (size_t)blockIdx.y * total + idx;
    int r = (int)(idx / Kp), c = (int)(idx % Kp);
    float v = (r < M && c < K) ? in[(size_t)r * K + c] : 0.f;
    bf16 h, l; split2(v, h, l);
    hi[o] = h; lo[o] = l;
}

// all 4 weight splits (q/k x layer1/layer2) in one launch
__global__ void wsplit_all_kernel(const float* __restrict__ Wq1,
                                  const float* __restrict__ Wk1,
                                  const float* __restrict__ Wq2,
                                  const float* __restrict__ Wk2,
                                  int G, int Kp1,
                                  bf16* __restrict__ W1h, bf16* __restrict__ W1l,
                                  bf16* __restrict__ W2h, bf16* __restrict__ W2l) {
    long idx = (long)blockIdx.x * blockDim.x + threadIdx.x;
    const long s1 = (long)Kp1 * F512;
    const long s2 = (long)F512 * F512;
    if (idx < 2 * s1) {
        int z = idx >= s1;
        long j = idx - (long)z * s1;
        int r = (int)(j / F512);
        float v = 0.f;
        if (r < G) v = z ? (0.99f * Wk1[j] + 0.01f * Wq1[j]) : Wq1[j];
        bf16 h, l; split2(v, h, l);
        W1h[idx] = h; W1l[idx] = l;
    } else if (idx < 2 * s1 + 2 * s2) {
        long j2 = idx - 2 * s1;
        int z = j2 >= s2;
        long j = j2 - (long)z * s2;
        float v = z ? (0.99f * Wk2[j] + 0.01f * Wq2[j]) : Wq2[j];
        bf16 h, l; split2(v, h, l);
        W2h[j2] = h; W2l[j2] = l;
    }
}

// zero deg/cur + 6 small vector blends, one launch
__global__ void misc_prep_kernel(int N,
                                 int* __restrict__ deg, int* __restrict__ cur,
                                 const float* ask1, const float* asq1,
                                 const float* adk1, const float* adq1,
                                 const float* bk1,  const float* bq1,
                                 const float* ask2, const float* asq2,
                                 const float* adk2, const float* adq2,
                                 const float* bk2,  const float* bq2,
                                 float* o1, float* o2, float* o3,
                                 float* o4, float* o5, float* o6) {
    int idx = blockIdx.x * blockDim.x + threadIdx.x;
    if (idx < N) { deg[idx] = 0; return; }
    if (idx < 2 * N) { cur[idx - N] = 0; return; }
    int j = idx - 2 * N;
    if (j < 512)       o1[j]        = 0.99f * ask1[j]        + 0.01f * asq1[j];
    else if (j < 1024) o2[j - 512]  = 0.99f * adk1[j - 512]  + 0.01f * adq1[j - 512];
    else if (j < 1536) o3[j - 1024] = 0.99f * bk1[j - 1024]  + 0.01f * bq1[j - 1024];
    else if (j < 2048) o4[j - 1536] = 0.99f * ask2[j - 1536] + 0.01f * asq2[j - 1536];
    else if (j < 2560) o5[j - 2048] = 0.99f * adk2[j - 2048] + 0.01f * adq2[j - 2048];
    else if (j < 2688) o6[j - 2560] = 0.99f * bk2[j - 2560]  + 0.01f * bq2[j - 2560];
}

// ------------------------------- CSR build ---------------------------------
__global__ void csr_count_kernel(const int* __restrict__ ei, int E, int N,
                                 int* __restrict__ deg) {
    int i = blockIdx.x * blockDim.x + threadIdx.x;
    int ET = E + N;
    if (i >= ET) return;
    int d = (i < E) ? ei[E + i] : (i - E);
    atomicAdd(&deg[d], 1);
}

__global__ void csr_scan_kernel(const int* __restrict__ deg,
                                int* __restrict__ off, int N) {
    __shared__ int sh[1024];
    __shared__ int carry;
    int t = threadIdx.x;
    if (t == 0) carry = 0;
    __syncthreads();
    for (int base = 0; base < N; base += 1024) {
        int v = (base + t < N) ? deg[base + t] : 0;
        sh[t] = v;
        __syncthreads();
        for (int o = 1; o < 1024; o <<= 1) {
            int x = (t >= o) ? sh[t - o] : 0;
            __syncthreads();
            sh[t] += x;
            __syncthreads();
        }
        int excl = sh[t] - v + carry;
        if (base + t < N) off[base + t] = excl;
        __syncthreads();
        if (t == 1023) carry += sh[1023];
        __syncthreads();
    }
    if (t == 0) off[N] = carry;
}

__global__ void csr_fill_kernel(const int* __restrict__ ei, int E, int N,
                                const int* __restrict__ off,
                                int* __restrict__ cur,
                                int* __restrict__ csrc) {
    int i = blockIdx.x * blockDim.x + threadIdx.x;
    int ET = E + N;
    if (i >= ET) return;
    int s, d;
    if (i < E) { s = ei[i]; d = ei[E + i]; } else { s = d = i - E; }
    int pos = atomicAdd(&cur[d], 1);
    csrc[off[d] + pos] = s;
}

// --------------- batched wmma GEMM, pre-split bf16, BK=64 ------------------
#define BM 128
#define BN 128
#define BK 64
#define A_LD 72
#define B_LD 136
#define A_TILE_B 18432u
#define B_TILE_B 17408u
#define ST_AH 0u
#define ST_AL A_TILE_B
#define ST_BH (2u * A_TILE_B)
#define ST_BL (2u * A_TILE_B + B_TILE_B)
#define STAGE_B (2u * A_TILE_B + 2u * B_TILE_B)
#define SMEM_GEMM_BYTES (2 * STAGE_B)

__global__ void __launch_bounds__(256, 1)
gemm_wmma_split_kernel(int K, int Nn,
                       const bf16* __restrict__ Ahg0, const bf16* __restrict__ Alg0,
                       const bf16* __restrict__ Bhg0, const bf16* __restrict__ Blg0,
                       float* __restrict__ C0,
                       size_t strideA, size_t strideB, size_t strideC) {
    extern __shared__ char smem[];
    const uint32_t sb = smem_u32(smem);
    const int tid = threadIdx.x;
    const int bn = blockIdx.x, bm = blockIdx.y;
    const size_t z = blockIdx.z;
    const bf16* Ahg = Ahg0 + z * strideA;
    const bf16* Alg = Alg0 + z * strideA;
    const bf16* Bhg = Bhg0 + z * strideB;
    const bf16* Blg = Blg0 + z * strideB;
    float* C = C0 + z * strideC;

    const int warpId = tid >> 5;
    const int wm = warpId & 3;
    const int wn = warpId >> 2;
    const int nk = K >> 6;

    const size_t aBase = (size_t)(bm * BM);
    const int cCol = bn * BN;

    auto load_stage = [&](int kt, uint32_t stg) {
#pragma unroll
        for (int i = 0; i < 4; i++) {
            int idx = tid + (i << 8);
            int ar = idx >> 3, as = (idx & 7) << 3;
            const size_t ago = (aBase + ar) * K + kt * BK + as;
            uint32_t aso = (uint32_t)(ar * A_LD + as) * 2;
            cp_async16(sb + stg + ST_AH + aso, Ahg + ago);
            cp_async16(sb + stg + ST_AL + aso, Alg + ago);
            int br = idx >> 4, bs = (idx & 15) << 3;
            const size_t bgo = (size_t)(kt * BK + br) * Nn + cCol + bs;
            uint32_t bso = (uint32_t)(br * B_LD + bs) * 2;
            cp_async16(sb + stg + ST_BH + bso, Bhg + bgo);
            cp_async16(sb + stg + ST_BL + bso, Blg + bgo);
        }
        CP_COMMIT();
    };

    wmma::fragment<wmma::accumulator, 16, 16, 16, float> acc[2][4];
#pragma unroll
    for (int i = 0; i < 2; i++)
#pragma unroll
        for (int j = 0; j < 4; j++) wmma::fill_fragment(acc[i][j], 0.0f);

    load_stage(0, 0);

    for (int kt = 0; kt < nk; kt++) {
        const uint32_t stg = (kt & 1) ? STAGE_B : 0u;
        if (kt + 1 < nk) {
            load_stage(kt + 1, (kt & 1) ? 0u : STAGE_B);
            CP_WAIT(1);
        } else {
            CP_WAIT(0);
        }
        __syncthreads();

        const bf16* sAh = (const bf16*)(smem + stg + ST_AH);
        const bf16* sAl = (const bf16*)(smem + stg + ST_AL);
        const bf16* sBh = (const bf16*)(smem + stg + ST_BH);
        const bf16* sBl = (const bf16*)(smem + stg + ST_BL);

#pragma unroll
        for (int kk = 0; kk < BK; kk += 16) {
            wmma::fragment<wmma::matrix_a, 16, 16, 16, bf16, wmma::row_major> ah[2], al[2];
            wmma::fragment<wmma::matrix_b, 16, 16, 16, bf16, wmma::row_major> bh[4], bl[4];
#pragma unroll
            for (int i = 0; i < 2; i++) {
                wmma::load_matrix_sync(ah[i], sAh + (wm * 32 + i * 16) * A_LD + kk, A_LD);
                wmma::load_matrix_sync(al[i], sAl + (wm * 32 + i * 16) * A_LD + kk, A_LD);
            }
#pragma unroll
            for (int j = 0; j < 4; j++) {
                wmma::load_matrix_sync(bh[j], sBh + kk * B_LD + wn * 64 + j * 16, B_LD);
                wmma::load_matrix_sync(bl[j], sBl + kk * B_LD + wn * 64 + j * 16, B_LD);
            }
#pragma unroll
            for (int i = 0; i < 2; i++)
#pragma unroll
                for (int j = 0; j < 4; j++) {
                    wmma::mma_sync(acc[i][j], ah[i], bh[j], acc[i][j]);
                    wmma::mma_sync(acc[i][j], ah[i], bl[j], acc[i][j]);
                    wmma::mma_sync(acc[i][j], al[i], bh[j], acc[i][j]);
                }
        }
        __syncthreads();
    }

#pragma unroll
    for (int i = 0; i < 2; i++) {
        int row = bm * BM + wm * 32 + i * 16;
#pragma unroll
        for (int j = 0; j < 4; j++) {
            int col = cCol + wn * 64 + j * 16;
            wmma::store_matrix_sync(&C[(size_t)row * Nn + col], acc[i][j],
                                    Nn, wmma::mem_row_major);
        }
    }
}

// ---------------------------- attention scores (batched) -------------------
__global__ void att_scores_kernel(const float* __restrict__ Hbase, size_t hstride,
                                  const float* __restrict__ s0, const float* __restrict__ d0,
                                  const float* __restrict__ s1, const float* __restrict__ d1,
                                  float* __restrict__ a_s_base,
                                  float* __restrict__ a_d_base, int N) {
    int n = blockIdx.x;
    if (n >= N) return;
    int z = blockIdx.y;
    const float* Hf = Hbase + (size_t)z * hstride;
    const float* att_s = z ? s1 : s0;
    const float* att_d = z ? d1 : d0;
    float* a_s = a_s_base + (size_t)z * NMAX * 4;
    float* a_d = a_d_base + (size_t)z * NMAX * 4;

    int h = threadIdx.y;
    int lane = threadIdx.x;
    const float* row = Hf + (size_t)n * F512 + h * C128;
    float ss = 0.f, sd = 0.f;
#pragma unroll
    for (int j = 0; j < 4; j++) {
        int c = lane + 32 * j;
        float v = row[c];
        ss += v * att_s[h * C128 + c];
        sd += v * att_d[h * C128 + c];
    }
#pragma unroll
    for (int o = 16; o > 0; o >>= 1) {
        ss += __shfl_down_sync(0xffffffffu, ss, o);
        sd += __shfl_down_sync(0xffffffffu, sd, o);
    }
    if (lane == 0) { a_s[n * 4 + h] = ss; a_d[n * 4 + h] = sd; }
}

// ---------------- fused per-dst softmax + aggregation (batched) ------------
__device__ __forceinline__ float leaky(float e) { return e > 0.f ? e : 0.2f * e; }

__global__ __launch_bounds__(256)
void gat_attn_kernel(const float* __restrict__ Hbase, size_t hstride,
                     const float4* __restrict__ a_s_base,
                     const float4* __restrict__ a_d_base,
                     const int* __restrict__ off,
                     const int* __restrict__ deg_arr,
                     const int* __restrict__ csrc,
                     const float* __restrict__ bias0,
                     const float* __restrict__ bias1,
                     bf16* __restrict__ outh, bf16* __restrict__ outl,
                     float* __restrict__ outf, size_t ostride) {
    int d = blockIdx.x;
    int z = blockIdx.y;
    int t = threadIdx.x;
    int lane = t & 31, wid = t >> 5;

    const float* Hf = Hbase + (size_t)z * hstride;
    const float4* a_s4 = a_s_base + (size_t)z * NMAX;
    const float4* a_d4 = a_d_base + (size_t)z * NMAX;
    const float* bias = z ? bias1 : bias0;

    __shared__ int   s_list[CAP];
    __shared__ float w[CAP][4];
    __shared__ float red[8][4];
    __shared__ float mx_s[4], invd_s[4];

    const int start = off[d];
    const int deg = deg_arr[d];
    const float4 ad = a_d4[d];

    float m0 = -1e30f, m1 = -1e30f, m2 = -1e30f, m3 = -1e30f;
    for (int j = t; j < deg; j += 256) {
        int s = csrc[start + j];
        float4 as = a_s4[s];
        float e0 = leaky(as.x + ad.x);
        float e1 = leaky(as.y + ad.y);
        float e2 = leaky(as.z + ad.z);
        float e3 = leaky(as.w + ad.w);
        if (j < CAP) {
            s_list[j] = s;
            w[j][0] = e0; w[j][1] = e1; w[j][2] = e2; w[j][3] = e3;
        }
        m0 = fmaxf(m0, e0); m1 = fmaxf(m1, e1);
        m2 = fmaxf(m2, e2); m3 = fmaxf(m3, e3);
    }
#pragma unroll
    for (int o = 16; o > 0; o >>= 1) {
        m0 = fmaxf(m0, __shfl_xor_sync(0xffffffffu, m0, o));
        m1 = fmaxf(m1, __shfl_xor_sync(0xffffffffu, m1, o));
        m2 = fmaxf(m2, __shfl_xor_sync(0xffffffffu, m2, o));
        m3 = fmaxf(m3, __shfl_xor_sync(0xffffffffu, m3, o));
    }
    if (lane == 0) { red[wid][0] = m0; red[wid][1] = m1; red[wid][2] = m2; red[wid][3] = m3; }
    __syncthreads();
    if (t < 4) {
        float mm = -1e30f;
#pragma unroll
        for (int k = 0; k < 8; k++) mm = fmaxf(mm, red[k][t]);
        mx_s[t] = mm;
    }
    __syncthreads();
    const float mx0 = mx_s[0], mx1 = mx_s[1], mx2 = mx_s[2], mx3 = mx_s[3];

    float s0 = 0.f, s1 = 0.f, s2 = 0.f, s3 = 0.f;
    for (int j = t; j < deg; j += 256) {
        float e0, e1, e2, e3;
        if (j < CAP) {
            e0 = w[j][0]; e1 = w[j][1]; e2 = w[j][2]; e3 = w[j][3];
        } else {
            int s = csrc[start + j];
            float4 as = a_s4[s];
            e0 = leaky(as.x + ad.x); e1 = leaky(as.y + ad.y);
            e2 = leaky(as.z + ad.z); e3 = leaky(as.w + ad.w);
        }
        float x0 = expf(e0 - mx0), x1 = expf(e1 - mx1);
        float x2 = expf(e2 - mx2), x3 = expf(e3 - mx3);
        if (j < CAP) { w[j][0] = x0; w[j][1] = x1; w[j][2] = x2; w[j][3] = x3; }
        s0 += x0; s1 += x1; s2 += x2; s3 += x3;
    }
#pragma unroll
    for (int o = 16; o > 0; o >>= 1) {
        s0 += __shfl_xor_sync(0xffffffffu, s0, o);
        s1 += __shfl_xor_sync(0xffffffffu, s1, o);
        s2 += __shfl_xor_sync(0xffffffffu, s2, o);
        s3 += __shfl_xor_sync(0xffffffffu, s3, o);
    }
    __syncthreads();
    if (lane == 0) { red[wid][0] = s0; red[wid][1] = s1; red[wid][2] = s2; red[wid][3] = s3; }
    __syncthreads();
    if (t < 4) {
        float ssum = 0.f;
#pragma unroll
        for (int k = 0; k < 8; k++) ssum += red[k][t];
        invd_s[t] = 1.0f / (ssum + 1e-16f);
    }
    __syncthreads();

    const int c2 = t * 2;
    const int h = c2 >> 7;
    const float inv = invd_s[h];
    const float mxh = mx_s[h];
    float acc0 = 0.f, acc1 = 0.f;
    for (int j = 0; j < deg; j++) {
        int s;
        float ww;
        if (j < CAP) {
            s = s_list[j];
            ww = w[j][h];
        } else {
            s = csrc[start + j];
            const float* asp = (const float*)&a_s4[s];
            const float* adp = (const float*)&ad;
            ww = expf(leaky(asp[h] + adp[h]) - mxh);
        }
        float alpha = ww * inv;
        float2 v = *(const float2*)(Hf + (size_t)s * F512 + c2);
        acc0 += v.x * alpha;
        acc1 += v.y * alpha;
    }
    if (outh) {
        acc0 = fmaxf(acc0 + bias[c2], 0.f);
        acc1 = fmaxf(acc1 + bias[c2 + 1], 0.f);
        bf16 h0, l0, h1, l1;
        split2(acc0, h0, l0);
        split2(acc1, h1, l1);
        size_t o = (size_t)z * NMAX * F512 + (size_t)d * F512 + c2;
        *(uint32_t*)(outh + o) = (uint32_t)__bfloat16_as_ushort(h0) |
                                 ((uint32_t)__bfloat16_as_ushort(h1) << 16);
        *(uint32_t*)(outl + o) = (uint32_t)__bfloat16_as_ushort(l0) |
                                 ((uint32_t)__bfloat16_as_ushort(l1) << 16);
    } else {
        size_t o = (size_t)z * ostride + (size_t)d * F512 + c2;
        *(float2*)(outf + o) = make_float2(acc0, acc1);
    }
}

// layer-2 epilogue (batched)
__global__ void head_mean_norm_kernel(const float* __restrict__ aggr_base, size_t astride,
                                      const float* __restrict__ bias0,
                                      const float* __restrict__ bias1,
                                      float* __restrict__ outq,
                                      float* __restrict__ outk, int B) {
    int n = blockIdx.x;
    if (n >= B) return;
    int z = blockIdx.y;
    const float* aggr = aggr_base + (size_t)z * astride;
    const float* bias = z ? bias1 : bias0;
    float* outv = z ? outk : outq;
    int c = threadIdx.x;
    size_t base = (size_t)n * F512;
    float v = 0.25f * (aggr[base + c] + aggr[base + 128 + c] +
                       aggr[base + 256 + c] + aggr[base + 384 + c]) + bias[c];
    float s = v * v;
#pragma unroll
    for (int o = 16; o > 0; o >>= 1) s += __shfl_down_sync(0xffffffffu, s, o);
    __shared__ float red[4];
    if ((c & 31) == 0) red[c >> 5] = s;
    __syncthreads();
    float tot = red[0] + red[1] + red[2] + red[3];
    outv[(size_t)n * C128 + c] = v * rsqrtf(tot + 1e-24f);
}

// ---------------- logits: tiled fp32 GEMM out[B,1+R] ------------------------
// out[n,0] = q.k/T ; out[n,1+kk] = q . queue[:,kk] / T ; tail zeros folded in.
#define LT 64
__global__ __launch_bounds__(256)
void logits_gemm_kernel(const float* __restrict__ q,
                        const float* __restrict__ kv,
                        const float* __restrict__ queue,
                        float* __restrict__ out, int B, int R,
                        long tail_off, long tail_len) {
    __shared__ float qt[LT][33];     // [row][k-chunk 32]
    __shared__ float kt[32][LT + 4]; // [k][col]
    const int tid = threadIdx.x;
    const int bx = blockIdx.x, by = blockIdx.y;
    const int tx = tid & 15, ty = tid >> 4;  // 16x16 threads, 4x4 each

    float acc[4][4];
#pragma unroll
    for (int i = 0; i < 4; i++)
#pragma unroll
        for (int j = 0; j < 4; j++) acc[i][j] = 0.f;

    for (int k0 = 0; k0 < 128; k0 += 32) {
        // load q tile: 64x32 = 2048 floats, 8 per thread
#pragma unroll
        for (int i = 0; i < 8; i++) {
            int e = tid + i * 256;          // 0..2047
            int r = e >> 5, c = e & 31;
            int gr = by * LT + r;
            qt[r][c] = (gr < B) ? q[(size_t)gr * 128 + k0 + c] : 0.f;
        }
        // load queue tile: 32x64
#pragma unroll
        for (int i = 0; i < 8; i++) {
            int e = tid + i * 256;
            int r = e >> 6, c = e & 63;
            int gc = bx * LT + c;
            kt[r][c] = (gc < R) ? queue[(size_t)(k0 + r) * R + gc] : 0.f;
        }
        __syncthreads();
#pragma unroll
        for (int k = 0; k < 32; k++) {
            float ra[4], rb[4];
#pragma unroll
            for (int i = 0; i < 4; i++) ra[i] = qt[ty * 4 + i][k];
#pragma unroll
            for (int j = 0; j < 4; j++) rb[j] = kt[k][tx * 4 + j];
#pragma unroll
            for (int i = 0; i < 4; i++)
#pragma unroll
                for (int j = 0; j < 4; j++) acc[i][j] += ra[i] * rb[j];
        }
        __syncthreads();
    }

#pragma unroll
    for (int i = 0; i < 4; i++) {
        int row = by * LT + ty * 4 + i;
        if (row >= B) continue;
#pragma unroll
        for (int j = 0; j < 4; j++) {
            int col = bx * LT + tx * 4 + j;
            if (col < R)
                out[(size_t)row * (R + 1) + 1 + col] = acc[i][j] * 5.0f;
        }
    }

    // l_pos column (blocks with bx==0)
    if (bx == 0 && tid < LT) {
        int n = by * LT + tid;
        if (n < B) {
            const float* qr = q + (size_t)n * 128;
            const float* kr = kv + (size_t)n * 128;
            float s = 0.f;
#pragma unroll 4
            for (int c = 0; c < 128; c++) s += qr[c] * kr[c];
            out[(size_t)n * (R + 1)] = s * 5.0f;
        }
    }
    // tail zeros (one block)
    if (bx == 0 && by == 0) {
        for (long i = tid; i < tail_len; i += 256) out[tail_off + i] = 0.f;
    }
}

// ------------------------------- launch ------------------------------------
extern "C" void kernel_launch(void* const* d_in, const int* in_sizes, int n_in,
                              void* d_out, int out_size) {
    int base = n_in - 17;

    const float* im_q = (const float*)d_in[0];
    const float* im_k = (const float*)d_in[1];
    const int*   ei   = (const int*)d_in[2];

    const float* Wq1  = (const float*)d_in[base + 0];
    const float* asq1 = (const float*)d_in[base + 1];
    const float* adq1 = (const float*)d_in[base + 2];
    const float* bq1  = (const float*)d_in[base + 3];
    const float* Wq2  = (const float*)d_in[base + 4];
    const float* asq2 = (const float*)d_in[base + 5];
    const float* adq2 = (const float*)d_in[base + 6];
    const float* bq2  = (const float*)d_in[base + 7];
    const float* Wk1  = (const float*)d_in[base + 8];
    const float* ask1 = (const float*)d_in[base + 9];
    const float* adk1 = (const float*)d_in[base + 10];
    const float* bk1  = (const float*)d_in[base + 11];
    const float* Wk2  = (const float*)d_in[base + 12];
    const float* ask2 = (const float*)d_in[base + 13];
    const float* adk2 = (const float*)d_in[base + 14];
    const float* bk2  = (const float*)d_in[base + 15];
    const float* queue= (const float*)d_in[base + 16];

    int G = in_sizes[base] / F512;
    int N = in_sizes[0] / G;
    int E = in_sizes[2] / 2;
    int R = in_sizes[base + 16] / C128;
    int B = (out_size % (R + 2) == 0) ? out_size / (R + 2) : out_size / (R + 1);
    if (B > N) B = N;
    int ET = E + N;
    int Mp = (N + 127) & ~127;
    int Kp1 = (G + 63) & ~63;

    float *Hbuf, *asrc, *adst, *seedq, *seedk;
    float *ask1m, *adk1m, *bk1m, *ask2m, *adk2m, *bk2m;
    int *deg, *off, *cur, *csrc;
    bf16 *A1h, *A1l, *A2h, *A2l, *W1h, *W1l, *W2h, *W2l;
    cudaGetSymbolAddress((void**)&Hbuf, g_H);
    cudaGetSymbolAddress((void**)&asrc, g_asrc);
    cudaGetSymbolAddress((void**)&adst, g_adst);
    cudaGetSymbolAddress((void**)&seedq, g_seedq);
    cudaGetSymbolAddress((void**)&seedk, g_seedk);
    cudaGetSymbolAddress((void**)&ask1m, g_ask1m);
    cudaGetSymbolAddress((void**)&adk1m, g_adk1m);
    cudaGetSymbolAddress((void**)&bk1m, g_bk1m);
    cudaGetSymbolAddress((void**)&ask2m, g_ask2m);
    cudaGetSymbolAddress((void**)&adk2m, g_adk2m);
    cudaGetSymbolAddress((void**)&bk2m, g_bk2m);
    cudaGetSymbolAddress((void**)&deg, g_deg);
    cudaGetSymbolAddress((void**)&off, g_off);
    cudaGetSymbolAddress((void**)&cur, g_cur);
    cudaGetSymbolAddress((void**)&csrc, g_csrc);
    cudaGetSymbolAddress((void**)&A1h, g_A1h);
    cudaGetSymbolAddress((void**)&A1l, g_A1l);
    cudaGetSymbolAddress((void**)&A2h, g_A2h);
    cudaGetSymbolAddress((void**)&A2l, g_A2l);
    cudaGetSymbolAddress((void**)&W1h, g_W1h);
    cudaGetSymbolAddress((void**)&W1l, g_W1l);
    cudaGetSymbolAddress((void**)&W2h, g_W2h);
    cudaGetSymbolAddress((void**)&W2l, g_W2l);

    cudaFuncSetAttribute(gemm_wmma_split_kernel,
                         cudaFuncAttributeMaxDynamicSharedMemorySize, SMEM_GEMM_BYTES);

    const size_t a1slot = (size_t)Mp * Kp1;
    const size_t a2slot = (size_t)NMAX * F512;
    const size_t hslot  = (size_t)NMAX * F512;
    const size_t w1slot = (size_t)Kp1 * F512;
    const size_t w2slot = (size_t)F512 * F512;
    float* aggr2 = (float*)A1h;                 // reuse layer-1 A buffer
    const size_t aggr2slot = (size_t)NMAX * F512;

    long totA1 = (long)Mp * Kp1;
    long wtot = 2 * (long)w1slot + 2 * (long)w2slot;

    // 1) input split (batched q/k)
    split_pad2_kernel<<<dim3((unsigned)((totA1 + 255) / 256), 2), 256>>>(
        im_q, im_k, N, G, Kp1, totA1, A1h, A1l);
    // 2) all weight splits
    wsplit_all_kernel<<<(int)((wtot + 255) / 256), 256>>>(
        Wq1, Wk1, Wq2, Wk2, G, Kp1, W1h, W1l, W2h, W2l);
    // 3) layer-1 GEMM (batched)
    {
        dim3 grid(F512 / BN, Mp / BM, 2);
        gemm_wmma_split_kernel<<<grid, 256, SMEM_GEMM_BYTES>>>(
            Kp1, F512, A1h, A1l, W1h, W1l, Hbuf, a1slot, w1slot, hslot);
    }
    // 4) misc prep: deg/cur zero + 6 vector blends
    misc_prep_kernel<<<(2 * N + 2688 + 255) / 256, 256>>>(
        N, deg, cur,
        ask1, asq1, adk1, adq1, bk1, bq1,
        ask2, asq2, adk2, adq2, bk2, bq2,
        ask1m, adk1m, bk1m, ask2m, adk2m, bk2m);
    // 5-7) CSR
    csr_count_kernel<<<(ET + 255) / 256, 256>>>(ei, E, N, deg);
    csr_scan_kernel<<<1, 1024>>>(deg, off, N);
    csr_fill_kernel<<<(ET + 255) / 256, 256>>>(ei, E, N, off, cur, csrc);
    // 8-9) layer-1 attention -> bf16 A2 (pad rows stay zero from init)
    att_scores_kernel<<<dim3(N, 2), dim3(32, 4)>>>(Hbuf, hslot, asq1, adq1, ask1m, adk1m,
                                                   asrc, adst, N);
    gat_attn_kernel<<<dim3(N, 2), 256>>>(Hbuf, hslot, (const float4*)asrc,
                                         (const float4*)adst, off, deg, csrc,
                                         bq1, bk1m, A2h, A2l, nullptr, 0);
    // 10) layer-2 GEMM (batched)
    {
        dim3 grid(F512 / BN, Mp / BM, 2);
        gemm_wmma_split_kernel<<<grid, 256, SMEM_GEMM_BYTES>>>(
            F512, F512, A2h, A2l, W2h, W2l, Hbuf, a2slot, w2slot, hslot);
    }
    // 11-12) layer-2 attention (dst < B only)
    att_scores_kernel<<<dim3(N, 2), dim3(32, 4)>>>(Hbuf, hslot, asq2, adq2, ask2m, adk2m,
                                                   asrc, adst, N);
    gat_attn_kernel<<<dim3(B, 2), 256>>>(Hbuf, hslot, (const float4*)asrc,
                                         (const float4*)adst, off, deg, csrc,
                                         nullptr, nullptr, nullptr, nullptr,
                                         aggr2, aggr2slot);
    // 13) head-mean + l2norm
    head_mean_norm_kernel<<<dim3(B, 2), 128>>>(aggr2, aggr2slot, bq2, bk2m,
                                               seedq, seedk, B);
    // 14) logits (tiled GEMM, l_pos + tail zero folded in)
    {
        long written = (long)B * (R + 1);
        long tail = (long)out_size - written;
        if (tail < 0) tail = 0;
        dim3 grid((R + LT - 1) / LT, (B + LT - 1) / LT);
        logits_gemm_kernel<<<grid, 256>>>(seedq, seedk, queue, (float*)d_out,
                                          B, R, written, tail);
    }
}

// round 8
// speedup vs baseline: 3.7091x; 1.0318x over previous
#include <cuda_runtime.h>
#include <cuda_bf16.h>
#include <mma.h>
#include <cstdint>

using namespace nvcuda;

// ---------------------------------------------------------------------------
// MoCoGraph: two 2-layer GAT encoders + MoCo logits.
// GEMMs: bf16 3-term split, pre-split operands, BK=64 cp.async double-buffer,
//        CTA 256x128 with 64x64 warp tiles (mma:load ratio 3:1), batched z=2.
// Attention: CSR gather, fused softmax+aggregate+bias/relu+bf16-split epilogue.
// Logits: smem-tiled fp32 GEMM.
// ---------------------------------------------------------------------------

#define NMAX   10240
#define ETMAX  180224
#define F512   512
#define C128   128
#define CAP    512
#define KPAD1  1024

typedef __nv_bfloat16 bf16;

// ------------------------- device scratch (no mallocs) ---------------------
__device__ float g_H   [2 * (size_t)NMAX * F512];
__device__ bf16  g_A1h [2 * (size_t)NMAX * KPAD1];
__device__ bf16  g_A1l [2 * (size_t)NMAX * KPAD1];
__device__ bf16  g_A2h [2 * (size_t)NMAX * F512];   // pad rows stay 0 (zero-init)
__device__ bf16  g_A2l [2 * (size_t)NMAX * F512];
__device__ bf16  g_W1h [2 * KPAD1 * F512], g_W1l[2 * KPAD1 * F512];
__device__ bf16  g_W2h [2 * F512 * F512],  g_W2l[2 * F512 * F512];
__device__ float g_asrc[2 * NMAX * 4];
__device__ float g_adst[2 * NMAX * 4];
__device__ float g_seedq[(size_t)NMAX * C128];
__device__ float g_seedk[(size_t)NMAX * C128];
__device__ float g_ask1m[F512], g_adk1m[F512], g_bk1m[F512];
__device__ float g_ask2m[F512], g_adk2m[F512], g_bk2m[C128];
__device__ int g_deg[NMAX];
__device__ int g_off[NMAX + 1];
__device__ int g_cur[NMAX];
__device__ int g_csrc[ETMAX];

// ------------------------------ helpers ------------------------------------
__device__ __forceinline__ uint32_t smem_u32(const void* p) {
    uint32_t a;
    asm("{ .reg .u64 t; cvta.to.shared.u64 t, %1; cvt.u32.u64 %0, t; }" : "=r"(a) : "l"(p));
    return a;
}
__device__ __forceinline__ void cp_async16(uint32_t s, const void* g) {
    asm volatile("cp.async.cg.shared.global [%0], [%1], 16;" :: "r"(s), "l"(g));
}
#define CP_COMMIT() asm volatile("cp.async.commit_group;" ::: "memory")
#define CP_WAIT(n)  asm volatile("cp.async.wait_group %0;" :: "n"(n) : "memory")

__device__ __forceinline__ void split2(float v, bf16& h, bf16& l) {
    h = __float2bfloat16(v);
    l = __float2bfloat16(v - __bfloat162float(h));
}

// ------------------------------ prep kernels -------------------------------
__global__ void split_pad2_kernel(const float* __restrict__ in0,
                                  const float* __restrict__ in1,
                                  int M, int K, int Kp, long total,
                                  bf16* __restrict__ hi, bf16* __restrict__ lo) {
    long idx = (long)blockIdx.x * blockDim.x + threadIdx.x;
    if (idx >= total) return;
    const float* in = blockIdx.y ? in1 : in0;
    size_t o = (size_t)blockIdx.y * total + idx;
    int r = (int)(idx / Kp), c = (int)(idx % Kp);
    float v = (r < M && c < K) ? in[(size_t)r * K + c] : 0.f;
    bf16 h, l; split2(v, h, l);
    hi[o] = h; lo[o] = l;
}

__global__ void wsplit_all_kernel(const float* __restrict__ Wq1,
                                  const float* __restrict__ Wk1,
                                  const float* __restrict__ Wq2,
                                  const float* __restrict__ Wk2,
                                  int G, int Kp1,
                                  bf16* __restrict__ W1h, bf16* __restrict__ W1l,
                                  bf16* __restrict__ W2h, bf16* __restrict__ W2l) {
    long idx = (long)blockIdx.x * blockDim.x + threadIdx.x;
    const long s1 = (long)Kp1 * F512;
    const long s2 = (long)F512 * F512;
    if (idx < 2 * s1) {
        int z = idx >= s1;
        long j = idx - (long)z * s1;
        int r = (int)(j / F512);
        float v = 0.f;
        if (r < G) v = z ? (0.99f * Wk1[j] + 0.01f * Wq1[j]) : Wq1[j];
        bf16 h, l; split2(v, h, l);
        W1h[idx] = h; W1l[idx] = l;
    } else if (idx < 2 * s1 + 2 * s2) {
        long j2 = idx - 2 * s1;
        int z = j2 >= s2;
        long j = j2 - (long)z * s2;
        float v = z ? (0.99f * Wk2[j] + 0.01f * Wq2[j]) : Wq2[j];
        bf16 h, l; split2(v, h, l);
        W2h[j2] = h; W2l[j2] = l;
    }
}

__global__ void misc_prep_kernel(int N,
                                 int* __restrict__ deg, int* __restrict__ cur,
                                 const float* ask1, const float* asq1,
                                 const float* adk1, const float* adq1,
                                 const float* bk1,  const float* bq1,
                                 const float* ask2, const float* asq2,
                                 const float* adk2, const float* adq2,
                                 const float* bk2,  const float* bq2,
                                 float* o1, float* o2, float* o3,
                                 float* o4, float* o5, float* o6) {
    int idx = blockIdx.x * blockDim.x + threadIdx.x;
    if (idx < N) { deg[idx] = 0; return; }
    if (idx < 2 * N) { cur[idx - N] = 0; return; }
    int j = idx - 2 * N;
    if (j < 512)       o1[j]        = 0.99f * ask1[j]        + 0.01f * asq1[j];
    else if (j < 1024) o2[j - 512]  = 0.99f * adk1[j - 512]  + 0.01f * adq1[j - 512];
    else if (j < 1536) o3[j - 1024] = 0.99f * bk1[j - 1024]  + 0.01f * bq1[j - 1024];
    else if (j < 2048) o4[j - 1536] = 0.99f * ask2[j - 1536] + 0.01f * asq2[j - 1536];
    else if (j < 2560) o5[j - 2048] = 0.99f * adk2[j - 2048] + 0.01f * adq2[j - 2048];
    else if (j < 2688) o6[j - 2560] = 0.99f * bk2[j - 2560]  + 0.01f * bq2[j - 2560];
}

// ------------------------------- CSR build ---------------------------------
__global__ void csr_count_kernel(const int* __restrict__ ei, int E, int N,
                                 int* __restrict__ deg) {
    int i = blockIdx.x * blockDim.x + threadIdx.x;
    int ET = E + N;
    if (i >= ET) return;
    int d = (i < E) ? ei[E + i] : (i - E);
    atomicAdd(&deg[d], 1);
}

__global__ void csr_scan_kernel(const int* __restrict__ deg,
                                int* __restrict__ off, int N) {
    __shared__ int sh[1024];
    __shared__ int carry;
    int t = threadIdx.x;
    if (t == 0) carry = 0;
    __syncthreads();
    for (int base = 0; base < N; base += 1024) {
        int v = (base + t < N) ? deg[base + t] : 0;
        sh[t] = v;
        __syncthreads();
        for (int o = 1; o < 1024; o <<= 1) {
            int x = (t >= o) ? sh[t - o] : 0;
            __syncthreads();
            sh[t] += x;
            __syncthreads();
        }
        int excl = sh[t] - v + carry;
        if (base + t < N) off[base + t] = excl;
        __syncthreads();
        if (t == 1023) carry += sh[1023];
        __syncthreads();
    }
    if (t == 0) off[N] = carry;
}

__global__ void csr_fill_kernel(const int* __restrict__ ei, int E, int N,
                                const int* __restrict__ off,
                                int* __restrict__ cur,
                                int* __restrict__ csrc) {
    int i = blockIdx.x * blockDim.x + threadIdx.x;
    int ET = E + N;
    if (i >= ET) return;
    int s, d;
    if (i < E) { s = ei[i]; d = ei[E + i]; } else { s = d = i - E; }
    int pos = atomicAdd(&cur[d], 1);
    csrc[off[d] + pos] = s;
}

// -------- batched wmma GEMM: CTA 256x128, warp 64x64, BK=64, 2-stage -------
#define BM 256
#define BN 128
#define BK 64
#define A_LD 72
#define B_LD 136
#define A_TILE_B 36864u      // 256*72*2
#define B_TILE_B 17408u      // 64*136*2
#define ST_AH 0u
#define ST_AL A_TILE_B
#define ST_BH (2u * A_TILE_B)
#define ST_BL (2u * A_TILE_B + B_TILE_B)
#define STAGE_B (2u * A_TILE_B + 2u * B_TILE_B)   // 108544
#define SMEM_GEMM_BYTES (2 * STAGE_B)             // 217088

__global__ void __launch_bounds__(256, 1)
gemm_wmma_split_kernel(int K, int Nn,
                       const bf16* __restrict__ Ahg0, const bf16* __restrict__ Alg0,
                       const bf16* __restrict__ Bhg0, const bf16* __restrict__ Blg0,
                       float* __restrict__ C0,
                       size_t strideA, size_t strideB, size_t strideC) {
    extern __shared__ char smem[];
    const uint32_t sb = smem_u32(smem);
    const int tid = threadIdx.x;
    const int bn = blockIdx.x, bm = blockIdx.y;
    const size_t z = blockIdx.z;
    const bf16* Ahg = Ahg0 + z * strideA;
    const bf16* Alg = Alg0 + z * strideA;
    const bf16* Bhg = Bhg0 + z * strideB;
    const bf16* Blg = Blg0 + z * strideB;
    float* C = C0 + z * strideC;

    const int warpId = tid >> 5;
    const int wm = warpId & 3;    // 4 row groups of 64
    const int wn = warpId >> 2;   // 2 col groups of 64
    const int nk = K >> 6;

    const size_t aBase = (size_t)(bm * BM);
    const int cCol = bn * BN;

    auto load_stage = [&](int kt, uint32_t stg) {
        // A: 256 rows x 8 segs x (h,l) -> 2048 chunk-ids, 8 iters
#pragma unroll
        for (int i = 0; i < 8; i++) {
            int idx = tid + (i << 8);
            int ar = idx >> 3, as = (idx & 7) << 3;
            const size_t ago = (aBase + ar) * K + kt * BK + as;
            uint32_t aso = (uint32_t)(ar * A_LD + as) * 2;
            cp_async16(sb + stg + ST_AH + aso, Ahg + ago);
            cp_async16(sb + stg + ST_AL + aso, Alg + ago);
        }
        // B: 64 rows x 16 segs -> 1024 chunk-ids, 4 iters
#pragma unroll
        for (int i = 0; i < 4; i++) {
            int idx = tid + (i << 8);
            int br = idx >> 4, bs = (idx & 15) << 3;
            const size_t bgo = (size_t)(kt * BK + br) * Nn + cCol + bs;
            uint32_t bso = (uint32_t)(br * B_LD + bs) * 2;
            cp_async16(sb + stg + ST_BH + bso, Bhg + bgo);
            cp_async16(sb + stg + ST_BL + bso, Blg + bgo);
        }
        CP_COMMIT();
    };

    wmma::fragment<wmma::accumulator, 16, 16, 16, float> acc[4][4];
#pragma unroll
    for (int i = 0; i < 4; i++)
#pragma unroll
        for (int j = 0; j < 4; j++) wmma::fill_fragment(acc[i][j], 0.0f);

    load_stage(0, 0);

    for (int kt = 0; kt < nk; kt++) {
        const uint32_t stg = (kt & 1) ? STAGE_B : 0u;
        if (kt + 1 < nk) {
            load_stage(kt + 1, (kt & 1) ? 0u : STAGE_B);
            CP_WAIT(1);
        } else {
            CP_WAIT(0);
        }
        __syncthreads();

        const bf16* sAh = (const bf16*)(smem + stg + ST_AH);
        const bf16* sAl = (const bf16*)(smem + stg + ST_AL);
        const bf16* sBh = (const bf16*)(smem + stg + ST_BH);
        const bf16* sBl = (const bf16*)(smem + stg + ST_BL);

#pragma unroll
        for (int kk = 0; kk < BK; kk += 16) {
            wmma::fragment<wmma::matrix_a, 16, 16, 16, bf16, wmma::row_major> ah[4], al[4];
#pragma unroll
            for (int i = 0; i < 4; i++) {
                wmma::load_matrix_sync(ah[i], sAh + (wm * 64 + i * 16) * A_LD + kk, A_LD);
                wmma::load_matrix_sync(al[i], sAl + (wm * 64 + i * 16) * A_LD + kk, A_LD);
            }
#pragma unroll
            for (int j = 0; j < 4; j++) {
                wmma::fragment<wmma::matrix_b, 16, 16, 16, bf16, wmma::row_major> bh, bl;
                wmma::load_matrix_sync(bh, sBh + kk * B_LD + wn * 64 + j * 16, B_LD);
                wmma::load_matrix_sync(bl, sBl + kk * B_LD + wn * 64 + j * 16, B_LD);
#pragma unroll
                for (int i = 0; i < 4; i++) {
                    wmma::mma_sync(acc[i][j], ah[i], bh, acc[i][j]);
                    wmma::mma_sync(acc[i][j], ah[i], bl, acc[i][j]);
                    wmma::mma_sync(acc[i][j], al[i], bh, acc[i][j]);
                }
            }
        }
        __syncthreads();
    }

#pragma unroll
    for (int i = 0; i < 4; i++) {
        int row = bm * BM + wm * 64 + i * 16;
#pragma unroll
        for (int j = 0; j < 4; j++) {
            int col = cCol + wn * 64 + j * 16;
            wmma::store_matrix_sync(&C[(size_t)row * Nn + col], acc[i][j],
                                    Nn, wmma::mem_row_major);
        }
    }
}

// ---------------------------- attention scores (batched) -------------------
__global__ void att_scores_kernel(const float* __restrict__ Hbase, size_t hstride,
                                  const float* __restrict__ s0, const float* __restrict__ d0,
                                  const float* __restrict__ s1, const float* __restrict__ d1,
                                  float* __restrict__ a_s_base,
                                  float* __restrict__ a_d_base, int N) {
    int n = blockIdx.x;
    if (n >= N) return;
    int z = blockIdx.y;
    const float* Hf = Hbase + (size_t)z * hstride;
    const float* att_s = z ? s1 : s0;
    const float* att_d = z ? d1 : d0;
    float* a_s = a_s_base + (size_t)z * NMAX * 4;
    float* a_d = a_d_base + (size_t)z * NMAX * 4;

    int h = threadIdx.y;
    int lane = threadIdx.x;
    const float* row = Hf + (size_t)n * F512 + h * C128;
    float ss = 0.f, sd = 0.f;
#pragma unroll
    for (int j = 0; j < 4; j++) {
        int c = lane + 32 * j;
        float v = row[c];
        ss += v * att_s[h * C128 + c];
        sd += v * att_d[h * C128 + c];
    }
#pragma unroll
    for (int o = 16; o > 0; o >>= 1) {
        ss += __shfl_down_sync(0xffffffffu, ss, o);
        sd += __shfl_down_sync(0xffffffffu, sd, o);
    }
    if (lane == 0) { a_s[n * 4 + h] = ss; a_d[n * 4 + h] = sd; }
}

// ---------------- fused per-dst softmax + aggregation (batched) ------------
__device__ __forceinline__ float leaky(float e) { return e > 0.f ? e : 0.2f * e; }

__global__ __launch_bounds__(256)
void gat_attn_kernel(const float* __restrict__ Hbase, size_t hstride,
                     const float4* __restrict__ a_s_base,
                     const float4* __restrict__ a_d_base,
                     const int* __restrict__ off,
                     const int* __restrict__ deg_arr,
                     const int* __restrict__ csrc,
                     const float* __restrict__ bias0,
                     const float* __restrict__ bias1,
                     bf16* __restrict__ outh, bf16* __restrict__ outl,
                     float* __restrict__ outf, size_t ostride) {
    int d = blockIdx.x;
    int z = blockIdx.y;
    int t = threadIdx.x;
    int lane = t & 31, wid = t >> 5;

    const float* Hf = Hbase + (size_t)z * hstride;
    const float4* a_s4 = a_s_base + (size_t)z * NMAX;
    const float4* a_d4 = a_d_base + (size_t)z * NMAX;
    const float* bias = z ? bias1 : bias0;

    __shared__ int   s_list[CAP];
    __shared__ float w[CAP][4];
    __shared__ float red[8][4];
    __shared__ float mx_s[4], invd_s[4];

    const int start = off[d];
    const int deg = deg_arr[d];
    const float4 ad = a_d4[d];

    float m0 = -1e30f, m1 = -1e30f, m2 = -1e30f, m3 = -1e30f;
    for (int j = t; j < deg; j += 256) {
        int s = csrc[start + j];
        float4 as = a_s4[s];
        float e0 = leaky(as.x + ad.x);
        float e1 = leaky(as.y + ad.y);
        float e2 = leaky(as.z + ad.z);
        float e3 = leaky(as.w + ad.w);
        if (j < CAP) {
            s_list[j] = s;
            w[j][0] = e0; w[j][1] = e1; w[j][2] = e2; w[j][3] = e3;
        }
        m0 = fmaxf(m0, e0); m1 = fmaxf(m1, e1);
        m2 = fmaxf(m2, e2); m3 = fmaxf(m3, e3);
    }
#pragma unroll
    for (int o = 16; o > 0; o >>= 1) {
        m0 = fmaxf(m0, __shfl_xor_sync(0xffffffffu, m0, o));
        m1 = fmaxf(m1, __shfl_xor_sync(0xffffffffu, m1, o));
        m2 = fmaxf(m2, __shfl_xor_sync(0xffffffffu, m2, o));
        m3 = fmaxf(m3, __shfl_xor_sync(0xffffffffu, m3, o));
    }
    if (lane == 0) { red[wid][0] = m0; red[wid][1] = m1; red[wid][2] = m2; red[wid][3] = m3; }
    __syncthreads();
    if (t < 4) {
        float mm = -1e30f;
#pragma unroll
        for (int k = 0; k < 8; k++) mm = fmaxf(mm, red[k][t]);
        mx_s[t] = mm;
    }
    __syncthreads();
    const float mx0 = mx_s[0], mx1 = mx_s[1], mx2 = mx_s[2], mx3 = mx_s[3];

    float s0 = 0.f, s1 = 0.f, s2 = 0.f, s3 = 0.f;
    for (int j = t; j < deg; j += 256) {
        float e0, e1, e2, e3;
        if (j < CAP) {
            e0 = w[j][0]; e1 = w[j][1]; e2 = w[j][2]; e3 = w[j][3];
        } else {
            int s = csrc[start + j];
            float4 as = a_s4[s];
            e0 = leaky(as.x + ad.x); e1 = leaky(as.y + ad.y);
            e2 = leaky(as.z + ad.z); e3 = leaky(as.w + ad.w);
        }
        float x0 = expf(e0 - mx0), x1 = expf(e1 - mx1);
        float x2 = expf(e2 - mx2), x3 = expf(e3 - mx3);
        if (j < CAP) { w[j][0] = x0; w[j][1] = x1; w[j][2] = x2; w[j][3] = x3; }
        s0 += x0; s1 += x1; s2 += x2; s3 += x3;
    }
#pragma unroll
    for (int o = 16; o > 0; o >>= 1) {
        s0 += __shfl_xor_sync(0xffffffffu, s0, o);
        s1 += __shfl_xor_sync(0xffffffffu, s1, o);
        s2 += __shfl_xor_sync(0xffffffffu, s2, o);
        s3 += __shfl_xor_sync(0xffffffffu, s3, o);
    }
    __syncthreads();
    if (lane == 0) { red[wid][0] = s0; red[wid][1] = s1; red[wid][2] = s2; red[wid][3] = s3; }
    __syncthreads();
    if (t < 4) {
        float ssum = 0.f;
#pragma unroll
        for (int k = 0; k < 8; k++) ssum += red[k][t];
        invd_s[t] = 1.0f / (ssum + 1e-16f);
    }
    __syncthreads();

    const int c2 = t * 2;
    const int h = c2 >> 7;
    const float inv = invd_s[h];
    const float mxh = mx_s[h];
    float acc0 = 0.f, acc1 = 0.f;
    for (int j = 0; j < deg; j++) {
        int s;
        float ww;
        if (j < CAP) {
            s = s_list[j];
            ww = w[j][h];
        } else {
            s = csrc[start + j];
            const float* asp = (const float*)&a_s4[s];
            const float* adp = (const float*)&ad;
            ww = expf(leaky(asp[h] + adp[h]) - mxh);
        }
        float alpha = ww * inv;
        float2 v = *(const float2*)(Hf + (size_t)s * F512 + c2);
        acc0 += v.x * alpha;
        acc1 += v.y * alpha;
    }
    if (outh) {
        acc0 = fmaxf(acc0 + bias[c2], 0.f);
        acc1 = fmaxf(acc1 + bias[c2 + 1], 0.f);
        bf16 h0, l0, h1, l1;
        split2(acc0, h0, l0);
        split2(acc1, h1, l1);
        size_t o = (size_t)z * NMAX * F512 + (size_t)d * F512 + c2;
        *(uint32_t*)(outh + o) = (uint32_t)__bfloat16_as_ushort(h0) |
                                 ((uint32_t)__bfloat16_as_ushort(h1) << 16);
        *(uint32_t*)(outl + o) = (uint32_t)__bfloat16_as_ushort(l0) |
                                 ((uint32_t)__bfloat16_as_ushort(l1) << 16);
    } else {
        size_t o = (size_t)z * ostride + (size_t)d * F512 + c2;
        *(float2*)(outf + o) = make_float2(acc0, acc1);
    }
}

// layer-2 epilogue (batched)
__global__ void head_mean_norm_kernel(const float* __restrict__ aggr_base, size_t astride,
                                      const float* __restrict__ bias0,
                                      const float* __restrict__ bias1,
                                      float* __restrict__ outq,
                                      float* __restrict__ outk, int B) {
    int n = blockIdx.x;
    if (n >= B) return;
    int z = blockIdx.y;
    const float* aggr = aggr_base + (size_t)z * astride;
    const float* bias = z ? bias1 : bias0;
    float* outv = z ? outk : outq;
    int c = threadIdx.x;
    size_t base = (size_t)n * F512;
    float v = 0.25f * (aggr[base + c] + aggr[base + 128 + c] +
                       aggr[base + 256 + c] + aggr[base + 384 + c]) + bias[c];
    float s = v * v;
#pragma unroll
    for (int o = 16; o > 0; o >>= 1) s += __shfl_down_sync(0xffffffffu, s, o);
    __shared__ float red[4];
    if ((c & 31) == 0) red[c >> 5] = s;
    __syncthreads();
    float tot = red[0] + red[1] + red[2] + red[3];
    outv[(size_t)n * C128 + c] = v * rsqrtf(tot + 1e-24f);
}

// ---------------- logits: tiled fp32 GEMM out[B,1+R] ------------------------
#define LT 64
__global__ __launch_bounds__(256)
void logits_gemm_kernel(const float* __restrict__ q,
                        const float* __restrict__ kv,
                        const float* __restrict__ queue,
                        float* __restrict__ out, int B, int R,
                        long tail_off, long tail_len) {
    __shared__ float qt[LT][33];
    __shared__ float kt[32][LT + 4];
    const int tid = threadIdx.x;
    const int bx = blockIdx.x, by = blockIdx.y;
    const int tx = tid & 15, ty = tid >> 4;

    float acc[4][4];
#pragma unroll
    for (int i = 0; i < 4; i++)
#pragma unroll
        for (int j = 0; j < 4; j++) acc[i][j] = 0.f;

    for (int k0 = 0; k0 < 128; k0 += 32) {
#pragma unroll
        for (int i = 0; i < 8; i++) {
            int e = tid + i * 256;
            int r = e >> 5, c = e & 31;
            int gr = by * LT + r;
            qt[r][c] = (gr < B) ? q[(size_t)gr * 128 + k0 + c] : 0.f;
        }
#pragma unroll
        for (int i = 0; i < 8; i++) {
            int e = tid + i * 256;
            int r = e >> 6, c = e & 63;
            int gc = bx * LT + c;
            kt[r][c] = (gc < R) ? queue[(size_t)(k0 + r) * R + gc] : 0.f;
        }
        __syncthreads();
#pragma unroll
        for (int k = 0; k < 32; k++) {
            float ra[4], rb[4];
#pragma unroll
            for (int i = 0; i < 4; i++) ra[i] = qt[ty * 4 + i][k];
#pragma unroll
            for (int j = 0; j < 4; j++) rb[j] = kt[k][tx * 4 + j];
#pragma unroll
            for (int i = 0; i < 4; i++)
#pragma unroll
                for (int j = 0; j < 4; j++) acc[i][j] += ra[i] * rb[j];
        }
        __syncthreads();
    }

#pragma unroll
    for (int i = 0; i < 4; i++) {
        int row = by * LT + ty * 4 + i;
        if (row >= B) continue;
#pragma unroll
        for (int j = 0; j < 4; j++) {
            int col = bx * LT + tx * 4 + j;
            if (col < R)
                out[(size_t)row * (R + 1) + 1 + col] = acc[i][j] * 5.0f;
        }
    }

    if (bx == 0 && tid < LT) {
        int n = by * LT + tid;
        if (n < B) {
            const float* qr = q + (size_t)n * 128;
            const float* kr = kv + (size_t)n * 128;
            float s = 0.f;
#pragma unroll 4
            for (int c = 0; c < 128; c++) s += qr[c] * kr[c];
            out[(size_t)n * (R + 1)] = s * 5.0f;
        }
    }
    if (bx == 0 && by == 0) {
        for (long i = tid; i < tail_len; i += 256) out[tail_off + i] = 0.f;
    }
}

// ------------------------------- launch ------------------------------------
extern "C" void kernel_launch(void* const* d_in, const int* in_sizes, int n_in,
                              void* d_out, int out_size) {
    int base = n_in - 17;

    const float* im_q = (const float*)d_in[0];
    const float* im_k = (const float*)d_in[1];
    const int*   ei   = (const int*)d_in[2];

    const float* Wq1  = (const float*)d_in[base + 0];
    const float* asq1 = (const float*)d_in[base + 1];
    const float* adq1 = (const float*)d_in[base + 2];
    const float* bq1  = (const float*)d_in[base + 3];
    const float* Wq2  = (const float*)d_in[base + 4];
    const float* asq2 = (const float*)d_in[base + 5];
    const float* adq2 = (const float*)d_in[base + 6];
    const float* bq2  = (const float*)d_in[base + 7];
    const float* Wk1  = (const float*)d_in[base + 8];
    const float* ask1 = (const float*)d_in[base + 9];
    const float* adk1 = (const float*)d_in[base + 10];
    const float* bk1  = (const float*)d_in[base + 11];
    const float* Wk2  = (const float*)d_in[base + 12];
    const float* ask2 = (const float*)d_in[base + 13];
    const float* adk2 = (const float*)d_in[base + 14];
    const float* bk2  = (const float*)d_in[base + 15];
    const float* queue= (const float*)d_in[base + 16];

    int G = in_sizes[base] / F512;
    int N = in_sizes[0] / G;
    int E = in_sizes[2] / 2;
    int R = in_sizes[base + 16] / C128;
    int B = (out_size % (R + 2) == 0) ? out_size / (R + 2) : out_size / (R + 1);
    if (B > N) B = N;
    int ET = E + N;
    int Mp = (N + 255) & ~255;           // BM=256 tiles
    int Kp1 = (G + 63) & ~63;

    float *Hbuf, *asrc, *adst, *seedq, *seedk;
    float *ask1m, *adk1m, *bk1m, *ask2m, *adk2m, *bk2m;
    int *deg, *off, *cur, *csrc;
    bf16 *A1h, *A1l, *A2h, *A2l, *W1h, *W1l, *W2h, *W2l;
    cudaGetSymbolAddress((void**)&Hbuf, g_H);
    cudaGetSymbolAddress((void**)&asrc, g_asrc);
    cudaGetSymbolAddress((void**)&adst, g_adst);
    cudaGetSymbolAddress((void**)&seedq, g_seedq);
    cudaGetSymbolAddress((void**)&seedk, g_seedk);
    cudaGetSymbolAddress((void**)&ask1m, g_ask1m);
    cudaGetSymbolAddress((void**)&adk1m, g_adk1m);
    cudaGetSymbolAddress((void**)&bk1m, g_bk1m);
    cudaGetSymbolAddress((void**)&ask2m, g_ask2m);
    cudaGetSymbolAddress((void**)&adk2m, g_adk2m);
    cudaGetSymbolAddress((void**)&bk2m, g_bk2m);
    cudaGetSymbolAddress((void**)&deg, g_deg);
    cudaGetSymbolAddress((void**)&off, g_off);
    cudaGetSymbolAddress((void**)&cur, g_cur);
    cudaGetSymbolAddress((void**)&csrc, g_csrc);
    cudaGetSymbolAddress((void**)&A1h, g_A1h);
    cudaGetSymbolAddress((void**)&A1l, g_A1l);
    cudaGetSymbolAddress((void**)&A2h, g_A2h);
    cudaGetSymbolAddress((void**)&A2l, g_A2l);
    cudaGetSymbolAddress((void**)&W1h, g_W1h);
    cudaGetSymbolAddress((void**)&W1l, g_W1l);
    cudaGetSymbolAddress((void**)&W2h, g_W2h);
    cudaGetSymbolAddress((void**)&W2l, g_W2l);

    cudaFuncSetAttribute(gemm_wmma_split_kernel,
                         cudaFuncAttributeMaxDynamicSharedMemorySize, SMEM_GEMM_BYTES);

    const size_t a1slot = (size_t)Mp * Kp1;
    const size_t a2slot = (size_t)NMAX * F512;
    const size_t hslot  = (size_t)NMAX * F512;
    const size_t w1slot = (size_t)Kp1 * F512;
    const size_t w2slot = (size_t)F512 * F512;
    float* aggr2 = (float*)A1h;
    const size_t aggr2slot = (size_t)NMAX * F512;

    long totA1 = (long)Mp * Kp1;
    long wtot = 2 * (long)w1slot + 2 * (long)w2slot;

    // 1) input split (batched q/k)
    split_pad2_kernel<<<dim3((unsigned)((totA1 + 255) / 256), 2), 256>>>(
        im_q, im_k, N, G, Kp1, totA1, A1h, A1l);
    // 2) all weight splits
    wsplit_all_kernel<<<(int)((wtot + 255) / 256), 256>>>(
        Wq1, Wk1, Wq2, Wk2, G, Kp1, W1h, W1l, W2h, W2l);
    // 3) layer-1 GEMM (batched)
    {
        dim3 grid(F512 / BN, Mp / BM, 2);
        gemm_wmma_split_kernel<<<grid, 256, SMEM_GEMM_BYTES>>>(
            Kp1, F512, A1h, A1l, W1h, W1l, Hbuf, a1slot, w1slot, hslot);
    }
    // 4) misc prep
    misc_prep_kernel<<<(2 * N + 2688 + 255) / 256, 256>>>(
        N, deg, cur,
        ask1, asq1, adk1, adq1, bk1, bq1,
        ask2, asq2, adk2, adq2, bk2, bq2,
        ask1m, adk1m, bk1m, ask2m, adk2m, bk2m);
    // 5-7) CSR
    csr_count_kernel<<<(ET + 255) / 256, 256>>>(ei, E, N, deg);
    csr_scan_kernel<<<1, 1024>>>(deg, off, N);
    csr_fill_kernel<<<(ET + 255) / 256, 256>>>(ei, E, N, off, cur, csrc);
    // 8-9) layer-1 attention -> bf16 A2 (pad rows stay zero from init)
    att_scores_kernel<<<dim3(N, 2), dim3(32, 4)>>>(Hbuf, hslot, asq1, adq1, ask1m, adk1m,
                                                   asrc, adst, N);
    gat_attn_kernel<<<dim3(N, 2), 256>>>(Hbuf, hslot, (const float4*)asrc,
                                         (const float4*)adst, off, deg, csrc,
                                         bq1, bk1m, A2h, A2l, nullptr, 0);
    // 10) layer-2 GEMM (batched)
    {
        dim3 grid(F512 / BN, Mp / BM, 2);
        gemm_wmma_split_kernel<<<grid, 256, SMEM_GEMM_BYTES>>>(
            F512, F512, A2h, A2l, W2h, W2l, Hbuf, a2slot, w2slot, hslot);
    }
    // 11-12) layer-2 attention (dst < B only)
    att_scores_kernel<<<dim3(N, 2), dim3(32, 4)>>>(Hbuf, hslot, asq2, adq2, ask2m, adk2m,
                                                   asrc, adst, N);
    gat_attn_kernel<<<dim3(B, 2), 256>>>(Hbuf, hslot, (const float4*)asrc,
                                         (const float4*)adst, off, deg, csrc,
                                         nullptr, nullptr, nullptr, nullptr,
                                         aggr2, aggr2slot);
    // 13) head-mean + l2norm
    head_mean_norm_kernel<<<dim3(B, 2), 128>>>(aggr2, aggr2slot, bq2, bk2m,
                                               seedq, seedk, B);
    // 14) logits
    {
        long written = (long)B * (R + 1);
        long tail = (long)out_size - written;
        if (tail < 0) tail = 0;
        dim3 grid((R + LT - 1) / LT, (B + LT - 1) / LT);
        logits_gemm_kernel<<<grid, 256>>>(seedq, seedk, queue, (float*)d_out,
                                          B, R, written, tail);
    }
}

// round 9
// speedup vs baseline: 4.0013x; 1.0788x over previous
#include <cuda_runtime.h>
#include <cuda_bf16.h>
#include <mma.h>
#include <cstdint>

using namespace nvcuda;

// ---------------------------------------------------------------------------
// MoCoGraph: two 2-layer GAT encoders + MoCo logits.
// GEMMs: bf16 3-term split, pre-split operands, BK=64 cp.async double-buffer,
//        CTA 192x128 (grid 432 = 2.92 waves on 148 SMs -> 97% wave util),
//        warp tile 48x64, batched over encoders (grid.z=2).
// Attention: CSR gather, fused softmax+aggregate+bias/relu+bf16-split epilogue.
// Logits: smem-tiled fp32 GEMM.
// ---------------------------------------------------------------------------

#define NMAX   10240
#define MPAD   10368     // multiple of 192 >= N
#define ETMAX  180224
#define F512   512
#define C128   128
#define CAP    512
#define KPAD1  1024

typedef __nv_bfloat16 bf16;

// ------------------------- device scratch (no mallocs) ---------------------
__device__ float g_H   [2 * (size_t)MPAD * F512];
__device__ bf16  g_A1h [2 * (size_t)MPAD * KPAD1];
__device__ bf16  g_A1l [2 * (size_t)MPAD * KPAD1];
__device__ bf16  g_A2h [2 * (size_t)MPAD * F512];   // pad rows stay 0 (zero-init)
__device__ bf16  g_A2l [2 * (size_t)MPAD * F512];
__device__ bf16  g_W1h [2 * KPAD1 * F512], g_W1l[2 * KPAD1 * F512];
__device__ bf16  g_W2h [2 * F512 * F512],  g_W2l[2 * F512 * F512];
__device__ float g_asrc[2 * NMAX * 4];
__device__ float g_adst[2 * NMAX * 4];
__device__ float g_seedq[(size_t)NMAX * C128];
__device__ float g_seedk[(size_t)NMAX * C128];
__device__ float g_ask1m[F512], g_adk1m[F512], g_bk1m[F512];
__device__ float g_ask2m[F512], g_adk2m[F512], g_bk2m[C128];
__device__ int g_deg[NMAX];
__device__ int g_off[NMAX + 1];
__device__ int g_cur[NMAX];
__device__ int g_csrc[ETMAX];

// ------------------------------ helpers ------------------------------------
__device__ __forceinline__ uint32_t smem_u32(const void* p) {
    uint32_t a;
    asm("{ .reg .u64 t; cvta.to.shared.u64 t, %1; cvt.u32.u64 %0, t; }" : "=r"(a) : "l"(p));
    return a;
}
__device__ __forceinline__ void cp_async16(uint32_t s, const void* g) {
    asm volatile("cp.async.cg.shared.global [%0], [%1], 16;" :: "r"(s), "l"(g));
}
#define CP_COMMIT() asm volatile("cp.async.commit_group;" ::: "memory")
#define CP_WAIT(n)  asm volatile("cp.async.wait_group %0;" :: "n"(n) : "memory")

__device__ __forceinline__ void split2(float v, bf16& h, bf16& l) {
    h = __float2bfloat16(v);
    l = __float2bfloat16(v - __bfloat162float(h));
}

// ------------------------------ prep kernels -------------------------------
__global__ void split_pad2_kernel(const float* __restrict__ in0,
                                  const float* __restrict__ in1,
                                  int M, int K, int Kp, long total,
                                  bf16* __restrict__ hi, bf16* __restrict__ lo) {
    long idx = (long)blockIdx.x * blockDim.x + threadIdx.x;
    if (idx >= total) return;
    const float* in = blockIdx.y ? in1 : in0;
    size_t o = (size_t)blockIdx.y * total + idx;
    int r = (int)(idx / Kp), c = (int)(idx % Kp);
    float v = (r < M && c < K) ? in[(size_t)r * K + c] : 0.f;
    bf16 h, l; split2(v, h, l);
    hi[o] = h; lo[o] = l;
}

__global__ void wsplit_all_kernel(const float* __restrict__ Wq1,
                                  const float* __restrict__ Wk1,
                                  const float* __restrict__ Wq2,
                                  const float* __restrict__ Wk2,
                                  int G, int Kp1,
                                  bf16* __restrict__ W1h, bf16* __restrict__ W1l,
                                  bf16* __restrict__ W2h, bf16* __restrict__ W2l) {
    long idx = (long)blockIdx.x * blockDim.x + threadIdx.x;
    const long s1 = (long)Kp1 * F512;
    const long s2 = (long)F512 * F512;
    if (idx < 2 * s1) {
        int z = idx >= s1;
        long j = idx - (long)z * s1;
        int r = (int)(j / F512);
        float v = 0.f;
        if (r < G) v = z ? (0.99f * Wk1[j] + 0.01f * Wq1[j]) : Wq1[j];
        bf16 h, l; split2(v, h, l);
        W1h[idx] = h; W1l[idx] = l;
    } else if (idx < 2 * s1 + 2 * s2) {
        long j2 = idx - 2 * s1;
        int z = j2 >= s2;
        long j = j2 - (long)z * s2;
        float v = z ? (0.99f * Wk2[j] + 0.01f * Wq2[j]) : Wq2[j];
        bf16 h, l; split2(v, h, l);
        W2h[j2] = h; W2l[j2] = l;
    }
}

__global__ void misc_prep_kernel(int N,
                                 int* __restrict__ deg, int* __restrict__ cur,
                                 const float* ask1, const float* asq1,
                                 const float* adk1, const float* adq1,
                                 const float* bk1,  const float* bq1,
                                 const float* ask2, const float* asq2,
                                 const float* adk2, const float* adq2,
                                 const float* bk2,  const float* bq2,
                                 float* o1, float* o2, float* o3,
                                 float* o4, float* o5, float* o6) {
    int idx = blockIdx.x * blockDim.x + threadIdx.x;
    if (idx < N) { deg[idx] = 0; return; }
    if (idx < 2 * N) { cur[idx - N] = 0; return; }
    int j = idx - 2 * N;
    if (j < 512)       o1[j]        = 0.99f * ask1[j]        + 0.01f * asq1[j];
    else if (j < 1024) o2[j - 512]  = 0.99f * adk1[j - 512]  + 0.01f * adq1[j - 512];
    else if (j < 1536) o3[j - 1024] = 0.99f * bk1[j - 1024]  + 0.01f * bq1[j - 1024];
    else if (j < 2048) o4[j - 1536] = 0.99f * ask2[j - 1536] + 0.01f * asq2[j - 1536];
    else if (j < 2560) o5[j - 2048] = 0.99f * adk2[j - 2048] + 0.01f * adq2[j - 2048];
    else if (j < 2688) o6[j - 2560] = 0.99f * bk2[j - 2560]  + 0.01f * bq2[j - 2560];
}

// ------------------------------- CSR build ---------------------------------
__global__ void csr_count_kernel(const int* __restrict__ ei, int E, int N,
                                 int* __restrict__ deg) {
    int i = blockIdx.x * blockDim.x + threadIdx.x;
    int ET = E + N;
    if (i >= ET) return;
    int d = (i < E) ? ei[E + i] : (i - E);
    atomicAdd(&deg[d], 1);
}

__global__ void csr_scan_kernel(const int* __restrict__ deg,
                                int* __restrict__ off, int N) {
    __shared__ int sh[1024];
    __shared__ int carry;
    int t = threadIdx.x;
    if (t == 0) carry = 0;
    __syncthreads();
    for (int base = 0; base < N; base += 1024) {
        int v = (base + t < N) ? deg[base + t] : 0;
        sh[t] = v;
        __syncthreads();
        for (int o = 1; o < 1024; o <<= 1) {
            int x = (t >= o) ? sh[t - o] : 0;
            __syncthreads();
            sh[t] += x;
            __syncthreads();
        }
        int excl = sh[t] - v + carry;
        if (base + t < N) off[base + t] = excl;
        __syncthreads();
        if (t == 1023) carry += sh[1023];
        __syncthreads();
    }
    if (t == 0) off[N] = carry;
}

__global__ void csr_fill_kernel(const int* __restrict__ ei, int E, int N,
                                const int* __restrict__ off,
                                int* __restrict__ cur,
                                int* __restrict__ csrc) {
    int i = blockIdx.x * blockDim.x + threadIdx.x;
    int ET = E + N;
    if (i >= ET) return;
    int s, d;
    if (i < E) { s = ei[i]; d = ei[E + i]; } else { s = d = i - E; }
    int pos = atomicAdd(&cur[d], 1);
    csrc[off[d] + pos] = s;
}

// -------- batched wmma GEMM: CTA 192x128, warp 48x64, BK=64, 2-stage -------
#define BM 192
#define BN 128
#define BK 64
#define A_LD 72
#define B_LD 136
#define A_TILE_B 27648u      // 192*72*2
#define B_TILE_B 17408u      // 64*136*2
#define ST_AH 0u
#define ST_AL A_TILE_B
#define ST_BH (2u * A_TILE_B)
#define ST_BL (2u * A_TILE_B + B_TILE_B)
#define STAGE_B (2u * A_TILE_B + 2u * B_TILE_B)   // 90112
#define SMEM_GEMM_BYTES (2 * STAGE_B)             // 180224

__global__ void __launch_bounds__(256, 1)
gemm_wmma_split_kernel(int K, int Nn,
                       const bf16* __restrict__ Ahg0, const bf16* __restrict__ Alg0,
                       const bf16* __restrict__ Bhg0, const bf16* __restrict__ Blg0,
                       float* __restrict__ C0,
                       size_t strideA, size_t strideB, size_t strideC) {
    extern __shared__ char smem[];
    const uint32_t sb = smem_u32(smem);
    const int tid = threadIdx.x;
    const int bn = blockIdx.x, bm = blockIdx.y;
    const size_t z = blockIdx.z;
    const bf16* Ahg = Ahg0 + z * strideA;
    const bf16* Alg = Alg0 + z * strideA;
    const bf16* Bhg = Bhg0 + z * strideB;
    const bf16* Blg = Blg0 + z * strideB;
    float* C = C0 + z * strideC;

    const int warpId = tid >> 5;
    const int wm = warpId & 3;    // 4 row groups of 48
    const int wn = warpId >> 2;   // 2 col groups of 64
    const int nk = K >> 6;

    const size_t aBase = (size_t)(bm * BM);
    const int cCol = bn * BN;

    auto load_stage = [&](int kt, uint32_t stg) {
        // A: 192 rows x 8 segs -> 1536 chunk-ids, 6 iters (per h/l)
#pragma unroll
        for (int i = 0; i < 6; i++) {
            int idx = tid + (i << 8);
            int ar = idx >> 3, as = (idx & 7) << 3;
            const size_t ago = (aBase + ar) * K + kt * BK + as;
            uint32_t aso = (uint32_t)(ar * A_LD + as) * 2;
            cp_async16(sb + stg + ST_AH + aso, Ahg + ago);
            cp_async16(sb + stg + ST_AL + aso, Alg + ago);
        }
        // B: 64 rows x 16 segs -> 1024 chunk-ids, 4 iters
#pragma unroll
        for (int i = 0; i < 4; i++) {
            int idx = tid + (i << 8);
            int br = idx >> 4, bs = (idx & 15) << 3;
            const size_t bgo = (size_t)(kt * BK + br) * Nn + cCol + bs;
            uint32_t bso = (uint32_t)(br * B_LD + bs) * 2;
            cp_async16(sb + stg + ST_BH + bso, Bhg + bgo);
            cp_async16(sb + stg + ST_BL + bso, Blg + bgo);
        }
        CP_COMMIT();
    };

    wmma::fragment<wmma::accumulator, 16, 16, 16, float> acc[3][4];
#pragma unroll
    for (int i = 0; i < 3; i++)
#pragma unroll
        for (int j = 0; j < 4; j++) wmma::fill_fragment(acc[i][j], 0.0f);

    load_stage(0, 0);

    for (int kt = 0; kt < nk; kt++) {
        const uint32_t stg = (kt & 1) ? STAGE_B : 0u;
        if (kt + 1 < nk) {
            load_stage(kt + 1, (kt & 1) ? 0u : STAGE_B);
            CP_WAIT(1);
        } else {
            CP_WAIT(0);
        }
        __syncthreads();

        const bf16* sAh = (const bf16*)(smem + stg + ST_AH);
        const bf16* sAl = (const bf16*)(smem + stg + ST_AL);
        const bf16* sBh = (const bf16*)(smem + stg + ST_BH);
        const bf16* sBl = (const bf16*)(smem + stg + ST_BL);

#pragma unroll
        for (int kk = 0; kk < BK; kk += 16) {
            wmma::fragment<wmma::matrix_a, 16, 16, 16, bf16, wmma::row_major> ah[3], al[3];
#pragma unroll
            for (int i = 0; i < 3; i++) {
                wmma::load_matrix_sync(ah[i], sAh + (wm * 48 + i * 16) * A_LD + kk, A_LD);
                wmma::load_matrix_sync(al[i], sAl + (wm * 48 + i * 16) * A_LD + kk, A_LD);
            }
#pragma unroll
            for (int j = 0; j < 4; j++) {
                wmma::fragment<wmma::matrix_b, 16, 16, 16, bf16, wmma::row_major> bh, bl;
                wmma::load_matrix_sync(bh, sBh + kk * B_LD + wn * 64 + j * 16, B_LD);
                wmma::load_matrix_sync(bl, sBl + kk * B_LD + wn * 64 + j * 16, B_LD);
#pragma unroll
                for (int i = 0; i < 3; i++) {
                    wmma::mma_sync(acc[i][j], ah[i], bh, acc[i][j]);
                    wmma::mma_sync(acc[i][j], ah[i], bl, acc[i][j]);
                    wmma::mma_sync(acc[i][j], al[i], bh, acc[i][j]);
                }
            }
        }
        __syncthreads();
    }

#pragma unroll
    for (int i = 0; i < 3; i++) {
        int row = bm * BM + wm * 48 + i * 16;
#pragma unroll
        for (int j = 0; j < 4; j++) {
            int col = cCol + wn * 64 + j * 16;
            wmma::store_matrix_sync(&C[(size_t)row * Nn + col], acc[i][j],
                                    Nn, wmma::mem_row_major);
        }
    }
}

// ---------------------------- attention scores (batched) -------------------
__global__ void att_scores_kernel(const float* __restrict__ Hbase, size_t hstride,
                                  const float* __restrict__ s0, const float* __restrict__ d0,
                                  const float* __restrict__ s1, const float* __restrict__ d1,
                                  float* __restrict__ a_s_base,
                                  float* __restrict__ a_d_base, int N) {
    int n = blockIdx.x;
    if (n >= N) return;
    int z = blockIdx.y;
    const float* Hf = Hbase + (size_t)z * hstride;
    const float* att_s = z ? s1 : s0;
    const float* att_d = z ? d1 : d0;
    float* a_s = a_s_base + (size_t)z * NMAX * 4;
    float* a_d = a_d_base + (size_t)z * NMAX * 4;

    int h = threadIdx.y;
    int lane = threadIdx.x;
    const float* row = Hf + (size_t)n * F512 + h * C128;
    float ss = 0.f, sd = 0.f;
#pragma unroll
    for (int j = 0; j < 4; j++) {
        int c = lane + 32 * j;
        float v = row[c];
        ss += v * att_s[h * C128 + c];
        sd += v * att_d[h * C128 + c];
    }
#pragma unroll
    for (int o = 16; o > 0; o >>= 1) {
        ss += __shfl_down_sync(0xffffffffu, ss, o);
        sd += __shfl_down_sync(0xffffffffu, sd, o);
    }
    if (lane == 0) { a_s[n * 4 + h] = ss; a_d[n * 4 + h] = sd; }
}

// ---------------- fused per-dst softmax + aggregation (batched) ------------
__device__ __forceinline__ float leaky(float e) { return e > 0.f ? e : 0.2f * e; }

__global__ __launch_bounds__(256)
void gat_attn_kernel(const float* __restrict__ Hbase, size_t hstride,
                     const float4* __restrict__ a_s_base,
                     const float4* __restrict__ a_d_base,
                     const int* __restrict__ off,
                     const int* __restrict__ deg_arr,
                     const int* __restrict__ csrc,
                     const float* __restrict__ bias0,
                     const float* __restrict__ bias1,
                     bf16* __restrict__ outh, bf16* __restrict__ outl,
                     float* __restrict__ outf, size_t ostride,
                     size_t oslot) {
    int d = blockIdx.x;
    int z = blockIdx.y;
    int t = threadIdx.x;
    int lane = t & 31, wid = t >> 5;

    const float* Hf = Hbase + (size_t)z * hstride;
    const float4* a_s4 = a_s_base + (size_t)z * NMAX;
    const float4* a_d4 = a_d_base + (size_t)z * NMAX;
    const float* bias = z ? bias1 : bias0;

    __shared__ int   s_list[CAP];
    __shared__ float w[CAP][4];
    __shared__ float red[8][4];
    __shared__ float mx_s[4], invd_s[4];

    const int start = off[d];
    const int deg = deg_arr[d];
    const float4 ad = a_d4[d];

    float m0 = -1e30f, m1 = -1e30f, m2 = -1e30f, m3 = -1e30f;
    for (int j = t; j < deg; j += 256) {
        int s = csrc[start + j];
        float4 as = a_s4[s];
        float e0 = leaky(as.x + ad.x);
        float e1 = leaky(as.y + ad.y);
        float e2 = leaky(as.z + ad.z);
        float e3 = leaky(as.w + ad.w);
        if (j < CAP) {
            s_list[j] = s;
            w[j][0] = e0; w[j][1] = e1; w[j][2] = e2; w[j][3] = e3;
        }
        m0 = fmaxf(m0, e0); m1 = fmaxf(m1, e1);
        m2 = fmaxf(m2, e2); m3 = fmaxf(m3, e3);
    }
#pragma unroll
    for (int o = 16; o > 0; o >>= 1) {
        m0 = fmaxf(m0, __shfl_xor_sync(0xffffffffu, m0, o));
        m1 = fmaxf(m1, __shfl_xor_sync(0xffffffffu, m1, o));
        m2 = fmaxf(m2, __shfl_xor_sync(0xffffffffu, m2, o));
        m3 = fmaxf(m3, __shfl_xor_sync(0xffffffffu, m3, o));
    }
    if (lane == 0) { red[wid][0] = m0; red[wid][1] = m1; red[wid][2] = m2; red[wid][3] = m3; }
    __syncthreads();
    if (t < 4) {
        float mm = -1e30f;
#pragma unroll
        for (int k = 0; k < 8; k++) mm = fmaxf(mm, red[k][t]);
        mx_s[t] = mm;
    }
    __syncthreads();
    const float mx0 = mx_s[0], mx1 = mx_s[1], mx2 = mx_s[2], mx3 = mx_s[3];

    float s0 = 0.f, s1 = 0.f, s2 = 0.f, s3 = 0.f;
    for (int j = t; j < deg; j += 256) {
        float e0, e1, e2, e3;
        if (j < CAP) {
            e0 = w[j][0]; e1 = w[j][1]; e2 = w[j][2]; e3 = w[j][3];
        } else {
            int s = csrc[start + j];
            float4 as = a_s4[s];
            e0 = leaky(as.x + ad.x); e1 = leaky(as.y + ad.y);
            e2 = leaky(as.z + ad.z); e3 = leaky(as.w + ad.w);
        }
        float x0 = expf(e0 - mx0), x1 = expf(e1 - mx1);
        float x2 = expf(e2 - mx2), x3 = expf(e3 - mx3);
        if (j < CAP) { w[j][0] = x0; w[j][1] = x1; w[j][2] = x2; w[j][3] = x3; }
        s0 += x0; s1 += x1; s2 += x2; s3 += x3;
    }
#pragma unroll
    for (int o = 16; o > 0; o >>= 1) {
        s0 += __shfl_xor_sync(0xffffffffu, s0, o);
        s1 += __shfl_xor_sync(0xffffffffu, s1, o);
        s2 += __shfl_xor_sync(0xffffffffu, s2, o);
        s3 += __shfl_xor_sync(0xffffffffu, s3, o);
    }
    __syncthreads();
    if (lane == 0) { red[wid][0] = s0; red[wid][1] = s1; red[wid][2] = s2; red[wid][3] = s3; }
    __syncthreads();
    if (t < 4) {
        float ssum = 0.f;
#pragma unroll
        for (int k = 0; k < 8; k++) ssum += red[k][t];
        invd_s[t] = 1.0f / (ssum + 1e-16f);
    }
    __syncthreads();

    const int c2 = t * 2;
    const int h = c2 >> 7;
    const float inv = invd_s[h];
    const float mxh = mx_s[h];
    float acc0 = 0.f, acc1 = 0.f;
    for (int j = 0; j < deg; j++) {
        int s;
        float ww;
        if (j < CAP) {
            s = s_list[j];
            ww = w[j][h];
        } else {
            s = csrc[start + j];
            const float* asp = (const float*)&a_s4[s];
            const float* adp = (const float*)&ad;
            ww = expf(leaky(asp[h] + adp[h]) - mxh);
        }
        float alpha = ww * inv;
        float2 v = *(const float2*)(Hf + (size_t)s * F512 + c2);
        acc0 += v.x * alpha;
        acc1 += v.y * alpha;
    }
    if (outh) {
        acc0 = fmaxf(acc0 + bias[c2], 0.f);
        acc1 = fmaxf(acc1 + bias[c2 + 1], 0.f);
        bf16 h0, l0, h1, l1;
        split2(acc0, h0, l0);
        split2(acc1, h1, l1);
        size_t o = (size_t)z * oslot + (size_t)d * F512 + c2;
        *(uint32_t*)(outh + o) = (uint32_t)__bfloat16_as_ushort(h0) |
                                 ((uint32_t)__bfloat16_as_ushort(h1) << 16);
        *(uint32_t*)(outl + o) = (uint32_t)__bfloat16_as_ushort(l0) |
                                 ((uint32_t)__bfloat16_as_ushort(l1) << 16);
    } else {
        size_t o = (size_t)z * ostride + (size_t)d * F512 + c2;
        *(float2*)(outf + o) = make_float2(acc0, acc1);
    }
}

// layer-2 epilogue (batched)
__global__ void head_mean_norm_kernel(const float* __restrict__ aggr_base, size_t astride,
                                      const float* __restrict__ bias0,
                                      const float* __restrict__ bias1,
                                      float* __restrict__ outq,
                                      float* __restrict__ outk, int B) {
    int n = blockIdx.x;
    if (n >= B) return;
    int z = blockIdx.y;
    const float* aggr = aggr_base + (size_t)z * astride;
    const float* bias = z ? bias1 : bias0;
    float* outv = z ? outk : outq;
    int c = threadIdx.x;
    size_t base = (size_t)n * F512;
    float v = 0.25f * (aggr[base + c] + aggr[base + 128 + c] +
                       aggr[base + 256 + c] + aggr[base + 384 + c]) + bias[c];
    float s = v * v;
#pragma unroll
    for (int o = 16; o > 0; o >>= 1) s += __shfl_down_sync(0xffffffffu, s, o);
    __shared__ float red[4];
    if ((c & 31) == 0) red[c >> 5] = s;
    __syncthreads();
    float tot = red[0] + red[1] + red[2] + red[3];
    outv[(size_t)n * C128 + c] = v * rsqrtf(tot + 1e-24f);
}

// ---------------- logits: tiled fp32 GEMM out[B,1+R] ------------------------
#define LT 64
__global__ __launch_bounds__(256)
void logits_gemm_kernel(const float* __restrict__ q,
                        const float* __restrict__ kv,
                        const float* __restrict__ queue,
                        float* __restrict__ out, int B, int R,
                        long tail_off, long tail_len) {
    __shared__ float qt[LT][33];
    __shared__ float kt[32][LT + 4];
    const int tid = threadIdx.x;
    const int bx = blockIdx.x, by = blockIdx.y;
    const int tx = tid & 15, ty = tid >> 4;

    float acc[4][4];
#pragma unroll
    for (int i = 0; i < 4; i++)
#pragma unroll
        for (int j = 0; j < 4; j++) acc[i][j] = 0.f;

    for (int k0 = 0; k0 < 128; k0 += 32) {
#pragma unroll
        for (int i = 0; i < 8; i++) {
            int e = tid + i * 256;
            int r = e >> 5, c = e & 31;
            int gr = by * LT + r;
            qt[r][c] = (gr < B) ? q[(size_t)gr * 128 + k0 + c] : 0.f;
        }
#pragma unroll
        for (int i = 0; i < 8; i++) {
            int e = tid + i * 256;
            int r = e >> 6, c = e & 63;
            int gc = bx * LT + c;
            kt[r][c] = (gc < R) ? queue[(size_t)(k0 + r) * R + gc] : 0.f;
        }
        __syncthreads();
#pragma unroll
        for (int k = 0; k < 32; k++) {
            float ra[4], rb[4];
#pragma unroll
            for (int i = 0; i < 4; i++) ra[i] = qt[ty * 4 + i][k];
#pragma unroll
            for (int j = 0; j < 4; j++) rb[j] = kt[k][tx * 4 + j];
#pragma unroll
            for (int i = 0; i < 4; i++)
#pragma unroll
                for (int j = 0; j < 4; j++) acc[i][j] += ra[i] * rb[j];
        }
        __syncthreads();
    }

#pragma unroll
    for (int i = 0; i < 4; i++) {
        int row = by * LT + ty * 4 + i;
        if (row >= B) continue;
#pragma unroll
        for (int j = 0; j < 4; j++) {
            int col = bx * LT + tx * 4 + j;
            if (col < R)
                out[(size_t)row * (R + 1) + 1 + col] = acc[i][j] * 5.0f;
        }
    }

    if (bx == 0 && tid < LT) {
        int n = by * LT + tid;
        if (n < B) {
            const float* qr = q + (size_t)n * 128;
            const float* kr = kv + (size_t)n * 128;
            float s = 0.f;
#pragma unroll 4
            for (int c = 0; c < 128; c++) s += qr[c] * kr[c];
            out[(size_t)n * (R + 1)] = s * 5.0f;
        }
    }
    if (bx == 0 && by == 0) {
        for (long i = tid; i < tail_len; i += 256) out[tail_off + i] = 0.f;
    }
}

// ------------------------------- launch ------------------------------------
extern "C" void kernel_launch(void* const* d_in, const int* in_sizes, int n_in,
                              void* d_out, int out_size) {
    int base = n_in - 17;

    const float* im_q = (const float*)d_in[0];
    const float* im_k = (const float*)d_in[1];
    const int*   ei   = (const int*)d_in[2];

    const float* Wq1  = (const float*)d_in[base + 0];
    const float* asq1 = (const float*)d_in[base + 1];
    const float* adq1 = (const float*)d_in[base + 2];
    const float* bq1  = (const float*)d_in[base + 3];
    const float* Wq2  = (const float*)d_in[base + 4];
    const float* asq2 = (const float*)d_in[base + 5];
    const float* adq2 = (const float*)d_in[base + 6];
    const float* bq2  = (const float*)d_in[base + 7];
    const float* Wk1  = (const float*)d_in[base + 8];
    const float* ask1 = (const float*)d_in[base + 9];
    const float* adk1 = (const float*)d_in[base + 10];
    const float* bk1  = (const float*)d_in[base + 11];
    const float* Wk2  = (const float*)d_in[base + 12];
    const float* ask2 = (const float*)d_in[base + 13];
    const float* adk2 = (const float*)d_in[base + 14];
    const float* bk2  = (const float*)d_in[base + 15];
    const float* queue= (const float*)d_in[base + 16];

    int G = in_sizes[base] / F512;
    int N = in_sizes[0] / G;
    int E = in_sizes[2] / 2;
    int R = in_sizes[base + 16] / C128;
    int B = (out_size % (R + 2) == 0) ? out_size / (R + 2) : out_size / (R + 1);
    if (B > N) B = N;
    int ET = E + N;
    int Mp = (N + BM - 1) / BM * BM;       // multiple of 192
    if (Mp > MPAD) Mp = MPAD;
    int Kp1 = (G + 63) & ~63;

    float *Hbuf, *asrc, *adst, *seedq, *seedk;
    float *ask1m, *adk1m, *bk1m, *ask2m, *adk2m, *bk2m;
    int *deg, *off, *cur, *csrc;
    bf16 *A1h, *A1l, *A2h, *A2l, *W1h, *W1l, *W2h, *W2l;
    cudaGetSymbolAddress((void**)&Hbuf, g_H);
    cudaGetSymbolAddress((void**)&asrc, g_asrc);
    cudaGetSymbolAddress((void**)&adst, g_adst);
    cudaGetSymbolAddress((void**)&seedq, g_seedq);
    cudaGetSymbolAddress((void**)&seedk, g_seedk);
    cudaGetSymbolAddress((void**)&ask1m, g_ask1m);
    cudaGetSymbolAddress((void**)&adk1m, g_adk1m);
    cudaGetSymbolAddress((void**)&bk1m, g_bk1m);
    cudaGetSymbolAddress((void**)&ask2m, g_ask2m);
    cudaGetSymbolAddress((void**)&adk2m, g_adk2m);
    cudaGetSymbolAddress((void**)&bk2m, g_bk2m);
    cudaGetSymbolAddress((void**)&deg, g_deg);
    cudaGetSymbolAddress((void**)&off, g_off);
    cudaGetSymbolAddress((void**)&cur, g_cur);
    cudaGetSymbolAddress((void**)&csrc, g_csrc);
    cudaGetSymbolAddress((void**)&A1h, g_A1h);
    cudaGetSymbolAddress((void**)&A1l, g_A1l);
    cudaGetSymbolAddress((void**)&A2h, g_A2h);
    cudaGetSymbolAddress((void**)&A2l, g_A2l);
    cudaGetSymbolAddress((void**)&W1h, g_W1h);
    cudaGetSymbolAddress((void**)&W1l, g_W1l);
    cudaGetSymbolAddress((void**)&W2h, g_W2h);
    cudaGetSymbolAddress((void**)&W2l, g_W2l);

    cudaFuncSetAttribute(gemm_wmma_split_kernel,
                         cudaFuncAttributeMaxDynamicSharedMemorySize, SMEM_GEMM_BYTES);

    const size_t a1slot = (size_t)Mp * Kp1;
    const size_t a2slot = (size_t)MPAD * F512;
    const size_t hslot  = (size_t)MPAD * F512;
    const size_t w1slot = (size_t)Kp1 * F512;
    const size_t w2slot = (size_t)F512 * F512;
    float* aggr2 = (float*)A1h;                 // reuse layer-1 A buffer
    const size_t aggr2slot = (size_t)NMAX * F512;

    long totA1 = (long)Mp * Kp1;
    long wtot = 2 * (long)w1slot + 2 * (long)w2slot;

    // 1) input split (batched q/k)
    split_pad2_kernel<<<dim3((unsigned)((totA1 + 255) / 256), 2), 256>>>(
        im_q, im_k, N, G, Kp1, totA1, A1h, A1l);
    // 2) all weight splits
    wsplit_all_kernel<<<(int)((wtot + 255) / 256), 256>>>(
        Wq1, Wk1, Wq2, Wk2, G, Kp1, W1h, W1l, W2h, W2l);
    // 3) layer-1 GEMM (batched)
    {
        dim3 grid(F512 / BN, Mp / BM, 2);
        gemm_wmma_split_kernel<<<grid, 256, SMEM_GEMM_BYTES>>>(
            Kp1, F512, A1h, A1l, W1h, W1l, Hbuf, a1slot, w1slot, hslot);
    }
    // 4) misc prep
    misc_prep_kernel<<<(2 * N + 2688 + 255) / 256, 256>>>(
        N, deg, cur,
        ask1, asq1, adk1, adq1, bk1, bq1,
        ask2, asq2, adk2, adq2, bk2, bq2,
        ask1m, adk1m, bk1m, ask2m, adk2m, bk2m);
    // 5-7) CSR
    csr_count_kernel<<<(ET + 255) / 256, 256>>>(ei, E, N, deg);
    csr_scan_kernel<<<1, 1024>>>(deg, off, N);
    csr_fill_kernel<<<(ET + 255) / 256, 256>>>(ei, E, N, off, cur, csrc);
    // 8-9) layer-1 attention -> bf16 A2 (pad rows stay zero from init)
    att_scores_kernel<<<dim3(N, 2), dim3(32, 4)>>>(Hbuf, hslot, asq1, adq1, ask1m, adk1m,
                                                   asrc, adst, N);
    gat_attn_kernel<<<dim3(N, 2), 256>>>(Hbuf, hslot, (const float4*)asrc,
                                         (const float4*)adst, off, deg, csrc,
                                         bq1, bk1m, A2h, A2l, nullptr, 0, a2slot);
    // 10) layer-2 GEMM (batched)
    {
        dim3 grid(F512 / BN, Mp / BM, 2);
        gemm_wmma_split_kernel<<<grid, 256, SMEM_GEMM_BYTES>>>(
            F512, F512, A2h, A2l, W2h, W2l, Hbuf, a2slot, w2slot, hslot);
    }
    // 11-12) layer-2 attention (dst < B only)
    att_scores_kernel<<<dim3(N, 2), dim3(32, 4)>>>(Hbuf, hslot, asq2, adq2, ask2m, adk2m,
                                                   asrc, adst, N);
    gat_attn_kernel<<<dim3(B, 2), 256>>>(Hbuf, hslot, (const float4*)asrc,
                                         (const float4*)adst, off, deg, csrc,
                                         nullptr, nullptr, nullptr, nullptr,
                                         aggr2, aggr2slot, 0);
    // 13) head-mean + l2norm
    head_mean_norm_kernel<<<dim3(B, 2), 128>>>(aggr2, aggr2slot, bq2, bk2m,
                                               seedq, seedk, B);
    // 14) logits
    {
        long written = (long)B * (R + 1);
        long tail = (long)out_size - written;
        if (tail < 0) tail = 0;
        dim3 grid((R + LT - 1) / LT, (B + LT - 1) / LT);
        logits_gemm_kernel<<<grid, 256>>>(seedq, seedk, queue, (float*)d_out,
                                          B, R, written, tail);
    }
}

// round 10
// speedup vs baseline: 4.0464x; 1.0113x over previous
#include <cuda_runtime.h>
#include <cuda_bf16.h>
#include <mma.h>
#include <cstdint>

using namespace nvcuda;

// ---------------------------------------------------------------------------
// MoCoGraph: two 2-layer GAT encoders + MoCo logits.
// GEMMs: bf16 3-term split, pre-split operands, BK=64 cp.async double-buffer,
//        CTA 192x128 (432 CTAs = 2.92 waves), 384 threads / 12 warps
//        (3 warps per SMSP for latency hiding), warp tile 32x64.
// Attention: CSR gather, fused softmax+aggregate+bias/relu+bf16-split epilogue.
// Logits: smem-tiled fp32 GEMM.
// ---------------------------------------------------------------------------

#define NMAX   10240
#define MPAD   10368     // multiple of 192 >= N
#define ETMAX  180224
#define F512   512
#define C128   128
#define CAP    512
#define KPAD1  1024

typedef __nv_bfloat16 bf16;

// ------------------------- device scratch (no mallocs) ---------------------
__device__ float g_H   [2 * (size_t)MPAD * F512];
__device__ bf16  g_A1h [2 * (size_t)MPAD * KPAD1];
__device__ bf16  g_A1l [2 * (size_t)MPAD * KPAD1];
__device__ bf16  g_A2h [2 * (size_t)MPAD * F512];   // pad rows stay 0 (zero-init)
__device__ bf16  g_A2l [2 * (size_t)MPAD * F512];
__device__ bf16  g_W1h [2 * KPAD1 * F512], g_W1l[2 * KPAD1 * F512];
__device__ bf16  g_W2h [2 * F512 * F512],  g_W2l[2 * F512 * F512];
__device__ float g_asrc[2 * NMAX * 4];
__device__ float g_adst[2 * NMAX * 4];
__device__ float g_seedq[(size_t)NMAX * C128];
__device__ float g_seedk[(size_t)NMAX * C128];
__device__ float g_ask1m[F512], g_adk1m[F512], g_bk1m[F512];
__device__ float g_ask2m[F512], g_adk2m[F512], g_bk2m[C128];
__device__ int g_deg[NMAX];
__device__ int g_off[NMAX + 1];
__device__ int g_cur[NMAX];
__device__ int g_csrc[ETMAX];

// ------------------------------ helpers ------------------------------------
__device__ __forceinline__ uint32_t smem_u32(const void* p) {
    uint32_t a;
    asm("{ .reg .u64 t; cvta.to.shared.u64 t, %1; cvt.u32.u64 %0, t; }" : "=r"(a) : "l"(p));
    return a;
}
__device__ __forceinline__ void cp_async16(uint32_t s, const void* g) {
    asm volatile("cp.async.cg.shared.global [%0], [%1], 16;" :: "r"(s), "l"(g));
}
#define CP_COMMIT() asm volatile("cp.async.commit_group;" ::: "memory")
#define CP_WAIT(n)  asm volatile("cp.async.wait_group %0;" :: "n"(n) : "memory")

__device__ __forceinline__ void split2(float v, bf16& h, bf16& l) {
    h = __float2bfloat16(v);
    l = __float2bfloat16(v - __bfloat162float(h));
}

// ------------------------------ prep kernels -------------------------------
__global__ void split_pad2_kernel(const float* __restrict__ in0,
                                  const float* __restrict__ in1,
                                  int M, int K, int Kp, long total,
                                  bf16* __restrict__ hi, bf16* __restrict__ lo) {
    long idx = (long)blockIdx.x * blockDim.x + threadIdx.x;
    if (idx >= total) return;
    const float* in = blockIdx.y ? in1 : in0;
    size_t o = (size_t)blockIdx.y * total + idx;
    int r = (int)(idx / Kp), c = (int)(idx % Kp);
    float v = (r < M && c < K) ? in[(size_t)r * K + c] : 0.f;
    bf16 h, l; split2(v, h, l);
    hi[o] = h; lo[o] = l;
}

__global__ void wsplit_all_kernel(const float* __restrict__ Wq1,
                                  const float* __restrict__ Wk1,
                                  const float* __restrict__ Wq2,
                                  const float* __restrict__ Wk2,
                                  int G, int Kp1,
                                  bf16* __restrict__ W1h, bf16* __restrict__ W1l,
                                  bf16* __restrict__ W2h, bf16* __restrict__ W2l) {
    long idx = (long)blockIdx.x * blockDim.x + threadIdx.x;
    const long s1 = (long)Kp1 * F512;
    const long s2 = (long)F512 * F512;
    if (idx < 2 * s1) {
        int z = idx >= s1;
        long j = idx - (long)z * s1;
        int r = (int)(j / F512);
        float v = 0.f;
        if (r < G) v = z ? (0.99f * Wk1[j] + 0.01f * Wq1[j]) : Wq1[j];
        bf16 h, l; split2(v, h, l);
        W1h[idx] = h; W1l[idx] = l;
    } else if (idx < 2 * s1 + 2 * s2) {
        long j2 = idx - 2 * s1;
        int z = j2 >= s2;
        long j = j2 - (long)z * s2;
        float v = z ? (0.99f * Wk2[j] + 0.01f * Wq2[j]) : Wq2[j];
        bf16 h, l; split2(v, h, l);
        W2h[j2] = h; W2l[j2] = l;
    }
}

__global__ void misc_prep_kernel(int N,
                                 int* __restrict__ deg, int* __restrict__ cur,
                                 const float* ask1, const float* asq1,
                                 const float* adk1, const float* adq1,
                                 const float* bk1,  const float* bq1,
                                 const float* ask2, const float* asq2,
                                 const float* adk2, const float* adq2,
                                 const float* bk2,  const float* bq2,
                                 float* o1, float* o2, float* o3,
                                 float* o4, float* o5, float* o6) {
    int idx = blockIdx.x * blockDim.x + threadIdx.x;
    if (idx < N) { deg[idx] = 0; return; }
    if (idx < 2 * N) { cur[idx - N] = 0; return; }
    int j = idx - 2 * N;
    if (j < 512)       o1[j]        = 0.99f * ask1[j]        + 0.01f * asq1[j];
    else if (j < 1024) o2[j - 512]  = 0.99f * adk1[j - 512]  + 0.01f * adq1[j - 512];
    else if (j < 1536) o3[j - 1024] = 0.99f * bk1[j - 1024]  + 0.01f * bq1[j - 1024];
    else if (j < 2048) o4[j - 1536] = 0.99f * ask2[j - 1536] + 0.01f * asq2[j - 1536];
    else if (j < 2560) o5[j - 2048] = 0.99f * adk2[j - 2048] + 0.01f * adq2[j - 2048];
    else if (j < 2688) o6[j - 2560] = 0.99f * bk2[j - 2560]  + 0.01f * bq2[j - 2560];
}

// ------------------------------- CSR build ---------------------------------
__global__ void csr_count_kernel(const int* __restrict__ ei, int E, int N,
                                 int* __restrict__ deg) {
    int i = blockIdx.x * blockDim.x + threadIdx.x;
    int ET = E + N;
    if (i >= ET) return;
    int d = (i < E) ? ei[E + i] : (i - E);
    atomicAdd(&deg[d], 1);
}

__global__ void csr_scan_kernel(const int* __restrict__ deg,
                                int* __restrict__ off, int N) {
    __shared__ int sh[1024];
    __shared__ int carry;
    int t = threadIdx.x;
    if (t == 0) carry = 0;
    __syncthreads();
    for (int base = 0; base < N; base += 1024) {
        int v = (base + t < N) ? deg[base + t] : 0;
        sh[t] = v;
        __syncthreads();
        for (int o = 1; o < 1024; o <<= 1) {
            int x = (t >= o) ? sh[t - o] : 0;
            __syncthreads();
            sh[t] += x;
            __syncthreads();
        }
        int excl = sh[t] - v + carry;
        if (base + t < N) off[base + t] = excl;
        __syncthreads();
        if (t == 1023) carry += sh[1023];
        __syncthreads();
    }
    if (t == 0) off[N] = carry;
}

__global__ void csr_fill_kernel(const int* __restrict__ ei, int E, int N,
                                const int* __restrict__ off,
                                int* __restrict__ cur,
                                int* __restrict__ csrc) {
    int i = blockIdx.x * blockDim.x + threadIdx.x;
    int ET = E + N;
    if (i >= ET) return;
    int s, d;
    if (i < E) { s = ei[i]; d = ei[E + i]; } else { s = d = i - E; }
    int pos = atomicAdd(&cur[d], 1);
    csrc[off[d] + pos] = s;
}

// ------ batched wmma GEMM: CTA 192x128, 12 warps, warp 32x64, BK=64 --------
#define BM 192
#define BN 128
#define BK 64
#define TGEMM 384
#define A_LD 72
#define B_LD 136
#define A_TILE_B 27648u      // 192*72*2
#define B_TILE_B 17408u      // 64*136*2
#define ST_AH 0u
#define ST_AL A_TILE_B
#define ST_BH (2u * A_TILE_B)
#define ST_BL (2u * A_TILE_B + B_TILE_B)
#define STAGE_B (2u * A_TILE_B + 2u * B_TILE_B)   // 90112
#define SMEM_GEMM_BYTES (2 * STAGE_B)             // 180224

__global__ void __launch_bounds__(TGEMM, 1)
gemm_wmma_split_kernel(int K, int Nn,
                       const bf16* __restrict__ Ahg0, const bf16* __restrict__ Alg0,
                       const bf16* __restrict__ Bhg0, const bf16* __restrict__ Blg0,
                       float* __restrict__ C0,
                       size_t strideA, size_t strideB, size_t strideC) {
    extern __shared__ char smem[];
    const uint32_t sb = smem_u32(smem);
    const int tid = threadIdx.x;
    const int bn = blockIdx.x, bm = blockIdx.y;
    const size_t z = blockIdx.z;
    const bf16* Ahg = Ahg0 + z * strideA;
    const bf16* Alg = Alg0 + z * strideA;
    const bf16* Bhg = Bhg0 + z * strideB;
    const bf16* Blg = Blg0 + z * strideB;
    float* C = C0 + z * strideC;

    const int warpId = tid >> 5;          // 0..11
    const int wm = warpId % 6;            // 6 row groups of 32
    const int wn = warpId / 6;             // 2 col groups of 64
    const int nk = K >> 6;

    const size_t aBase = (size_t)(bm * BM);
    const int cCol = bn * BN;

    auto load_stage = [&](int kt, uint32_t stg) {
        // A: 192 rows x 8 segs -> 1536 chunk-ids, 4 iters x 384 threads
#pragma unroll
        for (int i = 0; i < 4; i++) {
            int idx = tid + i * TGEMM;
            int ar = idx >> 3, as = (idx & 7) << 3;
            const size_t ago = (aBase + ar) * K + kt * BK + as;
            uint32_t aso = (uint32_t)(ar * A_LD + as) * 2;
            cp_async16(sb + stg + ST_AH + aso, Ahg + ago);
            cp_async16(sb + stg + ST_AL + aso, Alg + ago);
        }
        // B: 64 rows x 16 segs -> 1024 chunk-ids, 3 guarded iters
#pragma unroll
        for (int i = 0; i < 3; i++) {
            int idx = tid + i * TGEMM;
            if (idx < 1024) {
                int br = idx >> 4, bs = (idx & 15) << 3;
                const size_t bgo = (size_t)(kt * BK + br) * Nn + cCol + bs;
                uint32_t bso = (uint32_t)(br * B_LD + bs) * 2;
                cp_async16(sb + stg + ST_BH + bso, Bhg + bgo);
                cp_async16(sb + stg + ST_BL + bso, Blg + bgo);
            }
        }
        CP_COMMIT();
    };

    wmma::fragment<wmma::accumulator, 16, 16, 16, float> acc[2][4];
#pragma unroll
    for (int i = 0; i < 2; i++)
#pragma unroll
        for (int j = 0; j < 4; j++) wmma::fill_fragment(acc[i][j], 0.0f);

    load_stage(0, 0);

    for (int kt = 0; kt < nk; kt++) {
        const uint32_t stg = (kt & 1) ? STAGE_B : 0u;
        if (kt + 1 < nk) {
            load_stage(kt + 1, (kt & 1) ? 0u : STAGE_B);
            CP_WAIT(1);
        } else {
            CP_WAIT(0);
        }
        __syncthreads();

        const bf16* sAh = (const bf16*)(smem + stg + ST_AH);
        const bf16* sAl = (const bf16*)(smem + stg + ST_AL);
        const bf16* sBh = (const bf16*)(smem + stg + ST_BH);
        const bf16* sBl = (const bf16*)(smem + stg + ST_BL);

#pragma unroll
        for (int kk = 0; kk < BK; kk += 16) {
            wmma::fragment<wmma::matrix_a, 16, 16, 16, bf16, wmma::row_major> ah[2], al[2];
#pragma unroll
            for (int i = 0; i < 2; i++) {
                wmma::load_matrix_sync(ah[i], sAh + (wm * 32 + i * 16) * A_LD + kk, A_LD);
                wmma::load_matrix_sync(al[i], sAl + (wm * 32 + i * 16) * A_LD + kk, A_LD);
            }
#pragma unroll
            for (int j = 0; j < 4; j++) {
                wmma::fragment<wmma::matrix_b, 16, 16, 16, bf16, wmma::row_major> bh, bl;
                wmma::load_matrix_sync(bh, sBh + kk * B_LD + wn * 64 + j * 16, B_LD);
                wmma::load_matrix_sync(bl, sBl + kk * B_LD + wn * 64 + j * 16, B_LD);
#pragma unroll
                for (int i = 0; i < 2; i++) {
                    wmma::mma_sync(acc[i][j], ah[i], bh, acc[i][j]);
                    wmma::mma_sync(acc[i][j], ah[i], bl, acc[i][j]);
                    wmma::mma_sync(acc[i][j], al[i], bh, acc[i][j]);
                }
            }
        }
        __syncthreads();
    }

#pragma unroll
    for (int i = 0; i < 2; i++) {
        int row = bm * BM + wm * 32 + i * 16;
#pragma unroll
        for (int j = 0; j < 4; j++) {
            int col = cCol + wn * 64 + j * 16;
            wmma::store_matrix_sync(&C[(size_t)row * Nn + col], acc[i][j],
                                    Nn, wmma::mem_row_major);
        }
    }
}

// ---------------------------- attention scores (batched) -------------------
__global__ void att_scores_kernel(const float* __restrict__ Hbase, size_t hstride,
                                  const float* __restrict__ s0, const float* __restrict__ d0,
                                  const float* __restrict__ s1, const float* __restrict__ d1,
                                  float* __restrict__ a_s_base,
                                  float* __restrict__ a_d_base, int N) {
    int n = blockIdx.x;
    if (n >= N) return;
    int z = blockIdx.y;
    const float* Hf = Hbase + (size_t)z * hstride;
    const float* att_s = z ? s1 : s0;
    const float* att_d = z ? d1 : d0;
    float* a_s = a_s_base + (size_t)z * NMAX * 4;
    float* a_d = a_d_base + (size_t)z * NMAX * 4;

    int h = threadIdx.y;
    int lane = threadIdx.x;
    const float* row = Hf + (size_t)n * F512 + h * C128;
    float ss = 0.f, sd = 0.f;
#pragma unroll
    for (int j = 0; j < 4; j++) {
        int c = lane + 32 * j;
        float v = row[c];
        ss += v * att_s[h * C128 + c];
        sd += v * att_d[h * C128 + c];
    }
#pragma unroll
    for (int o = 16; o > 0; o >>= 1) {
        ss += __shfl_down_sync(0xffffffffu, ss, o);
        sd += __shfl_down_sync(0xffffffffu, sd, o);
    }
    if (lane == 0) { a_s[n * 4 + h] = ss; a_d[n * 4 + h] = sd; }
}

// ---------------- fused per-dst softmax + aggregation (batched) ------------
__device__ __forceinline__ float leaky(float e) { return e > 0.f ? e : 0.2f * e; }

__global__ __launch_bounds__(256)
void gat_attn_kernel(const float* __restrict__ Hbase, size_t hstride,
                     const float4* __restrict__ a_s_base,
                     const float4* __restrict__ a_d_base,
                     const int* __restrict__ off,
                     const int* __restrict__ deg_arr,
                     const int* __restrict__ csrc,
                     const float* __restrict__ bias0,
                     const float* __restrict__ bias1,
                     bf16* __restrict__ outh, bf16* __restrict__ outl,
                     float* __restrict__ outf, size_t ostride,
                     size_t oslot) {
    int d = blockIdx.x;
    int z = blockIdx.y;
    int t = threadIdx.x;
    int lane = t & 31, wid = t >> 5;

    const float* Hf = Hbase + (size_t)z * hstride;
    const float4* a_s4 = a_s_base + (size_t)z * NMAX;
    const float4* a_d4 = a_d_base + (size_t)z * NMAX;
    const float* bias = z ? bias1 : bias0;

    __shared__ int   s_list[CAP];
    __shared__ float w[CAP][4];
    __shared__ float red[8][4];
    __shared__ float mx_s[4], invd_s[4];

    const int start = off[d];
    const int deg = deg_arr[d];
    const float4 ad = a_d4[d];

    float m0 = -1e30f, m1 = -1e30f, m2 = -1e30f, m3 = -1e30f;
    for (int j = t; j < deg; j += 256) {
        int s = csrc[start + j];
        float4 as = a_s4[s];
        float e0 = leaky(as.x + ad.x);
        float e1 = leaky(as.y + ad.y);
        float e2 = leaky(as.z + ad.z);
        float e3 = leaky(as.w + ad.w);
        if (j < CAP) {
            s_list[j] = s;
            w[j][0] = e0; w[j][1] = e1; w[j][2] = e2; w[j][3] = e3;
        }
        m0 = fmaxf(m0, e0); m1 = fmaxf(m1, e1);
        m2 = fmaxf(m2, e2); m3 = fmaxf(m3, e3);
    }
#pragma unroll
    for (int o = 16; o > 0; o >>= 1) {
        m0 = fmaxf(m0, __shfl_xor_sync(0xffffffffu, m0, o));
        m1 = fmaxf(m1, __shfl_xor_sync(0xffffffffu, m1, o));
        m2 = fmaxf(m2, __shfl_xor_sync(0xffffffffu, m2, o));
        m3 = fmaxf(m3, __shfl_xor_sync(0xffffffffu, m3, o));
    }
    if (lane == 0) { red[wid][0] = m0; red[wid][1] = m1; red[wid][2] = m2; red[wid][3] = m3; }
    __syncthreads();
    if (t < 4) {
        float mm = -1e30f;
#pragma unroll
        for (int k = 0; k < 8; k++) mm = fmaxf(mm, red[k][t]);
        mx_s[t] = mm;
    }
    __syncthreads();
    const float mx0 = mx_s[0], mx1 = mx_s[1], mx2 = mx_s[2], mx3 = mx_s[3];

    float s0 = 0.f, s1 = 0.f, s2 = 0.f, s3 = 0.f;
    for (int j = t; j < deg; j += 256) {
        float e0, e1, e2, e3;
        if (j < CAP) {
            e0 = w[j][0]; e1 = w[j][1]; e2 = w[j][2]; e3 = w[j][3];
        } else {
            int s = csrc[start + j];
            float4 as = a_s4[s];
            e0 = leaky(as.x + ad.x); e1 = leaky(as.y + ad.y);
            e2 = leaky(as.z + ad.z); e3 = leaky(as.w + ad.w);
        }
        float x0 = expf(e0 - mx0), x1 = expf(e1 - mx1);
        float x2 = expf(e2 - mx2), x3 = expf(e3 - mx3);
        if (j < CAP) { w[j][0] = x0; w[j][1] = x1; w[j][2] = x2; w[j][3] = x3; }
        s0 += x0; s1 += x1; s2 += x2; s3 += x3;
    }
#pragma unroll
    for (int o = 16; o > 0; o >>= 1) {
        s0 += __shfl_xor_sync(0xffffffffu, s0, o);
        s1 += __shfl_xor_sync(0xffffffffu, s1, o);
        s2 += __shfl_xor_sync(0xffffffffu, s2, o);
        s3 += __shfl_xor_sync(0xffffffffu, s3, o);
    }
    __syncthreads();
    if (lane == 0) { red[wid][0] = s0; red[wid][1] = s1; red[wid][2] = s2; red[wid][3] = s3; }
    __syncthreads();
    if (t < 4) {
        float ssum = 0.f;
#pragma unroll
        for (int k = 0; k < 8; k++) ssum += red[k][t];
        invd_s[t] = 1.0f / (ssum + 1e-16f);
    }
    __syncthreads();

    const int c2 = t * 2;
    const int h = c2 >> 7;
    const float inv = invd_s[h];
    const float mxh = mx_s[h];
    float acc0 = 0.f, acc1 = 0.f;
    for (int j = 0; j < deg; j++) {
        int s;
        float ww;
        if (j < CAP) {
            s = s_list[j];
            ww = w[j][h];
        } else {
            s = csrc[start + j];
            const float* asp = (const float*)&a_s4[s];
            const float* adp = (const float*)&ad;
            ww = expf(leaky(asp[h] + adp[h]) - mxh);
        }
        float alpha = ww * inv;
        float2 v = *(const float2*)(Hf + (size_t)s * F512 + c2);
        acc0 += v.x * alpha;
        acc1 += v.y * alpha;
    }
    if (outh) {
        acc0 = fmaxf(acc0 + bias[c2], 0.f);
        acc1 = fmaxf(acc1 + bias[c2 + 1], 0.f);
        bf16 h0, l0, h1, l1;
        split2(acc0, h0, l0);
        split2(acc1, h1, l1);
        size_t o = (size_t)z * oslot + (size_t)d * F512 + c2;
        *(uint32_t*)(outh + o) = (uint32_t)__bfloat16_as_ushort(h0) |
                                 ((uint32_t)__bfloat16_as_ushort(h1) << 16);
        *(uint32_t*)(outl + o) = (uint32_t)__bfloat16_as_ushort(l0) |
                                 ((uint32_t)__bfloat16_as_ushort(l1) << 16);
    } else {
        size_t o = (size_t)z * ostride + (size_t)d * F512 + c2;
        *(float2*)(outf + o) = make_float2(acc0, acc1);
    }
}

// layer-2 epilogue (batched)
__global__ void head_mean_norm_kernel(const float* __restrict__ aggr_base, size_t astride,
                                      const float* __restrict__ bias0,
                                      const float* __restrict__ bias1,
                                      float* __restrict__ outq,
                                      float* __restrict__ outk, int B) {
    int n = blockIdx.x;
    if (n >= B) return;
    int z = blockIdx.y;
    const float* aggr = aggr_base + (size_t)z * astride;
    const float* bias = z ? bias1 : bias0;
    float* outv = z ? outk : outq;
    int c = threadIdx.x;
    size_t base = (size_t)n * F512;
    float v = 0.25f * (aggr[base + c] + aggr[base + 128 + c] +
                       aggr[base + 256 + c] + aggr[base + 384 + c]) + bias[c];
    float s = v * v;
#pragma unroll
    for (int o = 16; o > 0; o >>= 1) s += __shfl_down_sync(0xffffffffu, s, o);
    __shared__ float red[4];
    if ((c & 31) == 0) red[c >> 5] = s;
    __syncthreads();
    float tot = red[0] + red[1] + red[2] + red[3];
    outv[(size_t)n * C128 + c] = v * rsqrtf(tot + 1e-24f);
}

// ---------------- logits: tiled fp32 GEMM out[B,1+R] ------------------------
#define LT 64
__global__ __launch_bounds__(256)
void logits_gemm_kernel(const float* __restrict__ q,
                        const float* __restrict__ kv,
                        const float* __restrict__ queue,
                        float* __restrict__ out, int B, int R,
                        long tail_off, long tail_len) {
    __shared__ float qt[LT][33];
    __shared__ float kt[32][LT + 4];
    const int tid = threadIdx.x;
    const int bx = blockIdx.x, by = blockIdx.y;
    const int tx = tid & 15, ty = tid >> 4;

    float acc[4][4];
#pragma unroll
    for (int i = 0; i < 4; i++)
#pragma unroll
        for (int j = 0; j < 4; j++) acc[i][j] = 0.f;

    for (int k0 = 0; k0 < 128; k0 += 32) {
#pragma unroll
        for (int i = 0; i < 8; i++) {
            int e = tid + i * 256;
            int r = e >> 5, c = e & 31;
            int gr = by * LT + r;
            qt[r][c] = (gr < B) ? q[(size_t)gr * 128 + k0 + c] : 0.f;
        }
#pragma unroll
        for (int i = 0; i < 8; i++) {
            int e = tid + i * 256;
            int r = e >> 6, c = e & 63;
            int gc = bx * LT + c;
            kt[r][c] = (gc < R) ? queue[(size_t)(k0 + r) * R + gc] : 0.f;
        }
        __syncthreads();
#pragma unroll
        for (int k = 0; k < 32; k++) {
            float ra[4], rb[4];
#pragma unroll
            for (int i = 0; i < 4; i++) ra[i] = qt[ty * 4 + i][k];
#pragma unroll
            for (int j = 0; j < 4; j++) rb[j] = kt[k][tx * 4 + j];
#pragma unroll
            for (int i = 0; i < 4; i++)
#pragma unroll
                for (int j = 0; j < 4; j++) acc[i][j] += ra[i] * rb[j];
        }
        __syncthreads();
    }

#pragma unroll
    for (int i = 0; i < 4; i++) {
        int row = by * LT + ty * 4 + i;
        if (row >= B) continue;
#pragma unroll
        for (int j = 0; j < 4; j++) {
            int col = bx * LT + tx * 4 + j;
            if (col < R)
                out[(size_t)row * (R + 1) + 1 + col] = acc[i][j] * 5.0f;
        }
    }

    if (bx == 0 && tid < LT) {
        int n = by * LT + tid;
        if (n < B) {
            const float* qr = q + (size_t)n * 128;
            const float* kr = kv + (size_t)n * 128;
            float s = 0.f;
#pragma unroll 4
            for (int c = 0; c < 128; c++) s += qr[c] * kr[c];
            out[(size_t)n * (R + 1)] = s * 5.0f;
        }
    }
    if (bx == 0 && by == 0) {
        for (long i = tid; i < tail_len; i += 256) out[tail_off + i] = 0.f;
    }
}

// ------------------------------- launch ------------------------------------
extern "C" void kernel_launch(void* const* d_in, const int* in_sizes, int n_in,
                              void* d_out, int out_size) {
    int base = n_in - 17;

    const float* im_q = (const float*)d_in[0];
    const float* im_k = (const float*)d_in[1];
    const int*   ei   = (const int*)d_in[2];

    const float* Wq1  = (const float*)d_in[base + 0];
    const float* asq1 = (const float*)d_in[base + 1];
    const float* adq1 = (const float*)d_in[base + 2];
    const float* bq1  = (const float*)d_in[base + 3];
    const float* Wq2  = (const float*)d_in[base + 4];
    const float* asq2 = (const float*)d_in[base + 5];
    const float* adq2 = (const float*)d_in[base + 6];
    const float* bq2  = (const float*)d_in[base + 7];
    const float* Wk1  = (const float*)d_in[base + 8];
    const float* ask1 = (const float*)d_in[base + 9];
    const float* adk1 = (const float*)d_in[base + 10];
    const float* bk1  = (const float*)d_in[base + 11];
    const float* Wk2  = (const float*)d_in[base + 12];
    const float* ask2 = (const float*)d_in[base + 13];
    const float* adk2 = (const float*)d_in[base + 14];
    const float* bk2  = (const float*)d_in[base + 15];
    const float* queue= (const float*)d_in[base + 16];

    int G = in_sizes[base] / F512;
    int N = in_sizes[0] / G;
    int E = in_sizes[2] / 2;
    int R = in_sizes[base + 16] / C128;
    int B = (out_size % (R + 2) == 0) ? out_size / (R + 2) : out_size / (R + 1);
    if (B > N) B = N;
    int ET = E + N;
    int Mp = (N + BM - 1) / BM * BM;
    if (Mp > MPAD) Mp = MPAD;
    int Kp1 = (G + 63) & ~63;

    float *Hbuf, *asrc, *adst, *seedq, *seedk;
    float *ask1m, *adk1m, *bk1m, *ask2m, *adk2m, *bk2m;
    int *deg, *off, *cur, *csrc;
    bf16 *A1h, *A1l, *A2h, *A2l, *W1h, *W1l, *W2h, *W2l;
    cudaGetSymbolAddress((void**)&Hbuf, g_H);
    cudaGetSymbolAddress((void**)&asrc, g_asrc);
    cudaGetSymbolAddress((void**)&adst, g_adst);
    cudaGetSymbolAddress((void**)&seedq, g_seedq);
    cudaGetSymbolAddress((void**)&seedk, g_seedk);
    cudaGetSymbolAddress((void**)&ask1m, g_ask1m);
    cudaGetSymbolAddress((void**)&adk1m, g_adk1m);
    cudaGetSymbolAddress((void**)&bk1m, g_bk1m);
    cudaGetSymbolAddress((void**)&ask2m, g_ask2m);
    cudaGetSymbolAddress((void**)&adk2m, g_adk2m);
    cudaGetSymbolAddress((void**)&bk2m, g_bk2m);
    cudaGetSymbolAddress((void**)&deg, g_deg);
    cudaGetSymbolAddress((void**)&off, g_off);
    cudaGetSymbolAddress((void**)&cur, g_cur);
    cudaGetSymbolAddress((void**)&csrc, g_csrc);
    cudaGetSymbolAddress((void**)&A1h, g_A1h);
    cudaGetSymbolAddress((void**)&A1l, g_A1l);
    cudaGetSymbolAddress((void**)&A2h, g_A2h);
    cudaGetSymbolAddress((void**)&A2l, g_A2l);
    cudaGetSymbolAddress((void**)&W1h, g_W1h);
    cudaGetSymbolAddress((void**)&W1l, g_W1l);
    cudaGetSymbolAddress((void**)&W2h, g_W2h);
    cudaGetSymbolAddress((void**)&W2l, g_W2l);

    cudaFuncSetAttribute(gemm_wmma_split_kernel,
                         cudaFuncAttributeMaxDynamicSharedMemorySize, SMEM_GEMM_BYTES);

    const size_t a1slot = (size_t)Mp * Kp1;
    const size_t a2slot = (size_t)MPAD * F512;
    const size_t hslot  = (size_t)MPAD * F512;
    const size_t w1slot = (size_t)Kp1 * F512;
    const size_t w2slot = (size_t)F512 * F512;
    float* aggr2 = (float*)A1h;                 // reuse layer-1 A buffer
    const size_t aggr2slot = (size_t)NMAX * F512;

    long totA1 = (long)Mp * Kp1;
    long wtot = 2 * (long)w1slot + 2 * (long)w2slot;

    // 1) input split (batched q/k)
    split_pad2_kernel<<<dim3((unsigned)((totA1 + 255) / 256), 2), 256>>>(
        im_q, im_k, N, G, Kp1, totA1, A1h, A1l);
    // 2) all weight splits
    wsplit_all_kernel<<<(int)((wtot + 255) / 256), 256>>>(
        Wq1, Wk1, Wq2, Wk2, G, Kp1, W1h, W1l, W2h, W2l);
    // 3) layer-1 GEMM (batched)
    {
        dim3 grid(F512 / BN, Mp / BM, 2);
        gemm_wmma_split_kernel<<<grid, TGEMM, SMEM_GEMM_BYTES>>>(
            Kp1, F512, A1h, A1l, W1h, W1l, Hbuf, a1slot, w1slot, hslot);
    }
    // 4) misc prep
    misc_prep_kernel<<<(2 * N + 2688 + 255) / 256, 256>>>(
        N, deg, cur,
        ask1, asq1, adk1, adq1, bk1, bq1,
        ask2, asq2, adk2, adq2, bk2, bq2,
        ask1m, adk1m, bk1m, ask2m, adk2m, bk2m);
    // 5-7) CSR
    csr_count_kernel<<<(ET + 255) / 256, 256>>>(ei, E, N, deg);
    csr_scan_kernel<<<1, 1024>>>(deg, off, N);
    csr_fill_kernel<<<(ET + 255) / 256, 256>>>(ei, E, N, off, cur, csrc);
    // 8-9) layer-1 attention -> bf16 A2 (pad rows stay zero from init)
    att_scores_kernel<<<dim3(N, 2), dim3(32, 4)>>>(Hbuf, hslot, asq1, adq1, ask1m, adk1m,
                                                   asrc, adst, N);
    gat_attn_kernel<<<dim3(N, 2), 256>>>(Hbuf, hslot, (const float4*)asrc,
                                         (const float4*)adst, off, deg, csrc,
                                         bq1, bk1m, A2h, A2l, nullptr, 0, a2slot);
    // 10) layer-2 GEMM (batched)
    {
        dim3 grid(F512 / BN, Mp / BM, 2);
        gemm_wmma_split_kernel<<<grid, TGEMM, SMEM_GEMM_BYTES>>>(
            F512, F512, A2h, A2l, W2h, W2l, Hbuf, a2slot, w2slot, hslot);
    }
    // 11-12) layer-2 attention (dst < B only)
    att_scores_kernel<<<dim3(N, 2), dim3(32, 4)>>>(Hbuf, hslot, asq2, adq2, ask2m, adk2m,
                                                   asrc, adst, N);
    gat_attn_kernel<<<dim3(B, 2), 256>>>(Hbuf, hslot, (const float4*)asrc,
                                         (const float4*)adst, off, deg, csrc,
                                         nullptr, nullptr, nullptr, nullptr,
                                         aggr2, aggr2slot, 0);
    // 13) head-mean + l2norm
    head_mean_norm_kernel<<<dim3(B, 2), 128>>>(aggr2, aggr2slot, bq2, bk2m,
                                               seedq, seedk, B);
    // 14) logits
    {
        long written = (long)B * (R + 1);
        long tail = (long)out_size - written;
        if (tail < 0) tail = 0;
        dim3 grid((R + LT - 1) / LT, (B + LT - 1) / LT);
        logits_gemm_kernel<<<grid, 256>>>(seedq, seedk, queue, (float*)d_out,
                                          B, R, written, tail);
    }
}

// round 11
// speedup vs baseline: 5.7735x; 1.4268x over previous
#include <cuda_runtime.h>
#include <cuda_fp16.h>
#include <mma.h>
#include <cstdint>

using namespace nvcuda;

// ---------------------------------------------------------------------------
// MoCoGraph: two 2-layer GAT encoders + MoCo logits.
// GEMMs: fp16 single-pass wmma (fp32 accum), CTA 192x128, 12 warps,
//        BK=64 cp.async double-buffer, 2 CTAs/SM, batched encoders (grid.z=2).
// Attention: CSR gather, fused softmax+aggregate+bias/relu+fp16 epilogue.
// Logits: smem-tiled fp32 GEMM.
// ---------------------------------------------------------------------------

#define NMAX   10240
#define MPAD   10368     // multiple of 192 >= N
#define ETMAX  180224
#define F512   512
#define C128   128
#define CAP    512
#define KPAD1  1024

typedef __half hf;

// ------------------------- device scratch (no mallocs) ---------------------
__device__ float g_H  [2 * (size_t)MPAD * F512];
__device__ hf    g_A1 [2 * (size_t)MPAD * KPAD1];
__device__ hf    g_A2 [2 * (size_t)MPAD * F512];   // pad rows stay 0 (zero-init)
__device__ hf    g_W1 [2 * KPAD1 * F512];
__device__ hf    g_W2 [2 * F512 * F512];
__device__ float g_asrc[2 * NMAX * 4];
__device__ float g_adst[2 * NMAX * 4];
__device__ float g_seedq[(size_t)NMAX * C128];
__device__ float g_seedk[(size_t)NMAX * C128];
__device__ float g_ask1m[F512], g_adk1m[F512], g_bk1m[F512];
__device__ float g_ask2m[F512], g_adk2m[F512], g_bk2m[C128];
__device__ int g_deg[NMAX];
__device__ int g_off[NMAX + 1];
__device__ int g_cur[NMAX];
__device__ int g_csrc[ETMAX];
// fp32 scratch for layer-2 attention output (reuses nothing typed; own array)
__device__ float g_aggr2[2 * (size_t)NMAX * F512 / 4];   // only B rows used

// ------------------------------ helpers ------------------------------------
__device__ __forceinline__ uint32_t smem_u32(const void* p) {
    uint32_t a;
    asm("{ .reg .u64 t; cvta.to.shared.u64 t, %1; cvt.u32.u64 %0, t; }" : "=r"(a) : "l"(p));
    return a;
}
__device__ __forceinline__ void cp_async16(uint32_t s, const void* g) {
    asm volatile("cp.async.cg.shared.global [%0], [%1], 16;" :: "r"(s), "l"(g));
}
#define CP_COMMIT() asm volatile("cp.async.commit_group;" ::: "memory")
#define CP_WAIT(n)  asm volatile("cp.async.wait_group %0;" :: "n"(n) : "memory")

// ------------------------------ prep kernels -------------------------------
// batched input convert: z=0 -> in0, z=1 -> in1; out slot stride = total
__global__ void conv_pad2_kernel(const float* __restrict__ in0,
                                 const float* __restrict__ in1,
                                 int M, int K, int Kp, long total,
                                 hf* __restrict__ out) {
    long idx = (long)blockIdx.x * blockDim.x + threadIdx.x;
    if (idx >= total) return;
    const float* in = blockIdx.y ? in1 : in0;
    size_t o = (size_t)blockIdx.y * total + idx;
    int r = (int)(idx / Kp), c = (int)(idx % Kp);
    float v = (r < M && c < K) ? in[(size_t)r * K + c] : 0.f;
    out[o] = __float2half_rn(v);
}

// all 4 weight converts (q/k x layer1/layer2) in one launch
__global__ void wconv_all_kernel(const float* __restrict__ Wq1,
                                 const float* __restrict__ Wk1,
                                 const float* __restrict__ Wq2,
                                 const float* __restrict__ Wk2,
                                 int G, int Kp1,
                                 hf* __restrict__ W1, hf* __restrict__ W2) {
    long idx = (long)blockIdx.x * blockDim.x + threadIdx.x;
    const long s1 = (long)Kp1 * F512;
    const long s2 = (long)F512 * F512;
    if (idx < 2 * s1) {
        int z = idx >= s1;
        long j = idx - (long)z * s1;
        int r = (int)(j / F512);
        float v = 0.f;
        if (r < G) v = z ? (0.99f * Wk1[j] + 0.01f * Wq1[j]) : Wq1[j];
        W1[idx] = __float2half_rn(v);
    } else if (idx < 2 * s1 + 2 * s2) {
        long j2 = idx - 2 * s1;
        int z = j2 >= s2;
        long j = j2 - (long)z * s2;
        float v = z ? (0.99f * Wk2[j] + 0.01f * Wq2[j]) : Wq2[j];
        W2[j2] = __float2half_rn(v);
    }
}

__global__ void misc_prep_kernel(int N,
                                 int* __restrict__ deg, int* __restrict__ cur,
                                 const float* ask1, const float* asq1,
                                 const float* adk1, const float* adq1,
                                 const float* bk1,  const float* bq1,
                                 const float* ask2, const float* asq2,
                                 const float* adk2, const float* adq2,
                                 const float* bk2,  const float* bq2,
                                 float* o1, float* o2, float* o3,
                                 float* o4, float* o5, float* o6) {
    int idx = blockIdx.x * blockDim.x + threadIdx.x;
    if (idx < N) { deg[idx] = 0; return; }
    if (idx < 2 * N) { cur[idx - N] = 0; return; }
    int j = idx - 2 * N;
    if (j < 512)       o1[j]        = 0.99f * ask1[j]        + 0.01f * asq1[j];
    else if (j < 1024) o2[j - 512]  = 0.99f * adk1[j - 512]  + 0.01f * adq1[j - 512];
    else if (j < 1536) o3[j - 1024] = 0.99f * bk1[j - 1024]  + 0.01f * bq1[j - 1024];
    else if (j < 2048) o4[j - 1536] = 0.99f * ask2[j - 1536] + 0.01f * asq2[j - 1536];
    else if (j < 2560) o5[j - 2048] = 0.99f * adk2[j - 2048] + 0.01f * adq2[j - 2048];
    else if (j < 2688) o6[j - 2560] = 0.99f * bk2[j - 2560]  + 0.01f * bq2[j - 2560];
}

// ------------------------------- CSR build ---------------------------------
__global__ void csr_count_kernel(const int* __restrict__ ei, int E, int N,
                                 int* __restrict__ deg) {
    int i = blockIdx.x * blockDim.x + threadIdx.x;
    int ET = E + N;
    if (i >= ET) return;
    int d = (i < E) ? ei[E + i] : (i - E);
    atomicAdd(&deg[d], 1);
}

__global__ void csr_scan_kernel(const int* __restrict__ deg,
                                int* __restrict__ off, int N) {
    __shared__ int sh[1024];
    __shared__ int carry;
    int t = threadIdx.x;
    if (t == 0) carry = 0;
    __syncthreads();
    for (int base = 0; base < N; base += 1024) {
        int v = (base + t < N) ? deg[base + t] : 0;
        sh[t] = v;
        __syncthreads();
        for (int o = 1; o < 1024; o <<= 1) {
            int x = (t >= o) ? sh[t - o] : 0;
            __syncthreads();
            sh[t] += x;
            __syncthreads();
        }
        int excl = sh[t] - v + carry;
        if (base + t < N) off[base + t] = excl;
        __syncthreads();
        if (t == 1023) carry += sh[1023];
        __syncthreads();
    }
    if (t == 0) off[N] = carry;
}

__global__ void csr_fill_kernel(const int* __restrict__ ei, int E, int N,
                                const int* __restrict__ off,
                                int* __restrict__ cur,
                                int* __restrict__ csrc) {
    int i = blockIdx.x * blockDim.x + threadIdx.x;
    int ET = E + N;
    if (i >= ET) return;
    int s, d;
    if (i < E) { s = ei[i]; d = ei[E + i]; } else { s = d = i - E; }
    int pos = atomicAdd(&cur[d], 1);
    csrc[off[d] + pos] = s;
}

// ------ batched fp16 wmma GEMM: CTA 192x128, 12 warps, warp 32x64, BK=64 ---
#define BM 192
#define BN 128
#define BK 64
#define TGEMM 384
#define A_LD 72
#define B_LD 136
#define A_TILE_B 27648u      // 192*72*2
#define B_TILE_B 17408u      // 64*136*2
#define ST_A 0u
#define ST_B A_TILE_B
#define STAGE_B (A_TILE_B + B_TILE_B)   // 45056
#define SMEM_GEMM_BYTES (2 * STAGE_B)   // 90112 -> 2 CTAs/SM

__global__ void __launch_bounds__(TGEMM, 2)
gemm_wmma_fp16_kernel(int K, int Nn,
                      const hf* __restrict__ Ag0, const hf* __restrict__ Bg0,
                      float* __restrict__ C0,
                      size_t strideA, size_t strideB, size_t strideC) {
    extern __shared__ char smem[];
    const uint32_t sb = smem_u32(smem);
    const int tid = threadIdx.x;
    const int bn = blockIdx.x, bm = blockIdx.y;
    const size_t z = blockIdx.z;
    const hf* Ag = Ag0 + z * strideA;
    const hf* Bg = Bg0 + z * strideB;
    float* C = C0 + z * strideC;

    const int warpId = tid >> 5;          // 0..11
    const int wm = warpId % 6;            // 6 row groups of 32
    const int wn = warpId / 6;            // 2 col groups of 64
    const int nk = K >> 6;

    const size_t aBase = (size_t)(bm * BM);
    const int cCol = bn * BN;

    auto load_stage = [&](int kt, uint32_t stg) {
        // A: 192 rows x 8 segs -> 1536 chunks, 4 iters x 384 threads
#pragma unroll
        for (int i = 0; i < 4; i++) {
            int idx = tid + i * TGEMM;
            int ar = idx >> 3, as = (idx & 7) << 3;
            cp_async16(sb + stg + ST_A + (uint32_t)(ar * A_LD + as) * 2,
                       Ag + (aBase + ar) * K + kt * BK + as);
        }
        // B: 64 rows x 16 segs -> 1024 chunks, 3 guarded iters
#pragma unroll
        for (int i = 0; i < 3; i++) {
            int idx = tid + i * TGEMM;
            if (idx < 1024) {
                int br = idx >> 4, bs = (idx & 15) << 3;
                cp_async16(sb + stg + ST_B + (uint32_t)(br * B_LD + bs) * 2,
                           Bg + (size_t)(kt * BK + br) * Nn + cCol + bs);
            }
        }
        CP_COMMIT();
    };

    wmma::fragment<wmma::accumulator, 16, 16, 16, float> acc[2][4];
#pragma unroll
    for (int i = 0; i < 2; i++)
#pragma unroll
        for (int j = 0; j < 4; j++) wmma::fill_fragment(acc[i][j], 0.0f);

    load_stage(0, 0);

    for (int kt = 0; kt < nk; kt++) {
        const uint32_t stg = (kt & 1) ? STAGE_B : 0u;
        if (kt + 1 < nk) {
            load_stage(kt + 1, (kt & 1) ? 0u : STAGE_B);
            CP_WAIT(1);
        } else {
            CP_WAIT(0);
        }
        __syncthreads();

        const hf* sA = (const hf*)(smem + stg + ST_A);
        const hf* sB = (const hf*)(smem + stg + ST_B);

#pragma unroll
        for (int kk = 0; kk < BK; kk += 16) {
            wmma::fragment<wmma::matrix_a, 16, 16, 16, hf, wmma::row_major> af[2];
#pragma unroll
            for (int i = 0; i < 2; i++)
                wmma::load_matrix_sync(af[i], sA + (wm * 32 + i * 16) * A_LD + kk, A_LD);
#pragma unroll
            for (int j = 0; j < 4; j++) {
                wmma::fragment<wmma::matrix_b, 16, 16, 16, hf, wmma::row_major> bf;
                wmma::load_matrix_sync(bf, sB + kk * B_LD + wn * 64 + j * 16, B_LD);
#pragma unroll
                for (int i = 0; i < 2; i++)
                    wmma::mma_sync(acc[i][j], af[i], bf, acc[i][j]);
            }
        }
        __syncthreads();
    }

#pragma unroll
    for (int i = 0; i < 2; i++) {
        int row = bm * BM + wm * 32 + i * 16;
#pragma unroll
        for (int j = 0; j < 4; j++) {
            int col = cCol + wn * 64 + j * 16;
            wmma::store_matrix_sync(&C[(size_t)row * Nn + col], acc[i][j],
                                    Nn, wmma::mem_row_major);
        }
    }
}

// ---------------------------- attention scores (batched) -------------------
__global__ void att_scores_kernel(const float* __restrict__ Hbase, size_t hstride,
                                  const float* __restrict__ s0, const float* __restrict__ d0,
                                  const float* __restrict__ s1, const float* __restrict__ d1,
                                  float* __restrict__ a_s_base,
                                  float* __restrict__ a_d_base, int N) {
    int n = blockIdx.x;
    if (n >= N) return;
    int z = blockIdx.y;
    const float* Hf = Hbase + (size_t)z * hstride;
    const float* att_s = z ? s1 : s0;
    const float* att_d = z ? d1 : d0;
    float* a_s = a_s_base + (size_t)z * NMAX * 4;
    float* a_d = a_d_base + (size_t)z * NMAX * 4;

    int h = threadIdx.y;
    int lane = threadIdx.x;
    const float* row = Hf + (size_t)n * F512 + h * C128;
    float ss = 0.f, sd = 0.f;
#pragma unroll
    for (int j = 0; j < 4; j++) {
        int c = lane + 32 * j;
        float v = row[c];
        ss += v * att_s[h * C128 + c];
        sd += v * att_d[h * C128 + c];
    }
#pragma unroll
    for (int o = 16; o > 0; o >>= 1) {
        ss += __shfl_down_sync(0xffffffffu, ss, o);
        sd += __shfl_down_sync(0xffffffffu, sd, o);
    }
    if (lane == 0) { a_s[n * 4 + h] = ss; a_d[n * 4 + h] = sd; }
}

// ---------------- fused per-dst softmax + aggregation (batched) ------------
__device__ __forceinline__ float leaky(float e) { return e > 0.f ? e : 0.2f * e; }

__global__ __launch_bounds__(256)
void gat_attn_kernel(const float* __restrict__ Hbase, size_t hstride,
                     const float4* __restrict__ a_s_base,
                     const float4* __restrict__ a_d_base,
                     const int* __restrict__ off,
                     const int* __restrict__ deg_arr,
                     const int* __restrict__ csrc,
                     const float* __restrict__ bias0,
                     const float* __restrict__ bias1,
                     hf* __restrict__ outh,
                     float* __restrict__ outf, size_t ostride,
                     size_t oslot) {
    int d = blockIdx.x;
    int z = blockIdx.y;
    int t = threadIdx.x;
    int lane = t & 31, wid = t >> 5;

    const float* Hf = Hbase + (size_t)z * hstride;
    const float4* a_s4 = a_s_base + (size_t)z * NMAX;
    const float4* a_d4 = a_d_base + (size_t)z * NMAX;
    const float* bias = z ? bias1 : bias0;

    __shared__ int   s_list[CAP];
    __shared__ float w[CAP][4];
    __shared__ float red[8][4];
    __shared__ float mx_s[4], invd_s[4];

    const int start = off[d];
    const int deg = deg_arr[d];
    const float4 ad = a_d4[d];

    float m0 = -1e30f, m1 = -1e30f, m2 = -1e30f, m3 = -1e30f;
    for (int j = t; j < deg; j += 256) {
        int s = csrc[start + j];
        float4 as = a_s4[s];
        float e0 = leaky(as.x + ad.x);
        float e1 = leaky(as.y + ad.y);
        float e2 = leaky(as.z + ad.z);
        float e3 = leaky(as.w + ad.w);
        if (j < CAP) {
            s_list[j] = s;
            w[j][0] = e0; w[j][1] = e1; w[j][2] = e2; w[j][3] = e3;
        }
        m0 = fmaxf(m0, e0); m1 = fmaxf(m1, e1);
        m2 = fmaxf(m2, e2); m3 = fmaxf(m3, e3);
    }
#pragma unroll
    for (int o = 16; o > 0; o >>= 1) {
        m0 = fmaxf(m0, __shfl_xor_sync(0xffffffffu, m0, o));
        m1 = fmaxf(m1, __shfl_xor_sync(0xffffffffu, m1, o));
        m2 = fmaxf(m2, __shfl_xor_sync(0xffffffffu, m2, o));
        m3 = fmaxf(m3, __shfl_xor_sync(0xffffffffu, m3, o));
    }
    if (lane == 0) { red[wid][0] = m0; red[wid][1] = m1; red[wid][2] = m2; red[wid][3] = m3; }
    __syncthreads();
    if (t < 4) {
        float mm = -1e30f;
#pragma unroll
        for (int k = 0; k < 8; k++) mm = fmaxf(mm, red[k][t]);
        mx_s[t] = mm;
    }
    __syncthreads();
    const float mx0 = mx_s[0], mx1 = mx_s[1], mx2 = mx_s[2], mx3 = mx_s[3];

    float s0 = 0.f, s1 = 0.f, s2 = 0.f, s3 = 0.f;
    for (int j = t; j < deg; j += 256) {
        float e0, e1, e2, e3;
        if (j < CAP) {
            e0 = w[j][0]; e1 = w[j][1]; e2 = w[j][2]; e3 = w[j][3];
        } else {
            int s = csrc[start + j];
            float4 as = a_s4[s];
            e0 = leaky(as.x + ad.x); e1 = leaky(as.y + ad.y);
            e2 = leaky(as.z + ad.z); e3 = leaky(as.w + ad.w);
        }
        float x0 = expf(e0 - mx0), x1 = expf(e1 - mx1);
        float x2 = expf(e2 - mx2), x3 = expf(e3 - mx3);
        if (j < CAP) { w[j][0] = x0; w[j][1] = x1; w[j][2] = x2; w[j][3] = x3; }
        s0 += x0; s1 += x1; s2 += x2; s3 += x3;
    }
#pragma unroll
    for (int o = 16; o > 0; o >>= 1) {
        s0 += __shfl_xor_sync(0xffffffffu, s0, o);
        s1 += __shfl_xor_sync(0xffffffffu, s1, o);
        s2 += __shfl_xor_sync(0xffffffffu, s2, o);
        s3 += __shfl_xor_sync(0xffffffffu, s3, o);
    }
    __syncthreads();
    if (lane == 0) { red[wid][0] = s0; red[wid][1] = s1; red[wid][2] = s2; red[wid][3] = s3; }
    __syncthreads();
    if (t < 4) {
        float ssum = 0.f;
#pragma unroll
        for (int k = 0; k < 8; k++) ssum += red[k][t];
        invd_s[t] = 1.0f / (ssum + 1e-16f);
    }
    __syncthreads();

    const int c2 = t * 2;
    const int h = c2 >> 7;
    const float inv = invd_s[h];
    const float mxh = mx_s[h];
    float acc0 = 0.f, acc1 = 0.f;
    for (int j = 0; j < deg; j++) {
        int s;
        float ww;
        if (j < CAP) {
            s = s_list[j];
            ww = w[j][h];
        } else {
            s = csrc[start + j];
            const float* asp = (const float*)&a_s4[s];
            const float* adp = (const float*)&ad;
            ww = expf(leaky(asp[h] + adp[h]) - mxh);
        }
        float alpha = ww * inv;
        float2 v = *(const float2*)(Hf + (size_t)s * F512 + c2);
        acc0 += v.x * alpha;
        acc1 += v.y * alpha;
    }
    if (outh) {
        acc0 = fmaxf(acc0 + bias[c2], 0.f);
        acc1 = fmaxf(acc1 + bias[c2 + 1], 0.f);
        size_t o = (size_t)z * oslot + (size_t)d * F512 + c2;
        *(__half2*)(outh + o) = __floats2half2_rn(acc0, acc1);
    } else {
        size_t o = (size_t)z * ostride + (size_t)d * F512 + c2;
        *(float2*)(outf + o) = make_float2(acc0, acc1);
    }
}

// layer-2 epilogue (batched)
__global__ void head_mean_norm_kernel(const float* __restrict__ aggr_base, size_t astride,
                                      const float* __restrict__ bias0,
                                      const float* __restrict__ bias1,
                                      float* __restrict__ outq,
                                      float* __restrict__ outk, int B) {
    int n = blockIdx.x;
    if (n >= B) return;
    int z = blockIdx.y;
    const float* aggr = aggr_base + (size_t)z * astride;
    const float* bias = z ? bias1 : bias0;
    float* outv = z ? outk : outq;
    int c = threadIdx.x;
    size_t base = (size_t)n * F512;
    float v = 0.25f * (aggr[base + c] + aggr[base + 128 + c] +
                       aggr[base + 256 + c] + aggr[base + 384 + c]) + bias[c];
    float s = v * v;
#pragma unroll
    for (int o = 16; o > 0; o >>= 1) s += __shfl_down_sync(0xffffffffu, s, o);
    __shared__ float red[4];
    if ((c & 31) == 0) red[c >> 5] = s;
    __syncthreads();
    float tot = red[0] + red[1] + red[2] + red[3];
    outv[(size_t)n * C128 + c] = v * rsqrtf(tot + 1e-24f);
}

// ---------------- logits: tiled fp32 GEMM out[B,1+R] ------------------------
#define LT 64
__global__ __launch_bounds__(256)
void logits_gemm_kernel(const float* __restrict__ q,
                        const float* __restrict__ kv,
                        const float* __restrict__ queue,
                        float* __restrict__ out, int B, int R,
                        long tail_off, long tail_len) {
    __shared__ float qt[LT][33];
    __shared__ float kt[32][LT + 4];
    const int tid = threadIdx.x;
    const int bx = blockIdx.x, by = blockIdx.y;
    const int tx = tid & 15, ty = tid >> 4;

    float acc[4][4];
#pragma unroll
    for (int i = 0; i < 4; i++)
#pragma unroll
        for (int j = 0; j < 4; j++) acc[i][j] = 0.f;

    for (int k0 = 0; k0 < 128; k0 += 32) {
#pragma unroll
        for (int i = 0; i < 8; i++) {
            int e = tid + i * 256;
            int r = e >> 5, c = e & 31;
            int gr = by * LT + r;
            qt[r][c] = (gr < B) ? q[(size_t)gr * 128 + k0 + c] : 0.f;
        }
#pragma unroll
        for (int i = 0; i < 8; i++) {
            int e = tid + i * 256;
            int r = e >> 6, c = e & 63;
            int gc = bx * LT + c;
            kt[r][c] = (gc < R) ? queue[(size_t)(k0 + r) * R + gc] : 0.f;
        }
        __syncthreads();
#pragma unroll
        for (int k = 0; k < 32; k++) {
            float ra[4], rb[4];
#pragma unroll
            for (int i = 0; i < 4; i++) ra[i] = qt[ty * 4 + i][k];
#pragma unroll
            for (int j = 0; j < 4; j++) rb[j] = kt[k][tx * 4 + j];
#pragma unroll
            for (int i = 0; i < 4; i++)
#pragma unroll
                for (int j = 0; j < 4; j++) acc[i][j] += ra[i] * rb[j];
        }
        __syncthreads();
    }

#pragma unroll
    for (int i = 0; i < 4; i++) {
        int row = by * LT + ty * 4 + i;
        if (row >= B) continue;
#pragma unroll
        for (int j = 0; j < 4; j++) {
            int col = bx * LT + tx * 4 + j;
            if (col < R)
                out[(size_t)row * (R + 1) + 1 + col] = acc[i][j] * 5.0f;
        }
    }

    if (bx == 0 && tid < LT) {
        int n = by * LT + tid;
        if (n < B) {
            const float* qr = q + (size_t)n * 128;
            const float* kr = kv + (size_t)n * 128;
            float s = 0.f;
#pragma unroll 4
            for (int c = 0; c < 128; c++) s += qr[c] * kr[c];
            out[(size_t)n * (R + 1)] = s * 5.0f;
        }
    }
    if (bx == 0 && by == 0) {
        for (long i = tid; i < tail_len; i += 256) out[tail_off + i] = 0.f;
    }
}

// ------------------------------- launch ------------------------------------
extern "C" void kernel_launch(void* const* d_in, const int* in_sizes, int n_in,
                              void* d_out, int out_size) {
    int base = n_in - 17;

    const float* im_q = (const float*)d_in[0];
    const float* im_k = (const float*)d_in[1];
    const int*   ei   = (const int*)d_in[2];

    const float* Wq1  = (const float*)d_in[base + 0];
    const float* asq1 = (const float*)d_in[base + 1];
    const float* adq1 = (const float*)d_in[base + 2];
    const float* bq1  = (const float*)d_in[base + 3];
    const float* Wq2  = (const float*)d_in[base + 4];
    const float* asq2 = (const float*)d_in[base + 5];
    const float* adq2 = (const float*)d_in[base + 6];
    const float* bq2  = (const float*)d_in[base + 7];
    const float* Wk1  = (const float*)d_in[base + 8];
    const float* ask1 = (const float*)d_in[base + 9];
    const float* adk1 = (const float*)d_in[base + 10];
    const float* bk1  = (const float*)d_in[base + 11];
    const float* Wk2  = (const float*)d_in[base + 12];
    const float* ask2 = (const float*)d_in[base + 13];
    const float* adk2 = (const float*)d_in[base + 14];
    const float* bk2  = (const float*)d_in[base + 15];
    const float* queue= (const float*)d_in[base + 16];

    int G = in_sizes[base] / F512;
    int N = in_sizes[0] / G;
    int E = in_sizes[2] / 2;
    int R = in_sizes[base + 16] / C128;
    int B = (out_size % (R + 2) == 0) ? out_size / (R + 2) : out_size / (R + 1);
    if (B > N) B = N;
    int ET = E + N;
    int Mp = (N + BM - 1) / BM * BM;
    if (Mp > MPAD) Mp = MPAD;
    int Kp1 = (G + 63) & ~63;

    float *Hbuf, *asrc, *adst, *seedq, *seedk, *aggr2;
    float *ask1m, *adk1m, *bk1m, *ask2m, *adk2m, *bk2m;
    int *deg, *off, *cur, *csrc;
    hf *A1, *A2, *W1, *W2;
    cudaGetSymbolAddress((void**)&Hbuf, g_H);
    cudaGetSymbolAddress((void**)&asrc, g_asrc);
    cudaGetSymbolAddress((void**)&adst, g_adst);
    cudaGetSymbolAddress((void**)&seedq, g_seedq);
    cudaGetSymbolAddress((void**)&seedk, g_seedk);
    cudaGetSymbolAddress((void**)&aggr2, g_aggr2);
    cudaGetSymbolAddress((void**)&ask1m, g_ask1m);
    cudaGetSymbolAddress((void**)&adk1m, g_adk1m);
    cudaGetSymbolAddress((void**)&bk1m, g_bk1m);
    cudaGetSymbolAddress((void**)&ask2m, g_ask2m);
    cudaGetSymbolAddress((void**)&adk2m, g_adk2m);
    cudaGetSymbolAddress((void**)&bk2m, g_bk2m);
    cudaGetSymbolAddress((void**)&deg, g_deg);
    cudaGetSymbolAddress((void**)&off, g_off);
    cudaGetSymbolAddress((void**)&cur, g_cur);
    cudaGetSymbolAddress((void**)&csrc, g_csrc);
    cudaGetSymbolAddress((void**)&A1, g_A1);
    cudaGetSymbolAddress((void**)&A2, g_A2);
    cudaGetSymbolAddress((void**)&W1, g_W1);
    cudaGetSymbolAddress((void**)&W2, g_W2);

    cudaFuncSetAttribute(gemm_wmma_fp16_kernel,
                         cudaFuncAttributeMaxDynamicSharedMemorySize, SMEM_GEMM_BYTES);

    const size_t a1slot = (size_t)Mp * Kp1;
    const size_t a2slot = (size_t)MPAD * F512;
    const size_t hslot  = (size_t)MPAD * F512;
    const size_t w1slot = (size_t)Kp1 * F512;
    const size_t w2slot = (size_t)F512 * F512;
    // layer-2 attention fp32 output: only B rows per encoder needed
    const size_t aggr2slot = (size_t)NMAX * F512 / 4;   // >= B*512 (B<=2560)

    long totA1 = (long)Mp * Kp1;
    long wtot = 2 * (long)w1slot + 2 * (long)w2slot;

    // 1) input convert (batched q/k)
    conv_pad2_kernel<<<dim3((unsigned)((totA1 + 255) / 256), 2), 256>>>(
        im_q, im_k, N, G, Kp1, totA1, A1);
    // 2) all weight converts (+momentum blend for key)
    wconv_all_kernel<<<(int)((wtot + 255) / 256), 256>>>(
        Wq1, Wk1, Wq2, Wk2, G, Kp1, W1, W2);
    // 3) layer-1 GEMM (batched)
    {
        dim3 grid(F512 / BN, Mp / BM, 2);
        gemm_wmma_fp16_kernel<<<grid, TGEMM, SMEM_GEMM_BYTES>>>(
            Kp1, F512, A1, W1, Hbuf, a1slot, w1slot, hslot);
    }
    // 4) misc prep
    misc_prep_kernel<<<(2 * N + 2688 + 255) / 256, 256>>>(
        N, deg, cur,
        ask1, asq1, adk1, adq1, bk1, bq1,
        ask2, asq2, adk2, adq2, bk2, bq2,
        ask1m, adk1m, bk1m, ask2m, adk2m, bk2m);
    // 5-7) CSR
    csr_count_kernel<<<(ET + 255) / 256, 256>>>(ei, E, N, deg);
    csr_scan_kernel<<<1, 1024>>>(deg, off, N);
    csr_fill_kernel<<<(ET + 255) / 256, 256>>>(ei, E, N, off, cur, csrc);
    // 8-9) layer-1 attention -> fp16 A2 (pad rows stay zero from init)
    att_scores_kernel<<<dim3(N, 2), dim3(32, 4)>>>(Hbuf, hslot, asq1, adq1, ask1m, adk1m,
                                                   asrc, adst, N);
    gat_attn_kernel<<<dim3(N, 2), 256>>>(Hbuf, hslot, (const float4*)asrc,
                                         (const float4*)adst, off, deg, csrc,
                                         bq1, bk1m, A2, nullptr, 0, a2slot);
    // 10) layer-2 GEMM (batched)
    {
        dim3 grid(F512 / BN, Mp / BM, 2);
        gemm_wmma_fp16_kernel<<<grid, TGEMM, SMEM_GEMM_BYTES>>>(
            F512, F512, A2, W2, Hbuf, a2slot, w2slot, hslot);
    }
    // 11-12) layer-2 attention (dst < B only), fp32 out
    att_scores_kernel<<<dim3(N, 2), dim3(32, 4)>>>(Hbuf, hslot, asq2, adq2, ask2m, adk2m,
                                                   asrc, adst, N);
    gat_attn_kernel<<<dim3(B, 2), 256>>>(Hbuf, hslot, (const float4*)asrc,
                                         (const float4*)adst, off, deg, csrc,
                                         nullptr, nullptr, nullptr,
                                         aggr2, aggr2slot, 0);
    // 13) head-mean + l2norm
    head_mean_norm_kernel<<<dim3(B, 2), 128>>>(aggr2, aggr2slot, bq2, bk2m,
                                               seedq, seedk, B);
    // 14) logits
    {
        long written = (long)B * (R + 1);
        long tail = (long)out_size - written;
        if (tail < 0) tail = 0;
        dim3 grid((R + LT - 1) / LT, (B + LT - 1) / LT);
        logits_gemm_kernel<<<grid, 256>>>(seedq, seedk, queue, (float*)d_out,
                                          B, R, written, tail);
    }
}